// round 2
// baseline (speedup 1.0000x reference)
#include <cuda_runtime.h>
#include <math.h>

#define BATCH 32
#define EMB   768
#define HEADS 12
#define HD    64
#define NLAYERS 12
#define NFIX  6
#define NADAPT 6
#define MLPD  3072
#define NCLS  100
#define NTOK  198
#define NT2   197
#define PE_NN 100
#define PE_DD 256
#define NPATCH 196

// ---------------- scratch (device globals; no allocation allowed) ------------
__device__ float g_tok [BATCH*NTOK*EMB];
__device__ float g_xn  [BATCH*NTOK*EMB];
__device__ float g_qkv [BATCH*NTOK*3*EMB];
__device__ float g_att [BATCH*NTOK*EMB];
__device__ float g_mlpb[BATCH*NTOK*MLPD];
__device__ float g_t   [BATCH*NT2*EMB];
__device__ float g_t2  [BATCH*NT2*EMB];
__device__ float g_col [BATCH*NPATCH*EMB];
__device__ float g_pat [BATCH*NPATCH*EMB];
__device__ float g_pwt [EMB*EMB];
__device__ float g_lat1[BATCH*EMB];
__device__ float g_lat2[BATCH*EMB];
__device__ float g_lat3[BATCH*EMB];
__device__ float g_cls [BATCH*EMB];
__device__ int   g_actv[BATCH*NADAPT];

__device__ __forceinline__ float gelu_f(float v) {
    return 0.5f * v * (1.0f + erff(v * 0.70710678118654752440f));
}

// ---------------- tiled SGEMM: C = A[M,K] @ B[K,N] + bias (+gelu)(+res) -----
// BM=BN=128, BK=16, 256 threads, 8x8 per thread. N must be a multiple of 4
// (all our Ns are multiples of 128). M edge guarded. K multiple of 16.
template<int ACT, bool RES>
__global__ void __launch_bounds__(256) sgemm_k(
    const float* __restrict__ A, const float* __restrict__ B,
    const float* __restrict__ bias, const float* __restrict__ res,
    float* __restrict__ C, int M, int N, int K)
{
    __shared__ float As[16][128];
    __shared__ float Bs[16][128];
    const int tid  = threadIdx.x;
    const int brow = blockIdx.y * 128;
    const int bcol = blockIdx.x * 128;
    const int tr = (tid / 16) * 8;
    const int tc = (tid % 16) * 8;

    const int a_row  = tid / 4;         // 0..63  (+64)
    const int a_col4 = (tid % 4) * 4;   // 0,4,8,12
    const int b_row  = tid / 32;        // 0..7   (+8)
    const int b_col4 = (tid % 32) * 4;

    float acc[8][8];
    #pragma unroll
    for (int i = 0; i < 8; i++)
        #pragma unroll
        for (int j = 0; j < 8; j++) acc[i][j] = 0.0f;

    for (int k0 = 0; k0 < K; k0 += 16) {
        #pragma unroll
        for (int i = 0; i < 2; i++) {
            int r  = a_row + i * 64;
            int gr = brow + r;
            float4 v = make_float4(0.f, 0.f, 0.f, 0.f);
            if (gr < M) v = *(const float4*)&A[(size_t)gr * K + k0 + a_col4];
            As[a_col4 + 0][r] = v.x; As[a_col4 + 1][r] = v.y;
            As[a_col4 + 2][r] = v.z; As[a_col4 + 3][r] = v.w;
        }
        #pragma unroll
        for (int i = 0; i < 2; i++) {
            int r  = b_row + i * 8;
            int gc = bcol + b_col4;
            float4 v = make_float4(0.f, 0.f, 0.f, 0.f);
            if (gc < N) v = *(const float4*)&B[(size_t)(k0 + r) * N + gc];
            *(float4*)&Bs[r][b_col4] = v;
        }
        __syncthreads();
        #pragma unroll
        for (int kk = 0; kk < 16; kk++) {
            float ra[8], rb[8];
            *(float4*)&ra[0] = *(const float4*)&As[kk][tr];
            *(float4*)&ra[4] = *(const float4*)&As[kk][tr + 4];
            *(float4*)&rb[0] = *(const float4*)&Bs[kk][tc];
            *(float4*)&rb[4] = *(const float4*)&Bs[kk][tc + 4];
            #pragma unroll
            for (int i = 0; i < 8; i++)
                #pragma unroll
                for (int j = 0; j < 8; j++)
                    acc[i][j] += ra[i] * rb[j];
        }
        __syncthreads();
    }
    #pragma unroll
    for (int i = 0; i < 8; i++) {
        int gr = brow + tr + i;
        if (gr >= M) continue;
        #pragma unroll
        for (int j = 0; j < 8; j++) {
            int gc = bcol + tc + j;
            if (gc >= N) continue;
            float v = acc[i][j] + bias[gc];
            if (ACT == 1) v = gelu_f(v);
            if (RES)      v += res[(size_t)gr * N + gc];
            C[(size_t)gr * N + gc] = v;
        }
    }
}

// ---------------- LayerNorm over 768, one block (256 thr) per row -----------
__global__ void ln_k(const float* __restrict__ X, long istride,
                     const float* __restrict__ g, const float* __restrict__ b,
                     float* __restrict__ Y, long ostride)
{
    const int row = blockIdx.x;
    const int tid = threadIdx.x;
    const float* x = X + (size_t)row * istride;
    float* y       = Y + (size_t)row * ostride;
    __shared__ float red[8];
    __shared__ float stat[2];

    float v0 = x[tid], v1 = x[tid + 256], v2 = x[tid + 512];
    float s = v0 + v1 + v2;
    #pragma unroll
    for (int o = 16; o; o >>= 1) s += __shfl_xor_sync(~0u, s, o);
    if ((tid & 31) == 0) red[tid >> 5] = s;
    __syncthreads();
    if (tid == 0) {
        float t = 0.f;
        #pragma unroll
        for (int i = 0; i < 8; i++) t += red[i];
        stat[0] = t * (1.0f / 768.0f);
    }
    __syncthreads();
    const float mean = stat[0];
    float d0 = v0 - mean, d1 = v1 - mean, d2 = v2 - mean;
    s = d0 * d0 + d1 * d1 + d2 * d2;
    #pragma unroll
    for (int o = 16; o; o >>= 1) s += __shfl_xor_sync(~0u, s, o);
    __syncthreads();                 // protect red[] from pass-1 readers
    if ((tid & 31) == 0) red[tid >> 5] = s;
    __syncthreads();
    if (tid == 0) {
        float t = 0.f;
        #pragma unroll
        for (int i = 0; i < 8; i++) t += red[i];
        stat[1] = rsqrtf(t * (1.0f / 768.0f) + 1e-5f);
    }
    __syncthreads();
    const float rstd = stat[1];
    y[tid]       = d0 * rstd * g[tid]       + b[tid];
    y[tid + 256] = d1 * rstd * g[tid + 256] + b[tid + 256];
    y[tid + 512] = d2 * rstd * g[tid + 512] + b[tid + 512];
}

// ---------------- fused attention: one CTA per (b, head) --------------------
// smem: Kt[64][200] (K transposed), Vs[198][68], qbuf[8][64], probs[8][200]
#define KT_S 200
#define V_S  68
#define ATTN_SMEM_BYTES ((64*KT_S + NTOK*V_S + 8*64 + 8*200) * 4)

__global__ void attn_k(const float* __restrict__ qkv, float* __restrict__ O, int N)
{
    extern __shared__ float sm[];
    float* Kt = sm;                       // 64 x 200
    float* Vs = Kt + 64 * KT_S;           // 198 x 68
    float* qb = Vs + NTOK * V_S;          // 8 x 64
    float* pb = qb + 8 * 64;              // 8 x 200

    const int bh = blockIdx.x;
    const int b  = bh / HEADS, h = bh % HEADS;
    const int tid = threadIdx.x;
    const int w = tid >> 5, lane = tid & 31;
    const float* base = qkv + (size_t)b * N * (3 * EMB);

    for (int idx = tid; idx < N * 64; idx += 256) {
        int n = idx >> 6, d = idx & 63;
        const float* r = base + (size_t)n * (3 * EMB);
        Kt[d * KT_S + n] = r[EMB     + h * 64 + d];
        Vs[n * V_S  + d] = r[2 * EMB + h * 64 + d];
    }
    __syncthreads();

    for (int q = w; q < N; q += 8) {
        const float* qp = base + (size_t)q * (3 * EMB) + h * 64;
        qb[w * 64 + lane]      = qp[lane];
        qb[w * 64 + 32 + lane] = qp[32 + lane];
        __syncwarp();

        float sc[7];
        #pragma unroll
        for (int j = 0; j < 7; j++) {
            int kk = lane + 32 * j;
            float a = 0.f;
            if (kk < N) {
                #pragma unroll
                for (int d = 0; d < 64; d++)
                    a += qb[w * 64 + d] * Kt[d * KT_S + kk];
                a *= 0.125f;
            } else a = -1e30f;
            sc[j] = a;
        }
        float m = sc[0];
        #pragma unroll
        for (int j = 1; j < 7; j++) m = fmaxf(m, sc[j]);
        #pragma unroll
        for (int o = 16; o; o >>= 1) m = fmaxf(m, __shfl_xor_sync(~0u, m, o));
        float sum = 0.f;
        #pragma unroll
        for (int j = 0; j < 7; j++) {
            int kk = lane + 32 * j;
            float e = (kk < N) ? __expf(sc[j] - m) : 0.f;
            sc[j] = e; sum += e;
        }
        #pragma unroll
        for (int o = 16; o; o >>= 1) sum += __shfl_xor_sync(~0u, sum, o);
        const float inv = 1.0f / sum;
        #pragma unroll
        for (int j = 0; j < 7; j++) {
            int kk = lane + 32 * j;
            if (kk < N) pb[w * 200 + kk] = sc[j] * inv;
        }
        __syncwarp();

        float o0 = 0.f, o1 = 0.f;
        for (int kk = 0; kk < N; kk++) {
            float p = pb[w * 200 + kk];
            o0 += p * Vs[kk * V_S + lane];
            o1 += p * Vs[kk * V_S + 32 + lane];
        }
        float* op = O + ((size_t)b * N + q) * EMB + h * 64;
        op[lane]      = o0;
        op[32 + lane] = o1;
        __syncwarp();
    }
}

// ---------------- small / elementwise kernels -------------------------------
__global__ void im2col_k(const float* __restrict__ x, float* __restrict__ col, long total)
{
    long i = (long)blockIdx.x * blockDim.x + threadIdx.x;
    if (i >= total) return;
    int k = (int)(i % EMB);
    long m = i / EMB;
    int b = (int)(m / NPATCH), p = (int)(m % NPATCH);
    int c = k >> 8, r = k & 255, ii = r >> 4, jj = r & 15;
    int py = p / 14, px = p % 14;
    col[i] = x[(((size_t)b * 3 + c) * 224 + py * 16 + ii) * 224 + px * 16 + jj];
}

__global__ void tr_k(const float* __restrict__ w, float* __restrict__ wt, long total)
{
    long i = (long)blockIdx.x * blockDim.x + threadIdx.x;
    if (i >= total) return;
    int e = (int)(i % EMB);
    int k = (int)(i / EMB);
    wt[i] = w[(size_t)e * EMB + k];     // wt[k][e] = w[e][k]
}

__global__ void lat1_k(const float* __restrict__ pe, const float* __restrict__ w1,
                       const float* __restrict__ b1, const float* __restrict__ budget,
                       float* __restrict__ out)
{
    int b = blockIdx.x;
    int idx = (int)rintf(budget[b] * (float)(PE_NN - 1));
    const float* row = pe + (size_t)idx * PE_DD;
    for (int e = threadIdx.x; e < EMB; e += 256) {
        float s = b1[e];
        for (int k = 0; k < PE_DD; k++) s += row[k] * w1[(size_t)k * EMB + e];
        out[(size_t)b * EMB + e] = gelu_f(s);
    }
}

__global__ void assemble_k(const float* __restrict__ lat, const float* __restrict__ cls,
                           const float* __restrict__ pat, const float* __restrict__ pos,
                           float* __restrict__ tok, long total)
{
    long i = (long)blockIdx.x * blockDim.x + threadIdx.x;
    if (i >= total) return;
    int e = (int)(i % EMB);
    long bn = i / EMB;
    int n = (int)(bn % NTOK), b = (int)(bn / NTOK);
    float v;
    if (n == 0)      v = lat[(size_t)b * EMB + e];
    else if (n == 1) v = cls[e];
    else             v = pat[((size_t)b * NPATCH + (n - 2)) * EMB + e];
    tok[i] = v + pos[(size_t)n * EMB + e];
}

__global__ void sched_k(const float* __restrict__ tok, const float* __restrict__ sw,
                        const float* __restrict__ sb, const float* __restrict__ budget,
                        int* __restrict__ active)
{
    int b = blockIdx.x, lane = threadIdx.x;
    __shared__ float lg[NADAPT];
    if (lane < NADAPT) {
        const float* x = tok + (size_t)b * NTOK * EMB;   // token 0
        float s = sb[lane];
        for (int k = 0; k < EMB; k++) s += x[k] * sw[(size_t)k * NADAPT + lane];
        lg[lane] = s;
    }
    __syncwarp();
    if (lane < NADAPT) {
        int kk = (int)ceilf(budget[b] * (float)NADAPT);
        if (kk < 1) kk = 1;
        int rank = 0;
        for (int j = 0; j < NADAPT; j++)
            if (lg[j] > lg[lane] || (lg[j] == lg[lane] && j < lane)) rank++;
        active[b * NADAPT + lane] = (rank < kk) ? 1 : 0;
    }
}

__global__ void extract_k(const float* __restrict__ tok, float* __restrict__ t, long total)
{
    long i = (long)blockIdx.x * blockDim.x + threadIdx.x;
    if (i >= total) return;
    int e = (int)(i % EMB);
    long bn = i / EMB;
    int n = (int)(bn % NT2), b = (int)(bn / NT2);
    t[i] = tok[((size_t)b * NTOK + n + 1) * EMB + e];
}

__global__ void copy_k(const float* __restrict__ s, float* __restrict__ d, long n)
{
    long i = (long)blockIdx.x * blockDim.x + threadIdx.x;
    if (i < n) d[i] = s[i];
}

__global__ void merge_k(const float* __restrict__ t2, float* __restrict__ t,
                        const int* __restrict__ active, int layer, long total)
{
    long i = (long)blockIdx.x * blockDim.x + threadIdx.x;
    if (i >= total) return;
    int b = (int)(i / ((long)NT2 * EMB));
    if (active[b * NADAPT + layer]) t[i] = t2[i];
}

__global__ void head_k(const float* __restrict__ cls, const float* __restrict__ w,
                       const float* __restrict__ bias, float* __restrict__ out)
{
    int b = blockIdx.x, c = threadIdx.x;
    if (c >= NCLS) return;
    const float* x = cls + (size_t)b * EMB;
    float s = bias[c];
    for (int k = 0; k < EMB; k++) s += x[k] * w[(size_t)k * NCLS + c];
    out[(size_t)b * NCLS + c] = s;
}

// ---------------- host orchestration ----------------------------------------
static inline void launch_gemm(int act, bool res,
                               const float* A, const float* B, const float* bias,
                               const float* r, float* C, int M, int N, int K)
{
    dim3 g((N + 127) / 128, (M + 127) / 128), blk(256);
    if (act == 0 && !res) sgemm_k<0, false><<<g, blk>>>(A, B, bias, r, C, M, N, K);
    else if (act == 0)    sgemm_k<0, true ><<<g, blk>>>(A, B, bias, r, C, M, N, K);
    else if (!res)        sgemm_k<1, false><<<g, blk>>>(A, B, bias, r, C, M, N, K);
    else                  sgemm_k<1, true ><<<g, blk>>>(A, B, bias, r, C, M, N, K);
}

struct Ptrs {
    float *tok, *xn, *qkv, *att, *mlp, *t, *t2, *col, *pat, *pwt;
    float *lat1, *lat2, *lat3, *cls;
    int   *actv;
};

static void run_block(const Ptrs& P, float* X, int N, int l,
                      const float* ln1g, const float* ln1b,
                      const float* qkvw, const float* qkvb,
                      const float* projw, const float* projb,
                      const float* ln2g, const float* ln2b,
                      const float* fc1w, const float* fc1b,
                      const float* fc2w, const float* fc2b)
{
    const int M = BATCH * N;
    ln_k<<<M, 256>>>(X, EMB, ln1g + (size_t)l * EMB, ln1b + (size_t)l * EMB, P.xn, EMB);
    launch_gemm(0, false, P.xn, qkvw + (size_t)l * EMB * 3 * EMB,
                qkvb + (size_t)l * 3 * EMB, nullptr, P.qkv, M, 3 * EMB, EMB);
    attn_k<<<BATCH * HEADS, 256, ATTN_SMEM_BYTES>>>(P.qkv, P.att, N);
    launch_gemm(0, true, P.att, projw + (size_t)l * EMB * EMB,
                projb + (size_t)l * EMB, X, X, M, EMB, EMB);
    ln_k<<<M, 256>>>(X, EMB, ln2g + (size_t)l * EMB, ln2b + (size_t)l * EMB, P.xn, EMB);
    launch_gemm(1, false, P.xn, fc1w + (size_t)l * EMB * MLPD,
                fc1b + (size_t)l * MLPD, nullptr, P.mlp, M, MLPD, EMB);
    launch_gemm(0, true, P.mlp, fc2w + (size_t)l * MLPD * EMB,
                fc2b + (size_t)l * EMB, X, X, M, EMB, MLPD);
}

extern "C" void kernel_launch(void* const* d_in, const int* in_sizes, int n_in,
                              void* d_out, int out_size)
{
    const float* x        = (const float*)d_in[0];
    const float* budget   = (const float*)d_in[1];
    const float* pe_table = (const float*)d_in[2];
    const float* lat_w1   = (const float*)d_in[3];
    const float* lat_b1   = (const float*)d_in[4];
    const float* lat_ln_g = (const float*)d_in[5];
    const float* lat_ln_b = (const float*)d_in[6];
    const float* lat_w2   = (const float*)d_in[7];
    const float* lat_b2   = (const float*)d_in[8];
    const float* patch_w  = (const float*)d_in[9];
    const float* patch_b  = (const float*)d_in[10];
    const float* cls_tok  = (const float*)d_in[11];
    const float* pos_emb  = (const float*)d_in[12];
    const float* sched_w  = (const float*)d_in[13];
    const float* sched_b  = (const float*)d_in[14];
    const float* ln1_g    = (const float*)d_in[15];
    const float* ln1_b    = (const float*)d_in[16];
    const float* qkv_w    = (const float*)d_in[17];
    const float* qkv_b    = (const float*)d_in[18];
    const float* proj_w   = (const float*)d_in[19];
    const float* proj_b   = (const float*)d_in[20];
    const float* ln2_g    = (const float*)d_in[21];
    const float* ln2_b    = (const float*)d_in[22];
    const float* fc1_w    = (const float*)d_in[23];
    const float* fc1_b    = (const float*)d_in[24];
    const float* fc2_w    = (const float*)d_in[25];
    const float* fc2_b    = (const float*)d_in[26];
    const float* norm_g   = (const float*)d_in[27];
    const float* norm_b   = (const float*)d_in[28];
    const float* head_w   = (const float*)d_in[29];
    const float* head_b   = (const float*)d_in[30];
    float* out = (float*)d_out;

    Ptrs P;
    cudaGetSymbolAddress((void**)&P.tok,  g_tok);
    cudaGetSymbolAddress((void**)&P.xn,   g_xn);
    cudaGetSymbolAddress((void**)&P.qkv,  g_qkv);
    cudaGetSymbolAddress((void**)&P.att,  g_att);
    cudaGetSymbolAddress((void**)&P.mlp,  g_mlpb);
    cudaGetSymbolAddress((void**)&P.t,    g_t);
    cudaGetSymbolAddress((void**)&P.t2,   g_t2);
    cudaGetSymbolAddress((void**)&P.col,  g_col);
    cudaGetSymbolAddress((void**)&P.pat,  g_pat);
    cudaGetSymbolAddress((void**)&P.pwt,  g_pwt);
    cudaGetSymbolAddress((void**)&P.lat1, g_lat1);
    cudaGetSymbolAddress((void**)&P.lat2, g_lat2);
    cudaGetSymbolAddress((void**)&P.lat3, g_lat3);
    cudaGetSymbolAddress((void**)&P.cls,  g_cls);
    cudaGetSymbolAddress((void**)&P.actv, g_actv);

    cudaFuncSetAttribute(attn_k, cudaFuncAttributeMaxDynamicSharedMemorySize,
                         ATTN_SMEM_BYTES);

    // --- latent token ---
    lat1_k<<<BATCH, 256>>>(pe_table, lat_w1, lat_b1, budget, P.lat1);
    ln_k<<<BATCH, 256>>>(P.lat1, EMB, lat_ln_g, lat_ln_b, P.lat2, EMB);
    launch_gemm(0, false, P.lat2, lat_w2, lat_b2, nullptr, P.lat3, BATCH, EMB, EMB);

    // --- patch embedding ---
    {
        long tot = (long)BATCH * NPATCH * EMB;
        im2col_k<<<(unsigned)((tot + 255) / 256), 256>>>(x, P.col, tot);
        long tw = (long)EMB * EMB;
        tr_k<<<(unsigned)((tw + 255) / 256), 256>>>(patch_w, P.pwt, tw);
        launch_gemm(0, false, P.col, P.pwt, patch_b, nullptr, P.pat,
                    BATCH * NPATCH, EMB, EMB);
        long ta = (long)BATCH * NTOK * EMB;
        assemble_k<<<(unsigned)((ta + 255) / 256), 256>>>(P.lat3, cls_tok, P.pat,
                                                          pos_emb, P.tok, ta);
    }

    // --- 6 fixed blocks on 198 tokens ---
    for (int l = 0; l < NFIX; l++)
        run_block(P, P.tok, NTOK, l, ln1_g, ln1_b, qkv_w, qkv_b, proj_w, proj_b,
                  ln2_g, ln2_b, fc1_w, fc1_b, fc2_w, fc2_b);

    // --- scheduler gating ---
    sched_k<<<BATCH, 32>>>(P.tok, sched_w, sched_b, budget, P.actv);

    // --- adaptive blocks on 197 tokens ---
    const long tlen = (long)BATCH * NT2 * EMB;
    extract_k<<<(unsigned)((tlen + 255) / 256), 256>>>(P.tok, P.t, tlen);
    for (int i = 0; i < NADAPT; i++) {
        copy_k<<<(unsigned)((tlen + 255) / 256), 256>>>(P.t, P.t2, tlen);
        run_block(P, P.t2, NT2, NFIX + i, ln1_g, ln1_b, qkv_w, qkv_b,
                  proj_w, proj_b, ln2_g, ln2_b, fc1_w, fc1_b, fc2_w, fc2_b);
        merge_k<<<(unsigned)((tlen + 255) / 256), 256>>>(P.t2, P.t, P.actv, i, tlen);
    }

    // --- final LN (only row 0 per sample is needed) + head ---
    ln_k<<<BATCH, 256>>>(P.t, (long)NT2 * EMB, norm_g, norm_b, P.cls, EMB);
    head_k<<<BATCH, 128>>>(P.cls, head_w, head_b, out);
}

// round 3
// speedup vs baseline: 2.0308x; 2.0308x over previous
#include <cuda_runtime.h>
#include <math.h>
#include <stdint.h>

#define BATCH 32
#define EMB   768
#define HEADS 12
#define HD    64
#define NLAYERS 12
#define NFIX  6
#define NADAPT 6
#define MLPD  3072
#define NCLS  100
#define NTOK  198
#define NT2   197
#define PE_NN 100
#define PE_DD 256
#define NPATCH 196

// ---------------- scratch (device globals; no allocation allowed) ------------
__device__ float g_tok [BATCH*NTOK*EMB];
__device__ float g_xn  [BATCH*NTOK*EMB];
__device__ float g_qkv [BATCH*NTOK*3*EMB];
__device__ float g_att [BATCH*NTOK*EMB];
__device__ float g_mlpb[BATCH*NTOK*MLPD];
__device__ float g_t   [BATCH*NT2*EMB];
__device__ float g_t2  [BATCH*NT2*EMB];
__device__ float g_col [BATCH*NPATCH*EMB];
__device__ float g_pat [BATCH*NPATCH*EMB];
__device__ float g_pwt [EMB*EMB];
__device__ float g_lat1[BATCH*EMB];
__device__ float g_lat2[BATCH*EMB];
__device__ float g_lat3[BATCH*EMB];
__device__ float g_cls [BATCH*EMB];
__device__ int   g_actv[BATCH*NADAPT];

__device__ __forceinline__ float gelu_f(float v) {
    return 0.5f * v * (1.0f + erff(v * 0.70710678118654752440f));
}

__device__ __forceinline__ uint32_t f2tf32(float f) {
    uint32_t u;
    asm volatile("cvt.rna.tf32.f32 %0, %1;" : "=r"(u) : "f"(f));
    return u;
}

__device__ __forceinline__ void mma_tf32(float c[4], const uint32_t a[4], const uint32_t b[2]) {
    asm volatile(
        "mma.sync.aligned.m16n8k8.row.col.f32.tf32.tf32.f32 "
        "{%0,%1,%2,%3}, {%4,%5,%6,%7}, {%8,%9}, {%0,%1,%2,%3};\n"
        : "+f"(c[0]), "+f"(c[1]), "+f"(c[2]), "+f"(c[3])
        : "r"(a[0]), "r"(a[1]), "r"(a[2]), "r"(a[3]), "r"(b[0]), "r"(b[1]));
}

// ---------------- tf32 tensor-core GEMM: C = A[M,K] @ B[K,N] ----------------
// BM=BN=128, BK=16, 256 threads (8 warps, 2x4), warp tile 64x32, frag m16n8k8.
// Requires: K % 16 == 0, N % 128 == 0. M edge guarded.
template<int ACT, bool RES>
__global__ void __launch_bounds__(256) tgemm_k(
    const float* __restrict__ A, const float* __restrict__ B,
    const float* __restrict__ bias, const float* __restrict__ res,
    float* __restrict__ C, int M, int N, int K)
{
    __shared__ uint32_t As[128][20];   // [m][k], pad 20 -> conflict-free frag LDS
    __shared__ uint32_t Bs[16][132];   // [k][n], pad 132 -> conflict-free frag LDS

    const int tid  = threadIdx.x;
    const int warp = tid >> 5, lane = tid & 31;
    const int brow = blockIdx.y * 128;
    const int bcol = blockIdx.x * 128;
    const int warpM = (warp >> 2) * 64;   // 0 or 64
    const int warpN = (warp & 3) * 32;    // 0..96

    const int a_row = tid >> 2;           // 0..63 (+64)
    const int a_col = (tid & 3) * 4;      // 0,4,8,12
    const int b_row = tid >> 5;           // 0..7 (+8)
    const int b_col = lane * 4;           // 0..124

    float acc[4][4][4];
    #pragma unroll
    for (int i = 0; i < 4; i++)
        #pragma unroll
        for (int j = 0; j < 4; j++)
            #pragma unroll
            for (int r = 0; r < 4; r++) acc[i][j][r] = 0.0f;

    float4 pa[2], pb[2];

    // prefetch k0 = 0
    #pragma unroll
    for (int i = 0; i < 2; i++) {
        int gr = brow + a_row + i * 64;
        pa[i] = (gr < M) ? *(const float4*)&A[(size_t)gr * K + a_col]
                         : make_float4(0.f, 0.f, 0.f, 0.f);
        pb[i] = *(const float4*)&B[(size_t)(b_row + i * 8) * N + bcol + b_col];
    }

    for (int k0 = 0; k0 < K; k0 += 16) {
        #pragma unroll
        for (int i = 0; i < 2; i++) {
            int r = a_row + i * 64;
            As[r][a_col + 0] = f2tf32(pa[i].x);
            As[r][a_col + 1] = f2tf32(pa[i].y);
            As[r][a_col + 2] = f2tf32(pa[i].z);
            As[r][a_col + 3] = f2tf32(pa[i].w);
            int rb = b_row + i * 8;
            Bs[rb][b_col + 0] = f2tf32(pb[i].x);
            Bs[rb][b_col + 1] = f2tf32(pb[i].y);
            Bs[rb][b_col + 2] = f2tf32(pb[i].z);
            Bs[rb][b_col + 3] = f2tf32(pb[i].w);
        }
        __syncthreads();

        if (k0 + 16 < K) {
            int kn = k0 + 16;
            #pragma unroll
            for (int i = 0; i < 2; i++) {
                int gr = brow + a_row + i * 64;
                pa[i] = (gr < M) ? *(const float4*)&A[(size_t)gr * K + kn + a_col]
                                 : make_float4(0.f, 0.f, 0.f, 0.f);
                pb[i] = *(const float4*)&B[(size_t)(kn + b_row + i * 8) * N + bcol + b_col];
            }
        }

        #pragma unroll
        for (int ks = 0; ks < 16; ks += 8) {
            uint32_t af[4][4], bf[4][2];
            const int kk = ks + (lane & 3);
            const int g4 = lane >> 2;
            #pragma unroll
            for (int tm = 0; tm < 4; tm++) {
                int m = warpM + tm * 16 + g4;
                af[tm][0] = As[m][kk];
                af[tm][1] = As[m + 8][kk];
                af[tm][2] = As[m][kk + 4];
                af[tm][3] = As[m + 8][kk + 4];
            }
            #pragma unroll
            for (int tn = 0; tn < 4; tn++) {
                int n = warpN + tn * 8 + g4;
                bf[tn][0] = Bs[kk][n];
                bf[tn][1] = Bs[kk + 4][n];
            }
            #pragma unroll
            for (int tm = 0; tm < 4; tm++)
                #pragma unroll
                for (int tn = 0; tn < 4; tn++)
                    mma_tf32(acc[tm][tn], af[tm], bf[tn]);
        }
        __syncthreads();
    }

    // epilogue: c0,c1 at (r, c),(r, c+1); c2,c3 at (r+8, ...)
    const int g4 = lane >> 2, l2 = (lane & 3) * 2;
    #pragma unroll
    for (int tm = 0; tm < 4; tm++) {
        int r0 = brow + warpM + tm * 16 + g4;
        #pragma unroll
        for (int half = 0; half < 2; half++) {
            int gr = r0 + half * 8;
            if (gr >= M) continue;
            #pragma unroll
            for (int tn = 0; tn < 4; tn++) {
                int gc = bcol + warpN + tn * 8 + l2;
                #pragma unroll
                for (int e = 0; e < 2; e++) {
                    float v = acc[tm][tn][half * 2 + e] + bias[gc + e];
                    if (ACT == 1) v = gelu_f(v);
                    if (RES)      v += res[(size_t)gr * N + gc + e];
                    C[(size_t)gr * N + gc + e] = v;
                }
            }
        }
    }
}

// ---------------- LayerNorm over 768, one block (256 thr) per row -----------
__global__ void ln_k(const float* __restrict__ X, long istride,
                     const float* __restrict__ g, const float* __restrict__ b,
                     float* __restrict__ Y, long ostride)
{
    const int row = blockIdx.x;
    const int tid = threadIdx.x;
    const float* x = X + (size_t)row * istride;
    float* y       = Y + (size_t)row * ostride;
    __shared__ float red[8];
    __shared__ float stat[2];

    float v0 = x[tid], v1 = x[tid + 256], v2 = x[tid + 512];
    float s = v0 + v1 + v2;
    #pragma unroll
    for (int o = 16; o; o >>= 1) s += __shfl_xor_sync(~0u, s, o);
    if ((tid & 31) == 0) red[tid >> 5] = s;
    __syncthreads();
    if (tid == 0) {
        float t = 0.f;
        #pragma unroll
        for (int i = 0; i < 8; i++) t += red[i];
        stat[0] = t * (1.0f / 768.0f);
    }
    __syncthreads();
    const float mean = stat[0];
    float d0 = v0 - mean, d1 = v1 - mean, d2 = v2 - mean;
    s = d0 * d0 + d1 * d1 + d2 * d2;
    #pragma unroll
    for (int o = 16; o; o >>= 1) s += __shfl_xor_sync(~0u, s, o);
    __syncthreads();
    if ((tid & 31) == 0) red[tid >> 5] = s;
    __syncthreads();
    if (tid == 0) {
        float t = 0.f;
        #pragma unroll
        for (int i = 0; i < 8; i++) t += red[i];
        stat[1] = rsqrtf(t * (1.0f / 768.0f) + 1e-5f);
    }
    __syncthreads();
    const float rstd = stat[1];
    y[tid]       = d0 * rstd * g[tid]       + b[tid];
    y[tid + 256] = d1 * rstd * g[tid + 256] + b[tid + 256];
    y[tid + 512] = d2 * rstd * g[tid + 512] + b[tid + 512];
}

// ---------------- fused attention: one CTA per (b, head) --------------------
#define KT_S 200
#define V_S  68
#define ATTN_SMEM_BYTES ((64*KT_S + NTOK*V_S + 8*64 + 8*200) * 4)

__global__ void attn_k(const float* __restrict__ qkv, float* __restrict__ O, int N)
{
    extern __shared__ float sm[];
    float* Kt = sm;
    float* Vs = Kt + 64 * KT_S;
    float* qb = Vs + NTOK * V_S;
    float* pb = qb + 8 * 64;

    const int bh = blockIdx.x;
    const int b  = bh / HEADS, h = bh % HEADS;
    const int tid = threadIdx.x;
    const int w = tid >> 5, lane = tid & 31;
    const float* base = qkv + (size_t)b * N * (3 * EMB);

    for (int idx = tid; idx < N * 64; idx += 256) {
        int n = idx >> 6, d = idx & 63;
        const float* r = base + (size_t)n * (3 * EMB);
        Kt[d * KT_S + n] = r[EMB     + h * 64 + d];
        Vs[n * V_S  + d] = r[2 * EMB + h * 64 + d];
    }
    __syncthreads();

    for (int q = w; q < N; q += 8) {
        const float* qp = base + (size_t)q * (3 * EMB) + h * 64;
        qb[w * 64 + lane]      = qp[lane];
        qb[w * 64 + 32 + lane] = qp[32 + lane];
        __syncwarp();

        float sc[7];
        #pragma unroll
        for (int j = 0; j < 7; j++) {
            int kk = lane + 32 * j;
            float a = 0.f;
            if (kk < N) {
                #pragma unroll
                for (int d = 0; d < 64; d++)
                    a += qb[w * 64 + d] * Kt[d * KT_S + kk];
                a *= 0.125f;
            } else a = -1e30f;
            sc[j] = a;
        }
        float m = sc[0];
        #pragma unroll
        for (int j = 1; j < 7; j++) m = fmaxf(m, sc[j]);
        #pragma unroll
        for (int o = 16; o; o >>= 1) m = fmaxf(m, __shfl_xor_sync(~0u, m, o));
        float sum = 0.f;
        #pragma unroll
        for (int j = 0; j < 7; j++) {
            int kk = lane + 32 * j;
            float e = (kk < N) ? __expf(sc[j] - m) : 0.f;
            sc[j] = e; sum += e;
        }
        #pragma unroll
        for (int o = 16; o; o >>= 1) sum += __shfl_xor_sync(~0u, sum, o);
        const float inv = 1.0f / sum;
        #pragma unroll
        for (int j = 0; j < 7; j++) {
            int kk = lane + 32 * j;
            if (kk < N) pb[w * 200 + kk] = sc[j] * inv;
        }
        __syncwarp();

        float o0 = 0.f, o1 = 0.f;
        for (int kk = 0; kk < N; kk++) {
            float p = pb[w * 200 + kk];
            o0 += p * Vs[kk * V_S + lane];
            o1 += p * Vs[kk * V_S + 32 + lane];
        }
        float* op = O + ((size_t)b * N + q) * EMB + h * 64;
        op[lane]      = o0;
        op[32 + lane] = o1;
        __syncwarp();
    }
}

// ---------------- small / elementwise kernels -------------------------------
__global__ void im2col_k(const float* __restrict__ x, float* __restrict__ col, long total)
{
    long i = (long)blockIdx.x * blockDim.x + threadIdx.x;
    if (i >= total) return;
    int k = (int)(i % EMB);
    long m = i / EMB;
    int b = (int)(m / NPATCH), p = (int)(m % NPATCH);
    int c = k >> 8, r = k & 255, ii = r >> 4, jj = r & 15;
    int py = p / 14, px = p % 14;
    col[i] = x[(((size_t)b * 3 + c) * 224 + py * 16 + ii) * 224 + px * 16 + jj];
}

__global__ void tr_k(const float* __restrict__ w, float* __restrict__ wt, long total)
{
    long i = (long)blockIdx.x * blockDim.x + threadIdx.x;
    if (i >= total) return;
    int e = (int)(i % EMB);
    int k = (int)(i / EMB);
    wt[i] = w[(size_t)e * EMB + k];
}

__global__ void lat1_k(const float* __restrict__ pe, const float* __restrict__ w1,
                       const float* __restrict__ b1, const float* __restrict__ budget,
                       float* __restrict__ out)
{
    int b = blockIdx.x;
    int idx = (int)rintf(budget[b] * (float)(PE_NN - 1));
    const float* row = pe + (size_t)idx * PE_DD;
    for (int e = threadIdx.x; e < EMB; e += 256) {
        float s = b1[e];
        for (int k = 0; k < PE_DD; k++) s += row[k] * w1[(size_t)k * EMB + e];
        out[(size_t)b * EMB + e] = gelu_f(s);
    }
}

__global__ void assemble_k(const float* __restrict__ lat, const float* __restrict__ cls,
                           const float* __restrict__ pat, const float* __restrict__ pos,
                           float* __restrict__ tok, long total)
{
    long i = (long)blockIdx.x * blockDim.x + threadIdx.x;
    if (i >= total) return;
    int e = (int)(i % EMB);
    long bn = i / EMB;
    int n = (int)(bn % NTOK), b = (int)(bn / NTOK);
    float v;
    if (n == 0)      v = lat[(size_t)b * EMB + e];
    else if (n == 1) v = cls[e];
    else             v = pat[((size_t)b * NPATCH + (n - 2)) * EMB + e];
    tok[i] = v + pos[(size_t)n * EMB + e];
}

__global__ void sched_k(const float* __restrict__ tok, const float* __restrict__ sw,
                        const float* __restrict__ sb, const float* __restrict__ budget,
                        int* __restrict__ active)
{
    int b = blockIdx.x, lane = threadIdx.x;
    __shared__ float lg[NADAPT];
    if (lane < NADAPT) {
        const float* x = tok + (size_t)b * NTOK * EMB;
        float s = sb[lane];
        for (int k = 0; k < EMB; k++) s += x[k] * sw[(size_t)k * NADAPT + lane];
        lg[lane] = s;
    }
    __syncwarp();
    if (lane < NADAPT) {
        int kk = (int)ceilf(budget[b] * (float)NADAPT);
        if (kk < 1) kk = 1;
        int rank = 0;
        for (int j = 0; j < NADAPT; j++)
            if (lg[j] > lg[lane] || (lg[j] == lg[lane] && j < lane)) rank++;
        active[b * NADAPT + lane] = (rank < kk) ? 1 : 0;
    }
}

__global__ void extract_k(const float* __restrict__ tok, float* __restrict__ t, long total)
{
    long i = (long)blockIdx.x * blockDim.x + threadIdx.x;
    if (i >= total) return;
    int e = (int)(i % EMB);
    long bn = i / EMB;
    int n = (int)(bn % NT2), b = (int)(bn / NT2);
    t[i] = tok[((size_t)b * NTOK + n + 1) * EMB + e];
}

__global__ void copy_k(const float* __restrict__ s, float* __restrict__ d, long n)
{
    long i = (long)blockIdx.x * blockDim.x + threadIdx.x;
    if (i < n) d[i] = s[i];
}

__global__ void merge_k(const float* __restrict__ t2, float* __restrict__ t,
                        const int* __restrict__ active, int layer, long total)
{
    long i = (long)blockIdx.x * blockDim.x + threadIdx.x;
    if (i >= total) return;
    int b = (int)(i / ((long)NT2 * EMB));
    if (active[b * NADAPT + layer]) t[i] = t2[i];
}

__global__ void head_k(const float* __restrict__ cls, const float* __restrict__ w,
                       const float* __restrict__ bias, float* __restrict__ out)
{
    int b = blockIdx.x, c = threadIdx.x;
    if (c >= NCLS) return;
    const float* x = cls + (size_t)b * EMB;
    float s = bias[c];
    for (int k = 0; k < EMB; k++) s += x[k] * w[(size_t)k * NCLS + c];
    out[(size_t)b * NCLS + c] = s;
}

// ---------------- host orchestration ----------------------------------------
static inline void launch_gemm(int act, bool res,
                               const float* A, const float* B, const float* bias,
                               const float* r, float* C, int M, int N, int K)
{
    dim3 g(N / 128, (M + 127) / 128), blk(256);
    if (act == 0 && !res) tgemm_k<0, false><<<g, blk>>>(A, B, bias, r, C, M, N, K);
    else if (act == 0)    tgemm_k<0, true ><<<g, blk>>>(A, B, bias, r, C, M, N, K);
    else if (!res)        tgemm_k<1, false><<<g, blk>>>(A, B, bias, r, C, M, N, K);
    else                  tgemm_k<1, true ><<<g, blk>>>(A, B, bias, r, C, M, N, K);
}

struct Ptrs {
    float *tok, *xn, *qkv, *att, *mlp, *t, *t2, *col, *pat, *pwt;
    float *lat1, *lat2, *lat3, *cls;
    int   *actv;
};

static void run_block(const Ptrs& P, float* X, int N, int l,
                      const float* ln1g, const float* ln1b,
                      const float* qkvw, const float* qkvb,
                      const float* projw, const float* projb,
                      const float* ln2g, const float* ln2b,
                      const float* fc1w, const float* fc1b,
                      const float* fc2w, const float* fc2b)
{
    const int M = BATCH * N;
    ln_k<<<M, 256>>>(X, EMB, ln1g + (size_t)l * EMB, ln1b + (size_t)l * EMB, P.xn, EMB);
    launch_gemm(0, false, P.xn, qkvw + (size_t)l * EMB * 3 * EMB,
                qkvb + (size_t)l * 3 * EMB, nullptr, P.qkv, M, 3 * EMB, EMB);
    attn_k<<<BATCH * HEADS, 256, ATTN_SMEM_BYTES>>>(P.qkv, P.att, N);
    launch_gemm(0, true, P.att, projw + (size_t)l * EMB * EMB,
                projb + (size_t)l * EMB, X, X, M, EMB, EMB);
    ln_k<<<M, 256>>>(X, EMB, ln2g + (size_t)l * EMB, ln2b + (size_t)l * EMB, P.xn, EMB);
    launch_gemm(1, false, P.xn, fc1w + (size_t)l * EMB * MLPD,
                fc1b + (size_t)l * MLPD, nullptr, P.mlp, M, MLPD, EMB);
    launch_gemm(0, true, P.mlp, fc2w + (size_t)l * MLPD * EMB,
                fc2b + (size_t)l * EMB, X, X, M, EMB, MLPD);
}

extern "C" void kernel_launch(void* const* d_in, const int* in_sizes, int n_in,
                              void* d_out, int out_size)
{
    const float* x        = (const float*)d_in[0];
    const float* budget   = (const float*)d_in[1];
    const float* pe_table = (const float*)d_in[2];
    const float* lat_w1   = (const float*)d_in[3];
    const float* lat_b1   = (const float*)d_in[4];
    const float* lat_ln_g = (const float*)d_in[5];
    const float* lat_ln_b = (const float*)d_in[6];
    const float* lat_w2   = (const float*)d_in[7];
    const float* lat_b2   = (const float*)d_in[8];
    const float* patch_w  = (const float*)d_in[9];
    const float* patch_b  = (const float*)d_in[10];
    const float* cls_tok  = (const float*)d_in[11];
    const float* pos_emb  = (const float*)d_in[12];
    const float* sched_w  = (const float*)d_in[13];
    const float* sched_b  = (const float*)d_in[14];
    const float* ln1_g    = (const float*)d_in[15];
    const float* ln1_b    = (const float*)d_in[16];
    const float* qkv_w    = (const float*)d_in[17];
    const float* qkv_b    = (const float*)d_in[18];
    const float* proj_w   = (const float*)d_in[19];
    const float* proj_b   = (const float*)d_in[20];
    const float* ln2_g    = (const float*)d_in[21];
    const float* ln2_b    = (const float*)d_in[22];
    const float* fc1_w    = (const float*)d_in[23];
    const float* fc1_b    = (const float*)d_in[24];
    const float* fc2_w    = (const float*)d_in[25];
    const float* fc2_b    = (const float*)d_in[26];
    const float* norm_g   = (const float*)d_in[27];
    const float* norm_b   = (const float*)d_in[28];
    const float* head_w   = (const float*)d_in[29];
    const float* head_b   = (const float*)d_in[30];
    float* out = (float*)d_out;

    Ptrs P;
    cudaGetSymbolAddress((void**)&P.tok,  g_tok);
    cudaGetSymbolAddress((void**)&P.xn,   g_xn);
    cudaGetSymbolAddress((void**)&P.qkv,  g_qkv);
    cudaGetSymbolAddress((void**)&P.att,  g_att);
    cudaGetSymbolAddress((void**)&P.mlp,  g_mlpb);
    cudaGetSymbolAddress((void**)&P.t,    g_t);
    cudaGetSymbolAddress((void**)&P.t2,   g_t2);
    cudaGetSymbolAddress((void**)&P.col,  g_col);
    cudaGetSymbolAddress((void**)&P.pat,  g_pat);
    cudaGetSymbolAddress((void**)&P.pwt,  g_pwt);
    cudaGetSymbolAddress((void**)&P.lat1, g_lat1);
    cudaGetSymbolAddress((void**)&P.lat2, g_lat2);
    cudaGetSymbolAddress((void**)&P.lat3, g_lat3);
    cudaGetSymbolAddress((void**)&P.cls,  g_cls);
    cudaGetSymbolAddress((void**)&P.actv, g_actv);

    cudaFuncSetAttribute(attn_k, cudaFuncAttributeMaxDynamicSharedMemorySize,
                         ATTN_SMEM_BYTES);

    // --- latent token ---
    lat1_k<<<BATCH, 256>>>(pe_table, lat_w1, lat_b1, budget, P.lat1);
    ln_k<<<BATCH, 256>>>(P.lat1, EMB, lat_ln_g, lat_ln_b, P.lat2, EMB);
    launch_gemm(0, false, P.lat2, lat_w2, lat_b2, nullptr, P.lat3, BATCH, EMB, EMB);

    // --- patch embedding ---
    {
        long tot = (long)BATCH * NPATCH * EMB;
        im2col_k<<<(unsigned)((tot + 255) / 256), 256>>>(x, P.col, tot);
        long tw = (long)EMB * EMB;
        tr_k<<<(unsigned)((tw + 255) / 256), 256>>>(patch_w, P.pwt, tw);
        launch_gemm(0, false, P.col, P.pwt, patch_b, nullptr, P.pat,
                    BATCH * NPATCH, EMB, EMB);
        long ta = (long)BATCH * NTOK * EMB;
        assemble_k<<<(unsigned)((ta + 255) / 256), 256>>>(P.lat3, cls_tok, P.pat,
                                                          pos_emb, P.tok, ta);
    }

    // --- 6 fixed blocks on 198 tokens ---
    for (int l = 0; l < NFIX; l++)
        run_block(P, P.tok, NTOK, l, ln1_g, ln1_b, qkv_w, qkv_b, proj_w, proj_b,
                  ln2_g, ln2_b, fc1_w, fc1_b, fc2_w, fc2_b);

    // --- scheduler gating ---
    sched_k<<<BATCH, 32>>>(P.tok, sched_w, sched_b, budget, P.actv);

    // --- adaptive blocks on 197 tokens ---
    const long tlen = (long)BATCH * NT2 * EMB;
    extract_k<<<(unsigned)((tlen + 255) / 256), 256>>>(P.tok, P.t, tlen);
    for (int i = 0; i < NADAPT; i++) {
        copy_k<<<(unsigned)((tlen + 255) / 256), 256>>>(P.t, P.t2, tlen);
        run_block(P, P.t2, NT2, NFIX + i, ln1_g, ln1_b, qkv_w, qkv_b,
                  proj_w, proj_b, ln2_g, ln2_b, fc1_w, fc1_b, fc2_w, fc2_b);
        merge_k<<<(unsigned)((tlen + 255) / 256), 256>>>(P.t2, P.t, P.actv, i, tlen);
    }

    // --- final LN (only row 0 per sample is needed) + head ---
    ln_k<<<BATCH, 256>>>(P.t, (long)NT2 * EMB, norm_g, norm_b, P.cls, EMB);
    head_k<<<BATCH, 128>>>(P.cls, head_w, head_b, out);
}

// round 5
// speedup vs baseline: 3.0595x; 1.5066x over previous
#include <cuda_runtime.h>
#include <cuda_fp16.h>
#include <math.h>
#include <stdint.h>

#define BATCH 32
#define EMB   768
#define HEADS 12
#define HD    64
#define NLAYERS 12
#define NFIX  6
#define NADAPT 6
#define MLPD  3072
#define NCLS  100
#define NTOK  198
#define NT2   197
#define PE_NN 100
#define PE_DD 256
#define NPATCH 196

// ---------------- scratch (device globals; no allocation allowed) ------------
__device__ float g_tok [BATCH*NTOK*EMB];
__device__ float g_att32_unused[1];
__device__ __align__(16) __half g_xn  [BATCH*NTOK*EMB];
__device__ __align__(16) __half g_qkv [BATCH*NTOK*3*EMB];
__device__ __align__(16) __half g_attb[BATCH*NTOK*EMB];
__device__ __align__(16) __half g_mlpb[BATCH*NTOK*MLPD];
__device__ float g_t   [BATCH*NT2*EMB];
__device__ float g_t2  [BATCH*NT2*EMB];
__device__ __align__(16) __half g_col [BATCH*NPATCH*EMB];
__device__ float g_pat [BATCH*NPATCH*EMB];
__device__ float g_lat1[BATCH*EMB];
__device__ __align__(16) __half g_lat2[BATCH*EMB];
__device__ float g_lat3[BATCH*EMB];
__device__ __align__(16) __half g_cls [BATCH*EMB];
__device__ int   g_actv[BATCH*NADAPT];
// transposed+converted weights: [n][k] half layout for GEMM B operand
__device__ __align__(16) __half g_wqkv [NLAYERS*3*EMB*EMB];
__device__ __align__(16) __half g_wproj[NLAYERS*EMB*EMB];
__device__ __align__(16) __half g_wfc1 [NLAYERS*MLPD*EMB];
__device__ __align__(16) __half g_wfc2 [NLAYERS*EMB*MLPD];
__device__ __align__(16) __half g_wlat2[EMB*EMB];
__device__ __align__(16) __half g_wpat [EMB*EMB];

__device__ __forceinline__ float gelu_f(float v) {
    return 0.5f * v * (1.0f + erff(v * 0.70710678118654752440f));
}
__device__ __forceinline__ uint32_t smem_u32(const void* p) {
    uint32_t a;
    asm("{ .reg .u64 t; cvta.to.shared.u64 t, %1; cvt.u32.u64 %0, t; }" : "=r"(a) : "l"(p));
    return a;
}
__device__ __forceinline__ void cp16(uint32_t dst, const void* src, bool pred) {
    int sz = pred ? 16 : 0;
    asm volatile("cp.async.cg.shared.global [%0], [%1], 16, %2;"
                 :: "r"(dst), "l"(src), "r"(sz) : "memory");
}
__device__ __forceinline__ void mma_f16(float c[4], const uint32_t a[4], const uint32_t b[2]) {
    asm volatile(
        "mma.sync.aligned.m16n8k16.row.col.f32.f16.f16.f32 "
        "{%0,%1,%2,%3}, {%4,%5,%6,%7}, {%8,%9}, {%0,%1,%2,%3};\n"
        : "+f"(c[0]), "+f"(c[1]), "+f"(c[2]), "+f"(c[3])
        : "r"(a[0]), "r"(a[1]), "r"(a[2]), "r"(a[3]), "r"(b[0]), "r"(b[1]));
}

// ---------------- fp16 tensor-core GEMM: C = A[M,K] @ Bt[N,K]^T -------------
// 128x128x32 tile, 256 threads (8 warps 2x4), warp tile 64x32, m16n8k16.
// A,Bt half K-major. cp.async double-buffered. N%128==0, K%32==0, M guarded.
#define HSTRIDE 40   // halves per smem row (80B); conflict-free fragment loads
template<int ACT, bool RES, bool OUTH>
__global__ void __launch_bounds__(256) hgemm_k(
    const __half* __restrict__ A, const __half* __restrict__ Bt,
    const float* __restrict__ bias, const float* __restrict__ res,
    float* __restrict__ Cf, __half* __restrict__ Ch, int M, int N, int K)
{
    __shared__ __align__(16) __half sA[2][128 * HSTRIDE];
    __shared__ __align__(16) __half sB[2][128 * HSTRIDE];

    const int tid  = threadIdx.x;
    const int warp = tid >> 5, lane = tid & 31;
    const int brow = blockIdx.y * 128;
    const int bcol = blockIdx.x * 128;
    const int warpM = (warp >> 2) * 64;
    const int warpN = (warp & 3) * 32;
    const int g4 = lane >> 2, l2 = (lane & 3) * 2;

    const uint32_t sa0 = smem_u32(&sA[0][0]), sa1 = smem_u32(&sA[1][0]);
    const uint32_t sb0 = smem_u32(&sB[0][0]), sb1 = smem_u32(&sB[1][0]);

    float acc[4][4][4];
    #pragma unroll
    for (int i = 0; i < 4; i++)
        #pragma unroll
        for (int j = 0; j < 4; j++)
            #pragma unroll
            for (int r = 0; r < 4; r++) acc[i][j][r] = 0.0f;

    const int nch = K >> 5;
    const int r0 = tid >> 2, r1 = (tid + 256) >> 2;
    const int cb0 = (tid & 3), cb1 = ((tid + 256) & 3);

    // stage loader
    auto LOAD = [&](int chunk, int st) {
        const int k0 = chunk << 5;
        const uint32_t da = st ? sa1 : sa0;
        const uint32_t db = st ? sb1 : sb0;
        cp16(da + r0 * (HSTRIDE * 2) + cb0 * 16,
             A + (size_t)(brow + r0) * K + k0 + cb0 * 8, (brow + r0) < M);
        cp16(da + r1 * (HSTRIDE * 2) + cb1 * 16,
             A + (size_t)(brow + r1) * K + k0 + cb1 * 8, (brow + r1) < M);
        cp16(db + r0 * (HSTRIDE * 2) + cb0 * 16,
             Bt + (size_t)(bcol + r0) * K + k0 + cb0 * 8, true);
        cp16(db + r1 * (HSTRIDE * 2) + cb1 * 16,
             Bt + (size_t)(bcol + r1) * K + k0 + cb1 * 8, true);
        asm volatile("cp.async.commit_group;" ::: "memory");
    };

    LOAD(0, 0);

    for (int c = 0; c < nch; c++) {
        const int st = c & 1;
        if (c + 1 < nch) {
            LOAD(c + 1, st ^ 1);
            asm volatile("cp.async.wait_group 1;" ::: "memory");
        } else {
            asm volatile("cp.async.wait_group 0;" ::: "memory");
        }
        __syncthreads();

        const __half* As = sA[st];
        const __half* Bs = sB[st];
        #pragma unroll
        for (int ks = 0; ks < 2; ks++) {
            const int kk = ks * 16 + l2;
            uint32_t af[4][4], bf[4][2];
            #pragma unroll
            for (int tm = 0; tm < 4; tm++) {
                const int m = warpM + tm * 16 + g4;
                af[tm][0] = *(const uint32_t*)&As[m * HSTRIDE + kk];
                af[tm][1] = *(const uint32_t*)&As[(m + 8) * HSTRIDE + kk];
                af[tm][2] = *(const uint32_t*)&As[m * HSTRIDE + kk + 8];
                af[tm][3] = *(const uint32_t*)&As[(m + 8) * HSTRIDE + kk + 8];
            }
            #pragma unroll
            for (int tn = 0; tn < 4; tn++) {
                const int n = warpN + tn * 8 + g4;
                bf[tn][0] = *(const uint32_t*)&Bs[n * HSTRIDE + kk];
                bf[tn][1] = *(const uint32_t*)&Bs[n * HSTRIDE + kk + 8];
            }
            #pragma unroll
            for (int tm = 0; tm < 4; tm++)
                #pragma unroll
                for (int tn = 0; tn < 4; tn++)
                    mma_f16(acc[tm][tn], af[tm], bf[tn]);
        }
        __syncthreads();
    }

    // epilogue: c0,c1 at (row g4, col l2,l2+1); c2,c3 at row g4+8
    #pragma unroll
    for (int tm = 0; tm < 4; tm++) {
        const int rr = brow + warpM + tm * 16 + g4;
        #pragma unroll
        for (int half = 0; half < 2; half++) {
            const int gr = rr + half * 8;
            if (gr >= M) continue;
            #pragma unroll
            for (int tn = 0; tn < 4; tn++) {
                const int gc = bcol + warpN + tn * 8 + l2;
                float o0 = acc[tm][tn][half * 2 + 0] + bias[gc];
                float o1 = acc[tm][tn][half * 2 + 1] + bias[gc + 1];
                if (ACT == 1) { o0 = gelu_f(o0); o1 = gelu_f(o1); }
                if (RES) {
                    o0 += res[(size_t)gr * N + gc];
                    o1 += res[(size_t)gr * N + gc + 1];
                }
                if (OUTH) {
                    *(__half2*)&Ch[(size_t)gr * N + gc] = __floats2half2_rn(o0, o1);
                } else {
                    Cf[(size_t)gr * N + gc]     = o0;
                    Cf[(size_t)gr * N + gc + 1] = o1;
                }
            }
        }
    }
}

// ---------------- weight transpose+convert: out[l][n][k] = in[l][k][n] ------
__global__ void transpose_k(const float* __restrict__ in, __half* __restrict__ out,
                            int K, int N)
{
    __shared__ float t[32][33];
    const int l = blockIdx.z;
    const float* ip = in  + (size_t)l * K * N;
    __half*      op = out + (size_t)l * K * N;
    const int k0 = blockIdx.y * 32, n0 = blockIdx.x * 32;
    #pragma unroll
    for (int i = 0; i < 32; i += 8) {
        int k = k0 + threadIdx.y + i, n = n0 + threadIdx.x;
        if (k < K && n < N) t[threadIdx.y + i][threadIdx.x] = ip[(size_t)k * N + n];
    }
    __syncthreads();
    #pragma unroll
    for (int i = 0; i < 32; i += 8) {
        int n = n0 + threadIdx.y + i, k = k0 + threadIdx.x;
        if (n < N && k < K) op[(size_t)n * K + k] = __float2half_rn(t[threadIdx.x][threadIdx.y + i]);
    }
}

__global__ void cvt_k(const float* __restrict__ in, __half* __restrict__ out, long n)
{
    long i = (long)blockIdx.x * blockDim.x + threadIdx.x;
    if (i < n) out[i] = __float2half_rn(in[i]);
}

// ---------------- LayerNorm over 768 (fp32 in, half out) --------------------
__global__ void ln_k(const float* __restrict__ X, long istride,
                     const float* __restrict__ g, const float* __restrict__ b,
                     __half* __restrict__ Y, long ostride)
{
    const int row = blockIdx.x;
    const int tid = threadIdx.x;
    const float* x = X + (size_t)row * istride;
    __half* y      = Y + (size_t)row * ostride;
    __shared__ float red[8];
    __shared__ float stat[2];

    float v0 = x[tid], v1 = x[tid + 256], v2 = x[tid + 512];
    float s = v0 + v1 + v2;
    #pragma unroll
    for (int o = 16; o; o >>= 1) s += __shfl_xor_sync(~0u, s, o);
    if ((tid & 31) == 0) red[tid >> 5] = s;
    __syncthreads();
    if (tid == 0) {
        float t = 0.f;
        #pragma unroll
        for (int i = 0; i < 8; i++) t += red[i];
        stat[0] = t * (1.0f / 768.0f);
    }
    __syncthreads();
    const float mean = stat[0];
    float d0 = v0 - mean, d1 = v1 - mean, d2 = v2 - mean;
    s = d0 * d0 + d1 * d1 + d2 * d2;
    #pragma unroll
    for (int o = 16; o; o >>= 1) s += __shfl_xor_sync(~0u, s, o);
    __syncthreads();
    if ((tid & 31) == 0) red[tid >> 5] = s;
    __syncthreads();
    if (tid == 0) {
        float t = 0.f;
        #pragma unroll
        for (int i = 0; i < 8; i++) t += red[i];
        stat[1] = rsqrtf(t * (1.0f / 768.0f) + 1e-5f);
    }
    __syncthreads();
    const float rstd = stat[1];
    y[tid]       = __float2half_rn(d0 * rstd * g[tid]       + b[tid]);
    y[tid + 256] = __float2half_rn(d1 * rstd * g[tid + 256] + b[tid + 256]);
    y[tid + 512] = __float2half_rn(d2 * rstd * g[tid + 512] + b[tid + 512]);
}

// ---------------- fused attention: one CTA per (b, head), half I/O ----------
#define KT_S 200
#define V_S  68
#define ATTN_SMEM_BYTES ((64*KT_S + NTOK*V_S + 8*64 + 8*200) * 4)

__global__ void attn_k(const __half* __restrict__ qkv, __half* __restrict__ O, int N)
{
    extern __shared__ float sm[];
    float* Kt = sm;
    float* Vs = Kt + 64 * KT_S;
    float* qb = Vs + NTOK * V_S;
    float* pb = qb + 8 * 64;

    const int bh = blockIdx.x;
    const int b  = bh / HEADS, h = bh % HEADS;
    const int tid = threadIdx.x;
    const int w = tid >> 5, lane = tid & 31;
    const __half* base = qkv + (size_t)b * N * (3 * EMB);

    for (int idx = tid; idx < N * 64; idx += 256) {
        int n = idx >> 6, d = idx & 63;
        const __half* r = base + (size_t)n * (3 * EMB);
        Kt[d * KT_S + n] = __half2float(r[EMB     + h * 64 + d]);
        Vs[n * V_S  + d] = __half2float(r[2 * EMB + h * 64 + d]);
    }
    __syncthreads();

    for (int q = w; q < N; q += 8) {
        const __half* qp = base + (size_t)q * (3 * EMB) + h * 64;
        qb[w * 64 + lane]      = __half2float(qp[lane]);
        qb[w * 64 + 32 + lane] = __half2float(qp[32 + lane]);
        __syncwarp();

        float sc[7];
        #pragma unroll
        for (int j = 0; j < 7; j++) {
            int kk = lane + 32 * j;
            float a = 0.f;
            if (kk < N) {
                #pragma unroll
                for (int d = 0; d < 64; d++)
                    a += qb[w * 64 + d] * Kt[d * KT_S + kk];
                a *= 0.125f;
            } else a = -1e30f;
            sc[j] = a;
        }
        float m = sc[0];
        #pragma unroll
        for (int j = 1; j < 7; j++) m = fmaxf(m, sc[j]);
        #pragma unroll
        for (int o = 16; o; o >>= 1) m = fmaxf(m, __shfl_xor_sync(~0u, m, o));
        float sum = 0.f;
        #pragma unroll
        for (int j = 0; j < 7; j++) {
            int kk = lane + 32 * j;
            float e = (kk < N) ? __expf(sc[j] - m) : 0.f;
            sc[j] = e; sum += e;
        }
        #pragma unroll
        for (int o = 16; o; o >>= 1) sum += __shfl_xor_sync(~0u, sum, o);
        const float inv = 1.0f / sum;
        #pragma unroll
        for (int j = 0; j < 7; j++) {
            int kk = lane + 32 * j;
            if (kk < N) pb[w * 200 + kk] = sc[j] * inv;
        }
        __syncwarp();

        float o0 = 0.f, o1 = 0.f;
        for (int kk = 0; kk < N; kk++) {
            float p = pb[w * 200 + kk];
            o0 += p * Vs[kk * V_S + lane];
            o1 += p * Vs[kk * V_S + 32 + lane];
        }
        __half* op = O + ((size_t)b * N + q) * EMB + h * 64;
        op[lane]      = __float2half_rn(o0);
        op[32 + lane] = __float2half_rn(o1);
        __syncwarp();
    }
}

// ---------------- small / elementwise kernels -------------------------------
__global__ void im2col_k(const float* __restrict__ x, __half* __restrict__ col, long total)
{
    long i = (long)blockIdx.x * blockDim.x + threadIdx.x;
    if (i >= total) return;
    int k = (int)(i % EMB);
    long m = i / EMB;
    int b = (int)(m / NPATCH), p = (int)(m % NPATCH);
    int c = k >> 8, r = k & 255, ii = r >> 4, jj = r & 15;
    int py = p / 14, px = p % 14;
    col[i] = __float2half_rn(x[(((size_t)b * 3 + c) * 224 + py * 16 + ii) * 224 + px * 16 + jj]);
}

__global__ void lat1_k(const float* __restrict__ pe, const float* __restrict__ w1,
                       const float* __restrict__ b1, const float* __restrict__ budget,
                       float* __restrict__ out)
{
    int b = blockIdx.x;
    int idx = (int)rintf(budget[b] * (float)(PE_NN - 1));
    const float* row = pe + (size_t)idx * PE_DD;
    for (int e = threadIdx.x; e < EMB; e += 256) {
        float s = b1[e];
        for (int k = 0; k < PE_DD; k++) s += row[k] * w1[(size_t)k * EMB + e];
        out[(size_t)b * EMB + e] = gelu_f(s);
    }
}

__global__ void assemble_k(const float* __restrict__ lat, const float* __restrict__ cls,
                           const float* __restrict__ pat, const float* __restrict__ pos,
                           float* __restrict__ tok, long total)
{
    long i = (long)blockIdx.x * blockDim.x + threadIdx.x;
    if (i >= total) return;
    int e = (int)(i % EMB);
    long bn = i / EMB;
    int n = (int)(bn % NTOK), b = (int)(bn / NTOK);
    float v;
    if (n == 0)      v = lat[(size_t)b * EMB + e];
    else if (n == 1) v = cls[e];
    else             v = pat[((size_t)b * NPATCH + (n - 2)) * EMB + e];
    tok[i] = v + pos[(size_t)n * EMB + e];
}

__global__ void sched_k(const float* __restrict__ tok, const float* __restrict__ sw,
                        const float* __restrict__ sb, const float* __restrict__ budget,
                        int* __restrict__ active)
{
    int b = blockIdx.x, lane = threadIdx.x;
    __shared__ float lg[NADAPT];
    if (lane < NADAPT) {
        const float* x = tok + (size_t)b * NTOK * EMB;
        float s = sb[lane];
        for (int k = 0; k < EMB; k++) s += x[k] * sw[(size_t)k * NADAPT + lane];
        lg[lane] = s;
    }
    __syncwarp();
    if (lane < NADAPT) {
        int kk = (int)ceilf(budget[b] * (float)NADAPT);
        if (kk < 1) kk = 1;
        int rank = 0;
        for (int j = 0; j < NADAPT; j++)
            if (lg[j] > lg[lane] || (lg[j] == lg[lane] && j < lane)) rank++;
        active[b * NADAPT + lane] = (rank < kk) ? 1 : 0;
    }
}

__global__ void extract_k(const float* __restrict__ tok, float* __restrict__ t, long total)
{
    long i = (long)blockIdx.x * blockDim.x + threadIdx.x;
    if (i >= total) return;
    int e = (int)(i % EMB);
    long bn = i / EMB;
    int n = (int)(bn % NT2), b = (int)(bn / NT2);
    t[i] = tok[((size_t)b * NTOK + n + 1) * EMB + e];
}

__global__ void copy_k(const float* __restrict__ s, float* __restrict__ d, long n)
{
    long i = (long)blockIdx.x * blockDim.x + threadIdx.x;
    if (i < n) d[i] = s[i];
}

__global__ void merge_k(const float* __restrict__ t2, float* __restrict__ t,
                        const int* __restrict__ active, int layer, long total)
{
    long i = (long)blockIdx.x * blockDim.x + threadIdx.x;
    if (i >= total) return;
    int b = (int)(i / ((long)NT2 * EMB));
    if (active[b * NADAPT + layer]) t[i] = t2[i];
}

__global__ void head_k(const __half* __restrict__ cls, const float* __restrict__ w,
                       const float* __restrict__ bias, float* __restrict__ out)
{
    int b = blockIdx.x, c = threadIdx.x;
    if (c >= NCLS) return;
    const __half* x = cls + (size_t)b * EMB;
    float s = bias[c];
    for (int k = 0; k < EMB; k++) s += __half2float(x[k]) * w[(size_t)k * NCLS + c];
    out[(size_t)b * NCLS + c] = s;
}

// ---------------- host orchestration ----------------------------------------
static inline void launch_gemm(int act, bool res, bool outh,
                               const __half* A, const __half* Bt, const float* bias,
                               const float* r, float* Cf, __half* Ch, int M, int N, int K)
{
    dim3 g(N / 128, (M + 127) / 128), blk(256);
    if (outh) {
        if (act == 1)      hgemm_k<1, false, true><<<g, blk>>>(A, Bt, bias, r, Cf, Ch, M, N, K);
        else               hgemm_k<0, false, true><<<g, blk>>>(A, Bt, bias, r, Cf, Ch, M, N, K);
    } else {
        if (res)           hgemm_k<0, true,  false><<<g, blk>>>(A, Bt, bias, r, Cf, Ch, M, N, K);
        else               hgemm_k<0, false, false><<<g, blk>>>(A, Bt, bias, r, Cf, Ch, M, N, K);
    }
}

struct Ptrs {
    float *tok, *t, *t2, *pat, *lat1, *lat3;
    __half *xn, *qkv, *att, *mlp, *col, *lat2, *cls;
    __half *wqkv, *wproj, *wfc1, *wfc2, *wlat2, *wpat;
    int   *actv;
};

static void run_block(const Ptrs& P, float* X, int N, int l,
                      const float* ln1g, const float* ln1b, const float* qkvb,
                      const float* projb, const float* ln2g, const float* ln2b,
                      const float* fc1b, const float* fc2b)
{
    const int M = BATCH * N;
    ln_k<<<M, 256>>>(X, EMB, ln1g + (size_t)l * EMB, ln1b + (size_t)l * EMB, P.xn, EMB);
    launch_gemm(0, false, true, P.xn, P.wqkv + (size_t)l * EMB * 3 * EMB,
                qkvb + (size_t)l * 3 * EMB, nullptr, nullptr, P.qkv, M, 3 * EMB, EMB);
    attn_k<<<BATCH * HEADS, 256, ATTN_SMEM_BYTES>>>(P.qkv, P.att, N);
    launch_gemm(0, true, false, P.att, P.wproj + (size_t)l * EMB * EMB,
                projb + (size_t)l * EMB, X, X, nullptr, M, EMB, EMB);
    ln_k<<<M, 256>>>(X, EMB, ln2g + (size_t)l * EMB, ln2b + (size_t)l * EMB, P.xn, EMB);
    launch_gemm(1, false, true, P.xn, P.wfc1 + (size_t)l * EMB * MLPD,
                fc1b + (size_t)l * MLPD, nullptr, nullptr, P.mlp, M, MLPD, EMB);
    launch_gemm(0, true, false, P.mlp, P.wfc2 + (size_t)l * MLPD * EMB,
                fc2b + (size_t)l * EMB, X, X, nullptr, M, EMB, MLPD);
}

extern "C" void kernel_launch(void* const* d_in, const int* in_sizes, int n_in,
                              void* d_out, int out_size)
{
    const float* x        = (const float*)d_in[0];
    const float* budget   = (const float*)d_in[1];
    const float* pe_table = (const float*)d_in[2];
    const float* lat_w1   = (const float*)d_in[3];
    const float* lat_b1   = (const float*)d_in[4];
    const float* lat_ln_g = (const float*)d_in[5];
    const float* lat_ln_b = (const float*)d_in[6];
    const float* lat_w2   = (const float*)d_in[7];
    const float* lat_b2   = (const float*)d_in[8];
    const float* patch_w  = (const float*)d_in[9];
    const float* patch_b  = (const float*)d_in[10];
    const float* cls_tok  = (const float*)d_in[11];
    const float* pos_emb  = (const float*)d_in[12];
    const float* sched_w  = (const float*)d_in[13];
    const float* sched_b  = (const float*)d_in[14];
    const float* ln1_g    = (const float*)d_in[15];
    const float* ln1_b    = (const float*)d_in[16];
    const float* qkv_w    = (const float*)d_in[17];
    const float* qkv_b    = (const float*)d_in[18];
    const float* proj_w   = (const float*)d_in[19];
    const float* proj_b   = (const float*)d_in[20];
    const float* ln2_g    = (const float*)d_in[21];
    const float* ln2_b    = (const float*)d_in[22];
    const float* fc1_w    = (const float*)d_in[23];
    const float* fc1_b    = (const float*)d_in[24];
    const float* fc2_w    = (const float*)d_in[25];
    const float* fc2_b    = (const float*)d_in[26];
    const float* norm_g   = (const float*)d_in[27];
    const float* norm_b   = (const float*)d_in[28];
    const float* head_w   = (const float*)d_in[29];
    const float* head_b   = (const float*)d_in[30];
    float* out = (float*)d_out;

    Ptrs P;
    cudaGetSymbolAddress((void**)&P.tok,  g_tok);
    cudaGetSymbolAddress((void**)&P.xn,   g_xn);
    cudaGetSymbolAddress((void**)&P.qkv,  g_qkv);
    cudaGetSymbolAddress((void**)&P.att,  g_attb);
    cudaGetSymbolAddress((void**)&P.mlp,  g_mlpb);
    cudaGetSymbolAddress((void**)&P.t,    g_t);
    cudaGetSymbolAddress((void**)&P.t2,   g_t2);
    cudaGetSymbolAddress((void**)&P.col,  g_col);
    cudaGetSymbolAddress((void**)&P.pat,  g_pat);
    cudaGetSymbolAddress((void**)&P.lat1, g_lat1);
    cudaGetSymbolAddress((void**)&P.lat2, g_lat2);
    cudaGetSymbolAddress((void**)&P.lat3, g_lat3);
    cudaGetSymbolAddress((void**)&P.cls,  g_cls);
    cudaGetSymbolAddress((void**)&P.actv, g_actv);
    cudaGetSymbolAddress((void**)&P.wqkv, g_wqkv);
    cudaGetSymbolAddress((void**)&P.wproj,g_wproj);
    cudaGetSymbolAddress((void**)&P.wfc1, g_wfc1);
    cudaGetSymbolAddress((void**)&P.wfc2, g_wfc2);
    cudaGetSymbolAddress((void**)&P.wlat2,g_wlat2);
    cudaGetSymbolAddress((void**)&P.wpat, g_wpat);

    cudaFuncSetAttribute(attn_k, cudaFuncAttributeMaxDynamicSharedMemorySize, ATTN_SMEM_BYTES);

    // --- weight transposes+convert ([K,N] fp32 -> [N,K] half) ---
    {
        dim3 b32(32, 8);
        transpose_k<<<dim3(3*EMB/32, EMB/32, NLAYERS), b32>>>(qkv_w,  P.wqkv,  EMB, 3*EMB);
        transpose_k<<<dim3(EMB/32,   EMB/32, NLAYERS), b32>>>(proj_w, P.wproj, EMB, EMB);
        transpose_k<<<dim3(MLPD/32,  EMB/32, NLAYERS), b32>>>(fc1_w,  P.wfc1,  EMB, MLPD);
        transpose_k<<<dim3(EMB/32,  MLPD/32, NLAYERS), b32>>>(fc2_w,  P.wfc2,  MLPD, EMB);
        transpose_k<<<dim3(EMB/32,   EMB/32, 1),       b32>>>(lat_w2, P.wlat2, EMB, EMB);
        long pw = (long)EMB * EMB;
        cvt_k<<<(unsigned)((pw + 255) / 256), 256>>>(patch_w, P.wpat, pw);  // already [N][K]
    }

    // --- latent token ---
    lat1_k<<<BATCH, 256>>>(pe_table, lat_w1, lat_b1, budget, P.lat1);
    ln_k<<<BATCH, 256>>>(P.lat1, EMB, lat_ln_g, lat_ln_b, P.lat2, EMB);
    launch_gemm(0, false, false, P.lat2, P.wlat2, lat_b2, nullptr, P.lat3, nullptr,
                BATCH, EMB, EMB);

    // --- patch embedding ---
    {
        long tot = (long)BATCH * NPATCH * EMB;
        im2col_k<<<(unsigned)((tot + 255) / 256), 256>>>(x, P.col, tot);
        launch_gemm(0, false, false, P.col, P.wpat, patch_b, nullptr, P.pat, nullptr,
                    BATCH * NPATCH, EMB, EMB);
        long ta = (long)BATCH * NTOK * EMB;
        assemble_k<<<(unsigned)((ta + 255) / 256), 256>>>(P.lat3, cls_tok, P.pat,
                                                          pos_emb, P.tok, ta);
    }

    // --- 6 fixed blocks on 198 tokens ---
    for (int l = 0; l < NFIX; l++)
        run_block(P, P.tok, NTOK, l, ln1_g, ln1_b, qkv_b, proj_b,
                  ln2_g, ln2_b, fc1_b, fc2_b);

    // --- scheduler gating ---
    sched_k<<<BATCH, 32>>>(P.tok, sched_w, sched_b, budget, P.actv);

    // --- adaptive blocks on 197 tokens ---
    const long tlen = (long)BATCH * NT2 * EMB;
    extract_k<<<(unsigned)((tlen + 255) / 256), 256>>>(P.tok, P.t, tlen);
    for (int i = 0; i < NADAPT; i++) {
        copy_k<<<(unsigned)((tlen + 255) / 256), 256>>>(P.t, P.t2, tlen);
        run_block(P, P.t2, NT2, NFIX + i, ln1_g, ln1_b, qkv_b, proj_b,
                  ln2_g, ln2_b, fc1_b, fc2_b);
        merge_k<<<(unsigned)((tlen + 255) / 256), 256>>>(P.t2, P.t, P.actv, i, tlen);
    }

    // --- final LN (only row 0 per sample needed for output) + head ---
    ln_k<<<BATCH, 256>>>(P.t, (long)NT2 * EMB, norm_g, norm_b, P.cls, EMB);
    head_k<<<BATCH, 128>>>(P.cls, head_w, head_b, out);
}

// round 7
// speedup vs baseline: 5.0422x; 1.6480x over previous
#include <cuda_runtime.h>
#include <cuda_fp16.h>
#include <math.h>
#include <stdint.h>

#define BATCH 32
#define EMB   768
#define HEADS 12
#define HD    64
#define NLAYERS 12
#define NFIX  6
#define NADAPT 6
#define MLPD  3072
#define NCLS  100
#define NTOK  198
#define NT2   197
#define PE_NN 100
#define PE_DD 256
#define NPATCH 196

// ---------------- scratch (device globals; no allocation allowed) ------------
__device__ float g_tok [BATCH*NTOK*EMB];
__device__ __align__(16) __half g_xn  [BATCH*NTOK*EMB];
__device__ __align__(16) __half g_qkv [BATCH*NTOK*3*EMB];
__device__ __align__(16) __half g_attb[BATCH*NTOK*EMB];
__device__ __align__(16) __half g_mlpb[BATCH*NTOK*MLPD];
__device__ float g_t   [BATCH*NT2*EMB];
__device__ float g_t2  [BATCH*NT2*EMB];
__device__ __align__(16) __half g_col [BATCH*NPATCH*EMB];
__device__ float g_pat [BATCH*NPATCH*EMB];
__device__ float g_lat1[BATCH*EMB];
__device__ __align__(16) __half g_lat2[BATCH*EMB];
__device__ float g_lat3[BATCH*EMB];
__device__ __align__(16) __half g_cls [BATCH*EMB];
__device__ int   g_actv[BATCH*NADAPT];
__device__ __align__(16) __half g_wqkv [NLAYERS*3*EMB*EMB];
__device__ __align__(16) __half g_wproj[NLAYERS*EMB*EMB];
__device__ __align__(16) __half g_wfc1 [NLAYERS*MLPD*EMB];
__device__ __align__(16) __half g_wfc2 [NLAYERS*EMB*MLPD];
__device__ __align__(16) __half g_wlat2[EMB*EMB];
__device__ __align__(16) __half g_wpat [EMB*EMB];

__device__ __forceinline__ float gelu_f(float v) {
    return 0.5f * v * (1.0f + erff(v * 0.70710678118654752440f));
}
__device__ __forceinline__ uint32_t smem_u32(const void* p) {
    uint32_t a;
    asm("{ .reg .u64 t; cvta.to.shared.u64 t, %1; cvt.u32.u64 %0, t; }" : "=r"(a) : "l"(p));
    return a;
}
__device__ __forceinline__ uint32_t h2_u32(__half2 h) {
    uint32_t u;
    *(__half2*)&u = h;
    return u;
}
__device__ __forceinline__ void cp16(uint32_t dst, const void* src, bool pred) {
    int sz = pred ? 16 : 0;
    asm volatile("cp.async.cg.shared.global [%0], [%1], 16, %2;"
                 :: "r"(dst), "l"(src), "r"(sz) : "memory");
}
__device__ __forceinline__ void mma_f16(float c[4], const uint32_t a[4], const uint32_t b[2]) {
    asm volatile(
        "mma.sync.aligned.m16n8k16.row.col.f32.f16.f16.f32 "
        "{%0,%1,%2,%3}, {%4,%5,%6,%7}, {%8,%9}, {%0,%1,%2,%3};\n"
        : "+f"(c[0]), "+f"(c[1]), "+f"(c[2]), "+f"(c[3])
        : "r"(a[0]), "r"(a[1]), "r"(a[2]), "r"(a[3]), "r"(b[0]), "r"(b[1]));
}

// ---------------- fp16 tensor-core GEMM: C = A[M,K] @ Bt[N,K]^T -------------
#define HSTRIDE 40
template<int ACT, bool RES, bool OUTH>
__global__ void __launch_bounds__(256) hgemm_k(
    const __half* __restrict__ A, const __half* __restrict__ Bt,
    const float* __restrict__ bias, const float* __restrict__ res,
    float* __restrict__ Cf, __half* __restrict__ Ch, int M, int N, int K)
{
    __shared__ __align__(16) __half sA[2][128 * HSTRIDE];
    __shared__ __align__(16) __half sB[2][128 * HSTRIDE];

    const int tid  = threadIdx.x;
    const int warp = tid >> 5, lane = tid & 31;
    const int brow = blockIdx.y * 128;
    const int bcol = blockIdx.x * 128;
    const int warpM = (warp >> 2) * 64;
    const int warpN = (warp & 3) * 32;
    const int g4 = lane >> 2, l2 = (lane & 3) * 2;

    const uint32_t sa0 = smem_u32(&sA[0][0]), sa1 = smem_u32(&sA[1][0]);
    const uint32_t sb0 = smem_u32(&sB[0][0]), sb1 = smem_u32(&sB[1][0]);

    float acc[4][4][4];
    #pragma unroll
    for (int i = 0; i < 4; i++)
        #pragma unroll
        for (int j = 0; j < 4; j++)
            #pragma unroll
            for (int r = 0; r < 4; r++) acc[i][j][r] = 0.0f;

    const int nch = K >> 5;
    const int r0 = tid >> 2, r1 = (tid + 256) >> 2;
    const int cb0 = (tid & 3), cb1 = ((tid + 256) & 3);

    auto LOAD = [&](int chunk, int st) {
        const int k0 = chunk << 5;
        const uint32_t da = st ? sa1 : sa0;
        const uint32_t db = st ? sb1 : sb0;
        cp16(da + r0 * (HSTRIDE * 2) + cb0 * 16,
             A + (size_t)(brow + r0) * K + k0 + cb0 * 8, (brow + r0) < M);
        cp16(da + r1 * (HSTRIDE * 2) + cb1 * 16,
             A + (size_t)(brow + r1) * K + k0 + cb1 * 8, (brow + r1) < M);
        cp16(db + r0 * (HSTRIDE * 2) + cb0 * 16,
             Bt + (size_t)(bcol + r0) * K + k0 + cb0 * 8, true);
        cp16(db + r1 * (HSTRIDE * 2) + cb1 * 16,
             Bt + (size_t)(bcol + r1) * K + k0 + cb1 * 8, true);
        asm volatile("cp.async.commit_group;" ::: "memory");
    };

    LOAD(0, 0);

    for (int c = 0; c < nch; c++) {
        const int st = c & 1;
        if (c + 1 < nch) {
            LOAD(c + 1, st ^ 1);
            asm volatile("cp.async.wait_group 1;" ::: "memory");
        } else {
            asm volatile("cp.async.wait_group 0;" ::: "memory");
        }
        __syncthreads();

        const __half* As = sA[st];
        const __half* Bs = sB[st];
        #pragma unroll
        for (int ks = 0; ks < 2; ks++) {
            const int kk = ks * 16 + l2;
            uint32_t af[4][4], bf[4][2];
            #pragma unroll
            for (int tm = 0; tm < 4; tm++) {
                const int m = warpM + tm * 16 + g4;
                af[tm][0] = *(const uint32_t*)&As[m * HSTRIDE + kk];
                af[tm][1] = *(const uint32_t*)&As[(m + 8) * HSTRIDE + kk];
                af[tm][2] = *(const uint32_t*)&As[m * HSTRIDE + kk + 8];
                af[tm][3] = *(const uint32_t*)&As[(m + 8) * HSTRIDE + kk + 8];
            }
            #pragma unroll
            for (int tn = 0; tn < 4; tn++) {
                const int n = warpN + tn * 8 + g4;
                bf[tn][0] = *(const uint32_t*)&Bs[n * HSTRIDE + kk];
                bf[tn][1] = *(const uint32_t*)&Bs[n * HSTRIDE + kk + 8];
            }
            #pragma unroll
            for (int tm = 0; tm < 4; tm++)
                #pragma unroll
                for (int tn = 0; tn < 4; tn++)
                    mma_f16(acc[tm][tn], af[tm], bf[tn]);
        }
        __syncthreads();
    }

    #pragma unroll
    for (int tm = 0; tm < 4; tm++) {
        const int rr = brow + warpM + tm * 16 + g4;
        #pragma unroll
        for (int half = 0; half < 2; half++) {
            const int gr = rr + half * 8;
            if (gr >= M) continue;
            #pragma unroll
            for (int tn = 0; tn < 4; tn++) {
                const int gc = bcol + warpN + tn * 8 + l2;
                float o0 = acc[tm][tn][half * 2 + 0] + bias[gc];
                float o1 = acc[tm][tn][half * 2 + 1] + bias[gc + 1];
                if (ACT == 1) { o0 = gelu_f(o0); o1 = gelu_f(o1); }
                if (RES) {
                    o0 += res[(size_t)gr * N + gc];
                    o1 += res[(size_t)gr * N + gc + 1];
                }
                if (OUTH) {
                    *(__half2*)&Ch[(size_t)gr * N + gc] = __floats2half2_rn(o0, o1);
                } else {
                    Cf[(size_t)gr * N + gc]     = o0;
                    Cf[(size_t)gr * N + gc + 1] = o1;
                }
            }
        }
    }
}

// ---------------- weight transpose+convert ----------------------------------
__global__ void transpose_k(const float* __restrict__ in, __half* __restrict__ out,
                            int K, int N)
{
    __shared__ float t[32][33];
    const int l = blockIdx.z;
    const float* ip = in  + (size_t)l * K * N;
    __half*      op = out + (size_t)l * K * N;
    const int k0 = blockIdx.y * 32, n0 = blockIdx.x * 32;
    #pragma unroll
    for (int i = 0; i < 32; i += 8) {
        int k = k0 + threadIdx.y + i, n = n0 + threadIdx.x;
        if (k < K && n < N) t[threadIdx.y + i][threadIdx.x] = ip[(size_t)k * N + n];
    }
    __syncthreads();
    #pragma unroll
    for (int i = 0; i < 32; i += 8) {
        int n = n0 + threadIdx.y + i, k = k0 + threadIdx.x;
        if (n < N && k < K) op[(size_t)n * K + k] = __float2half_rn(t[threadIdx.x][threadIdx.y + i]);
    }
}

__global__ void cvt_k(const float* __restrict__ in, __half* __restrict__ out, long n)
{
    long i = (long)blockIdx.x * blockDim.x + threadIdx.x;
    if (i < n) out[i] = __float2half_rn(in[i]);
}

// ---------------- LayerNorm over 768 (fp32 in, half out) --------------------
__global__ void ln_k(const float* __restrict__ X, long istride,
                     const float* __restrict__ g, const float* __restrict__ b,
                     __half* __restrict__ Y, long ostride)
{
    const int row = blockIdx.x;
    const int tid = threadIdx.x;
    const float* x = X + (size_t)row * istride;
    __half* y      = Y + (size_t)row * ostride;
    __shared__ float red[8];
    __shared__ float stat[2];

    float v0 = x[tid], v1 = x[tid + 256], v2 = x[tid + 512];
    float s = v0 + v1 + v2;
    #pragma unroll
    for (int o = 16; o; o >>= 1) s += __shfl_xor_sync(~0u, s, o);
    if ((tid & 31) == 0) red[tid >> 5] = s;
    __syncthreads();
    if (tid == 0) {
        float t = 0.f;
        #pragma unroll
        for (int i = 0; i < 8; i++) t += red[i];
        stat[0] = t * (1.0f / 768.0f);
    }
    __syncthreads();
    const float mean = stat[0];
    float d0 = v0 - mean, d1 = v1 - mean, d2 = v2 - mean;
    s = d0 * d0 + d1 * d1 + d2 * d2;
    #pragma unroll
    for (int o = 16; o; o >>= 1) s += __shfl_xor_sync(~0u, s, o);
    __syncthreads();
    if ((tid & 31) == 0) red[tid >> 5] = s;
    __syncthreads();
    if (tid == 0) {
        float t = 0.f;
        #pragma unroll
        for (int i = 0; i < 8; i++) t += red[i];
        stat[1] = rsqrtf(t * (1.0f / 768.0f) + 1e-5f);
    }
    __syncthreads();
    const float rstd = stat[1];
    y[tid]       = __float2half_rn(d0 * rstd * g[tid]       + b[tid]);
    y[tid + 256] = __float2half_rn(d1 * rstd * g[tid + 256] + b[tid + 256]);
    y[tid + 512] = __float2half_rn(d2 * rstd * g[tid + 512] + b[tid + 512]);
}

// ---------------- tensor-core attention: one CTA (128 thr) per (b,h) --------
#define APAD 208
#define KST  72
#define VST  216
#define ATTN_SMEM_BYTES ((2*APAD*KST + 64*VST) * 2)

__global__ void __launch_bounds__(128) attn_k(const __half* __restrict__ qkv,
                                              __half* __restrict__ O, int N)
{
    extern __shared__ __half smh[];
    __half* Qs = smh;
    __half* Ks = Qs + APAD * KST;
    __half* Vt = Ks + APAD * KST;

    const int bh = blockIdx.x;
    const int b  = bh / HEADS, h = bh % HEADS;
    const int tid = threadIdx.x;
    const int w = tid >> 5, lane = tid & 31;
    const int g4 = lane >> 2, l2 = (lane & 3) * 2;
    const __half* base = qkv + (size_t)b * N * (3 * EMB) + h * 64;

    for (int n = tid; n < APAD; n += 128) {
        uint4* qd = (uint4*)&Qs[n * KST];
        uint4* kd = (uint4*)&Ks[n * KST];
        if (n < N) {
            const uint4* qs = (const uint4*)(base + (size_t)n * (3 * EMB));
            const uint4* ks = (const uint4*)(base + (size_t)n * (3 * EMB) + EMB);
            #pragma unroll
            for (int i = 0; i < 8; i++) { qd[i] = qs[i]; kd[i] = ks[i]; }
        } else {
            uint4 z = make_uint4(0, 0, 0, 0);
            #pragma unroll
            for (int i = 0; i < 8; i++) { qd[i] = z; kd[i] = z; }
        }
    }
    for (int idx = tid; idx < APAD * 64; idx += 128) {
        const int n = idx >> 6, d = idx & 63;
        __half v = (n < N) ? base[(size_t)n * (3 * EMB) + 2 * EMB + d] : __ushort_as_half(0);
        Vt[d * VST + n] = v;
    }
    __syncthreads();

    for (int qt = w; qt < 13; qt += 4) {
        const int q0 = qt * 16;
        uint32_t aq[4][4];
        #pragma unroll
        for (int ks = 0; ks < 4; ks++) {
            const int kk = ks * 16 + l2;
            aq[ks][0] = *(const uint32_t*)&Qs[(q0 + g4) * KST + kk];
            aq[ks][1] = *(const uint32_t*)&Qs[(q0 + g4 + 8) * KST + kk];
            aq[ks][2] = *(const uint32_t*)&Qs[(q0 + g4) * KST + kk + 8];
            aq[ks][3] = *(const uint32_t*)&Qs[(q0 + g4 + 8) * KST + kk + 8];
        }
        float sc[26][4];
        #pragma unroll
        for (int nt = 0; nt < 26; nt++) {
            sc[nt][0] = sc[nt][1] = sc[nt][2] = sc[nt][3] = 0.f;
            #pragma unroll
            for (int ks = 0; ks < 4; ks++) {
                const int kk = ks * 16 + l2;
                uint32_t bf[2];
                bf[0] = *(const uint32_t*)&Ks[(nt * 8 + g4) * KST + kk];
                bf[1] = *(const uint32_t*)&Ks[(nt * 8 + g4) * KST + kk + 8];
                mma_f16(sc[nt], aq[ks], bf);
            }
        }
        float m0 = -1e30f, m1 = -1e30f;
        #pragma unroll
        for (int nt = 0; nt < 26; nt++) {
            #pragma unroll
            for (int e = 0; e < 2; e++) {
                const int col = nt * 8 + l2 + e;
                const bool ok = col < N;
                float v0 = ok ? sc[nt][e]     * 0.125f : -1e30f;
                float v1 = ok ? sc[nt][2 + e] * 0.125f : -1e30f;
                sc[nt][e] = v0; sc[nt][2 + e] = v1;
                m0 = fmaxf(m0, v0); m1 = fmaxf(m1, v1);
            }
        }
        m0 = fmaxf(m0, __shfl_xor_sync(~0u, m0, 1));
        m0 = fmaxf(m0, __shfl_xor_sync(~0u, m0, 2));
        m1 = fmaxf(m1, __shfl_xor_sync(~0u, m1, 1));
        m1 = fmaxf(m1, __shfl_xor_sync(~0u, m1, 2));
        float s0 = 0.f, s1 = 0.f;
        #pragma unroll
        for (int nt = 0; nt < 26; nt++) {
            #pragma unroll
            for (int e = 0; e < 2; e++) {
                float e0 = __expf(sc[nt][e]     - m0);
                float e1 = __expf(sc[nt][2 + e] - m1);
                sc[nt][e] = e0; sc[nt][2 + e] = e1;
                s0 += e0; s1 += e1;
            }
        }
        s0 += __shfl_xor_sync(~0u, s0, 1); s0 += __shfl_xor_sync(~0u, s0, 2);
        s1 += __shfl_xor_sync(~0u, s1, 1); s1 += __shfl_xor_sync(~0u, s1, 2);
        const float i0 = 1.0f / s0, i1 = 1.0f / s1;
        float o[8][4];
        #pragma unroll
        for (int dt = 0; dt < 8; dt++) o[dt][0] = o[dt][1] = o[dt][2] = o[dt][3] = 0.f;
        #pragma unroll
        for (int kt = 0; kt < 13; kt++) {
            uint32_t ap[4];
            ap[0] = h2_u32(__floats2half2_rn(sc[2*kt][0]   * i0, sc[2*kt][1]   * i0));
            ap[1] = h2_u32(__floats2half2_rn(sc[2*kt][2]   * i1, sc[2*kt][3]   * i1));
            ap[2] = h2_u32(__floats2half2_rn(sc[2*kt+1][0] * i0, sc[2*kt+1][1] * i0));
            ap[3] = h2_u32(__floats2half2_rn(sc[2*kt+1][2] * i1, sc[2*kt+1][3] * i1));
            #pragma unroll
            for (int dt = 0; dt < 8; dt++) {
                uint32_t bv[2];
                bv[0] = *(const uint32_t*)&Vt[(dt * 8 + g4) * VST + kt * 16 + l2];
                bv[1] = *(const uint32_t*)&Vt[(dt * 8 + g4) * VST + kt * 16 + l2 + 8];
                mma_f16(o[dt], ap, bv);
            }
        }
        const int r0 = q0 + g4, r1 = q0 + g4 + 8;
        __half* ob = O + h * 64;
        #pragma unroll
        for (int dt = 0; dt < 8; dt++) {
            const int c = dt * 8 + l2;
            if (r0 < N)
                *(__half2*)&ob[((size_t)b * N + r0) * EMB + c] = __floats2half2_rn(o[dt][0], o[dt][1]);
            if (r1 < N)
                *(__half2*)&ob[((size_t)b * N + r1) * EMB + c] = __floats2half2_rn(o[dt][2], o[dt][3]);
        }
    }
}

// ---------------- small / elementwise kernels -------------------------------
__global__ void im2col_k(const float* __restrict__ x, __half* __restrict__ col, long total)
{
    long i = (long)blockIdx.x * blockDim.x + threadIdx.x;
    if (i >= total) return;
    int k = (int)(i % EMB);
    long m = i / EMB;
    int b = (int)(m / NPATCH), p = (int)(m % NPATCH);
    int c = k >> 8, r = k & 255, ii = r >> 4, jj = r & 15;
    int py = p / 14, px = p % 14;
    col[i] = __float2half_rn(x[(((size_t)b * 3 + c) * 224 + py * 16 + ii) * 224 + px * 16 + jj]);
}

__global__ void lat1_k(const float* __restrict__ pe, const float* __restrict__ w1,
                       const float* __restrict__ b1, const float* __restrict__ budget,
                       float* __restrict__ out)
{
    int b = blockIdx.x;
    int idx = (int)rintf(budget[b] * (float)(PE_NN - 1));
    const float* row = pe + (size_t)idx * PE_DD;
    for (int e = threadIdx.x; e < EMB; e += 256) {
        float s = b1[e];
        for (int k = 0; k < PE_DD; k++) s += row[k] * w1[(size_t)k * EMB + e];
        out[(size_t)b * EMB + e] = gelu_f(s);
    }
}

__global__ void assemble_k(const float* __restrict__ lat, const float* __restrict__ cls,
                           const float* __restrict__ pat, const float* __restrict__ pos,
                           float* __restrict__ tok, long total)
{
    long i = (long)blockIdx.x * blockDim.x + threadIdx.x;
    if (i >= total) return;
    int e = (int)(i % EMB);
    long bn = i / EMB;
    int n = (int)(bn % NTOK), b = (int)(bn / NTOK);
    float v;
    if (n == 0)      v = lat[(size_t)b * EMB + e];
    else if (n == 1) v = cls[e];
    else             v = pat[((size_t)b * NPATCH + (n - 2)) * EMB + e];
    tok[i] = v + pos[(size_t)n * EMB + e];
}

__global__ void sched_k(const float* __restrict__ tok, const float* __restrict__ sw,
                        const float* __restrict__ sb, const float* __restrict__ budget,
                        int* __restrict__ active)
{
    int b = blockIdx.x, lane = threadIdx.x;
    __shared__ float lg[NADAPT];
    if (lane < NADAPT) {
        const float* x = tok + (size_t)b * NTOK * EMB;
        float s = sb[lane];
        for (int k = 0; k < EMB; k++) s += x[k] * sw[(size_t)k * NADAPT + lane];
        lg[lane] = s;
    }
    __syncwarp();
    if (lane < NADAPT) {
        int kk = (int)ceilf(budget[b] * (float)NADAPT);
        if (kk < 1) kk = 1;
        int rank = 0;
        for (int j = 0; j < NADAPT; j++)
            if (lg[j] > lg[lane] || (lg[j] == lg[lane] && j < lane)) rank++;
        active[b * NADAPT + lane] = (rank < kk) ? 1 : 0;
    }
}

__global__ void extract_k(const float* __restrict__ tok, float* __restrict__ t, long total)
{
    long i = (long)blockIdx.x * blockDim.x + threadIdx.x;
    if (i >= total) return;
    int e = (int)(i % EMB);
    long bn = i / EMB;
    int n = (int)(bn % NT2), b = (int)(bn / NT2);
    t[i] = tok[((size_t)b * NTOK + n + 1) * EMB + e];
}

__global__ void copy_k(const float* __restrict__ s, float* __restrict__ d, long n)
{
    long i = (long)blockIdx.x * blockDim.x + threadIdx.x;
    if (i < n) d[i] = s[i];
}

__global__ void merge_k(const float* __restrict__ t2, float* __restrict__ t,
                        const int* __restrict__ active, int layer, long total)
{
    long i = (long)blockIdx.x * blockDim.x + threadIdx.x;
    if (i >= total) return;
    int b = (int)(i / ((long)NT2 * EMB));
    if (active[b * NADAPT + layer]) t[i] = t2[i];
}

__global__ void head_k(const __half* __restrict__ cls, const float* __restrict__ w,
                       const float* __restrict__ bias, float* __restrict__ out)
{
    int b = blockIdx.x, c = threadIdx.x;
    if (c >= NCLS) return;
    const __half* x = cls + (size_t)b * EMB;
    float s = bias[c];
    for (int k = 0; k < EMB; k++) s += __half2float(x[k]) * w[(size_t)k * NCLS + c];
    out[(size_t)b * NCLS + c] = s;
}

// ---------------- host orchestration ----------------------------------------
static inline void launch_gemm(int act, bool res, bool outh,
                               const __half* A, const __half* Bt, const float* bias,
                               const float* r, float* Cf, __half* Ch, int M, int N, int K)
{
    dim3 g(N / 128, (M + 127) / 128), blk(256);
    if (outh) {
        if (act == 1)      hgemm_k<1, false, true><<<g, blk>>>(A, Bt, bias, r, Cf, Ch, M, N, K);
        else               hgemm_k<0, false, true><<<g, blk>>>(A, Bt, bias, r, Cf, Ch, M, N, K);
    } else {
        if (res)           hgemm_k<0, true,  false><<<g, blk>>>(A, Bt, bias, r, Cf, Ch, M, N, K);
        else               hgemm_k<0, false, false><<<g, blk>>>(A, Bt, bias, r, Cf, Ch, M, N, K);
    }
}

struct Ptrs {
    float *tok, *t, *t2, *pat, *lat1, *lat3;
    __half *xn, *qkv, *att, *mlp, *col, *lat2, *cls;
    __half *wqkv, *wproj, *wfc1, *wfc2, *wlat2, *wpat;
    int   *actv;
};

static void run_block(const Ptrs& P, float* X, int N, int l,
                      const float* ln1g, const float* ln1b, const float* qkvb,
                      const float* projb, const float* ln2g, const float* ln2b,
                      const float* fc1b, const float* fc2b)
{
    const int M = BATCH * N;
    ln_k<<<M, 256>>>(X, EMB, ln1g + (size_t)l * EMB, ln1b + (size_t)l * EMB, P.xn, EMB);
    launch_gemm(0, false, true, P.xn, P.wqkv + (size_t)l * EMB * 3 * EMB,
                qkvb + (size_t)l * 3 * EMB, nullptr, nullptr, P.qkv, M, 3 * EMB, EMB);
    attn_k<<<BATCH * HEADS, 128, ATTN_SMEM_BYTES>>>(P.qkv, P.att, N);
    launch_gemm(0, true, false, P.att, P.wproj + (size_t)l * EMB * EMB,
                projb + (size_t)l * EMB, X, X, nullptr, M, EMB, EMB);
    ln_k<<<M, 256>>>(X, EMB, ln2g + (size_t)l * EMB, ln2b + (size_t)l * EMB, P.xn, EMB);
    launch_gemm(1, false, true, P.xn, P.wfc1 + (size_t)l * EMB * MLPD,
                fc1b + (size_t)l * MLPD, nullptr, nullptr, P.mlp, M, MLPD, EMB);
    launch_gemm(0, true, false, P.mlp, P.wfc2 + (size_t)l * MLPD * EMB,
                fc2b + (size_t)l * EMB, X, X, nullptr, M, EMB, MLPD);
}

extern "C" void kernel_launch(void* const* d_in, const int* in_sizes, int n_in,
                              void* d_out, int out_size)
{
    const float* x        = (const float*)d_in[0];
    const float* budget   = (const float*)d_in[1];
    const float* pe_table = (const float*)d_in[2];
    const float* lat_w1   = (const float*)d_in[3];
    const float* lat_b1   = (const float*)d_in[4];
    const float* lat_ln_g = (const float*)d_in[5];
    const float* lat_ln_b = (const float*)d_in[6];
    const float* lat_w2   = (const float*)d_in[7];
    const float* lat_b2   = (const float*)d_in[8];
    const float* patch_w  = (const float*)d_in[9];
    const float* patch_b  = (const float*)d_in[10];
    const float* cls_tok  = (const float*)d_in[11];
    const float* pos_emb  = (const float*)d_in[12];
    const float* sched_w  = (const float*)d_in[13];
    const float* sched_b  = (const float*)d_in[14];
    const float* ln1_g    = (const float*)d_in[15];
    const float* ln1_b    = (const float*)d_in[16];
    const float* qkv_w    = (const float*)d_in[17];
    const float* qkv_b    = (const float*)d_in[18];
    const float* proj_w   = (const float*)d_in[19];
    const float* proj_b   = (const float*)d_in[20];
    const float* ln2_g    = (const float*)d_in[21];
    const float* ln2_b    = (const float*)d_in[22];
    const float* fc1_w    = (const float*)d_in[23];
    const float* fc1_b    = (const float*)d_in[24];
    const float* fc2_w    = (const float*)d_in[25];
    const float* fc2_b    = (const float*)d_in[26];
    const float* norm_g   = (const float*)d_in[27];
    const float* norm_b   = (const float*)d_in[28];
    const float* head_w   = (const float*)d_in[29];
    const float* head_b   = (const float*)d_in[30];
    float* out = (float*)d_out;

    Ptrs P;
    cudaGetSymbolAddress((void**)&P.tok,  g_tok);
    cudaGetSymbolAddress((void**)&P.xn,   g_xn);
    cudaGetSymbolAddress((void**)&P.qkv,  g_qkv);
    cudaGetSymbolAddress((void**)&P.att,  g_attb);
    cudaGetSymbolAddress((void**)&P.mlp,  g_mlpb);
    cudaGetSymbolAddress((void**)&P.t,    g_t);
    cudaGetSymbolAddress((void**)&P.t2,   g_t2);
    cudaGetSymbolAddress((void**)&P.col,  g_col);
    cudaGetSymbolAddress((void**)&P.pat,  g_pat);
    cudaGetSymbolAddress((void**)&P.lat1, g_lat1);
    cudaGetSymbolAddress((void**)&P.lat2, g_lat2);
    cudaGetSymbolAddress((void**)&P.lat3, g_lat3);
    cudaGetSymbolAddress((void**)&P.cls,  g_cls);
    cudaGetSymbolAddress((void**)&P.actv, g_actv);
    cudaGetSymbolAddress((void**)&P.wqkv, g_wqkv);
    cudaGetSymbolAddress((void**)&P.wproj,g_wproj);
    cudaGetSymbolAddress((void**)&P.wfc1, g_wfc1);
    cudaGetSymbolAddress((void**)&P.wfc2, g_wfc2);
    cudaGetSymbolAddress((void**)&P.wlat2,g_wlat2);
    cudaGetSymbolAddress((void**)&P.wpat, g_wpat);

    cudaFuncSetAttribute(attn_k, cudaFuncAttributeMaxDynamicSharedMemorySize, ATTN_SMEM_BYTES);

    // --- weight transposes+convert ([K,N] fp32 -> [N,K] half) ---
    {
        dim3 b32(32, 8);
        transpose_k<<<dim3(3*EMB/32, EMB/32, NLAYERS), b32>>>(qkv_w,  P.wqkv,  EMB, 3*EMB);
        transpose_k<<<dim3(EMB/32,   EMB/32, NLAYERS), b32>>>(proj_w, P.wproj, EMB, EMB);
        transpose_k<<<dim3(MLPD/32,  EMB/32, NLAYERS), b32>>>(fc1_w,  P.wfc1,  EMB, MLPD);
        transpose_k<<<dim3(EMB/32,  MLPD/32, NLAYERS), b32>>>(fc2_w,  P.wfc2,  MLPD, EMB);
        transpose_k<<<dim3(EMB/32,   EMB/32, 1),       b32>>>(lat_w2, P.wlat2, EMB, EMB);
        long pw = (long)EMB * EMB;
        cvt_k<<<(unsigned)((pw + 255) / 256), 256>>>(patch_w, P.wpat, pw);
    }

    // --- latent token ---
    lat1_k<<<BATCH, 256>>>(pe_table, lat_w1, lat_b1, budget, P.lat1);
    ln_k<<<BATCH, 256>>>(P.lat1, EMB, lat_ln_g, lat_ln_b, P.lat2, EMB);
    launch_gemm(0, false, false, P.lat2, P.wlat2, lat_b2, nullptr, P.lat3, nullptr,
                BATCH, EMB, EMB);

    // --- patch embedding ---
    {
        long tot = (long)BATCH * NPATCH * EMB;
        im2col_k<<<(unsigned)((tot + 255) / 256), 256>>>(x, P.col, tot);
        launch_gemm(0, false, false, P.col, P.wpat, patch_b, nullptr, P.pat, nullptr,
                    BATCH * NPATCH, EMB, EMB);
        long ta = (long)BATCH * NTOK * EMB;
        assemble_k<<<(unsigned)((ta + 255) / 256), 256>>>(P.lat3, cls_tok, P.pat,
                                                          pos_emb, P.tok, ta);
    }

    // --- 6 fixed blocks on 198 tokens ---
    for (int l = 0; l < NFIX; l++)
        run_block(P, P.tok, NTOK, l, ln1_g, ln1_b, qkv_b, proj_b,
                  ln2_g, ln2_b, fc1_b, fc2_b);

    // --- scheduler gating ---
    sched_k<<<BATCH, 32>>>(P.tok, sched_w, sched_b, budget, P.actv);

    // --- adaptive blocks on 197 tokens ---
    const long tlen = (long)BATCH * NT2 * EMB;
    extract_k<<<(unsigned)((tlen + 255) / 256), 256>>>(P.tok, P.t, tlen);
    for (int i = 0; i < NADAPT; i++) {
        copy_k<<<(unsigned)((tlen + 255) / 256), 256>>>(P.t, P.t2, tlen);
        run_block(P, P.t2, NT2, NFIX + i, ln1_g, ln1_b, qkv_b, proj_b,
                  ln2_g, ln2_b, fc1_b, fc2_b);
        merge_k<<<(unsigned)((tlen + 255) / 256), 256>>>(P.t2, P.t, P.actv, i, tlen);
    }

    // --- final LN (only row 0 per sample needed for output) + head ---
    ln_k<<<BATCH, 256>>>(P.t, (long)NT2 * EMB, norm_g, norm_b, P.cls, EMB);
    head_k<<<BATCH, 128>>>(P.cls, head_w, head_b, out);
}

// round 8
// speedup vs baseline: 5.6690x; 1.1243x over previous
#include <cuda_runtime.h>
#include <cuda_fp16.h>
#include <math.h>
#include <stdint.h>

#define BATCH 32
#define EMB   768
#define HEADS 12
#define HD    64
#define NLAYERS 12
#define NFIX  6
#define NADAPT 6
#define MLPD  3072
#define NCLS  100
#define NTOK  198
#define NT2   197
#define PE_NN 100
#define PE_DD 256
#define NPATCH 196

// ---------------- scratch (device globals; no allocation allowed) ------------
__device__ float g_tok [BATCH*NTOK*EMB];
__device__ __align__(16) __half g_xn  [BATCH*NTOK*EMB];
__device__ __align__(16) __half g_qkv [BATCH*NTOK*3*EMB];
__device__ __align__(16) __half g_attb[BATCH*NTOK*EMB];
__device__ __align__(16) __half g_mlpb[BATCH*NTOK*MLPD];
__device__ float g_t   [BATCH*NT2*EMB];
__device__ float g_t2  [BATCH*NT2*EMB];
__device__ __align__(16) __half g_col [BATCH*NPATCH*EMB];
__device__ float g_pat [BATCH*NPATCH*EMB];
__device__ float g_lat1[BATCH*EMB];
__device__ __align__(16) __half g_lat2[BATCH*EMB];
__device__ float g_lat3[BATCH*EMB];
__device__ __align__(16) __half g_cls [BATCH*EMB];
__device__ int   g_actv[BATCH*NADAPT];
__device__ __align__(16) __half g_wqkv [NLAYERS*3*EMB*EMB];
__device__ __align__(16) __half g_wproj[NLAYERS*EMB*EMB];
__device__ __align__(16) __half g_wfc1 [NLAYERS*MLPD*EMB];
__device__ __align__(16) __half g_wfc2 [NLAYERS*EMB*MLPD];
__device__ __align__(16) __half g_wlat2[EMB*EMB];
__device__ __align__(16) __half g_wpat [EMB*EMB];

__device__ __forceinline__ float gelu_f(float v) {
    return 0.5f * v * (1.0f + erff(v * 0.70710678118654752440f));
}
__device__ __forceinline__ uint32_t smem_u32(const void* p) {
    uint32_t a;
    asm("{ .reg .u64 t; cvta.to.shared.u64 t, %1; cvt.u32.u64 %0, t; }" : "=r"(a) : "l"(p));
    return a;
}
__device__ __forceinline__ uint32_t h2_u32(__half2 h) {
    uint32_t u;
    *(__half2*)&u = h;
    return u;
}
__device__ __forceinline__ void cp16(uint32_t dst, const void* src, bool pred) {
    int sz = pred ? 16 : 0;
    asm volatile("cp.async.cg.shared.global [%0], [%1], 16, %2;"
                 :: "r"(dst), "l"(src), "r"(sz) : "memory");
}
__device__ __forceinline__ void mma_f16(float c[4], const uint32_t a[4], const uint32_t b[2]) {
    asm volatile(
        "mma.sync.aligned.m16n8k16.row.col.f32.f16.f16.f32 "
        "{%0,%1,%2,%3}, {%4,%5,%6,%7}, {%8,%9}, {%0,%1,%2,%3};\n"
        : "+f"(c[0]), "+f"(c[1]), "+f"(c[2]), "+f"(c[3])
        : "r"(a[0]), "r"(a[1]), "r"(a[2]), "r"(a[3]), "r"(b[0]), "r"(b[1]));
}

// ---------------- fp16 tensor-core GEMM: C = A[M,K] @ Bt[N,K]^T -------------
// gate: optional per-sample active flags (stride gstride), rps rows/sample.
#define HSTRIDE 40
template<int ACT, bool RES, bool OUTH>
__global__ void __launch_bounds__(256) hgemm_k(
    const __half* __restrict__ A, const __half* __restrict__ Bt,
    const float* __restrict__ bias, const float* __restrict__ res,
    float* __restrict__ Cf, __half* __restrict__ Ch, int M, int N, int K,
    const int* __restrict__ gate, int gstride, int rps)
{
    const int brow = blockIdx.y * 128;
    if (gate) {
        const int s0 = brow / rps;
        const int s1 = min(brow + 127, M - 1) / rps;
        bool any = false;
        for (int s = s0; s <= s1; s++) any |= (gate[s * gstride] != 0);
        if (!any) return;
    }

    __shared__ __align__(16) __half sA[2][128 * HSTRIDE];
    __shared__ __align__(16) __half sB[2][128 * HSTRIDE];

    const int tid  = threadIdx.x;
    const int warp = tid >> 5, lane = tid & 31;
    const int bcol = blockIdx.x * 128;
    const int warpM = (warp >> 2) * 64;
    const int warpN = (warp & 3) * 32;
    const int g4 = lane >> 2, l2 = (lane & 3) * 2;

    const uint32_t sa0 = smem_u32(&sA[0][0]), sa1 = smem_u32(&sA[1][0]);
    const uint32_t sb0 = smem_u32(&sB[0][0]), sb1 = smem_u32(&sB[1][0]);

    float acc[4][4][4];
    #pragma unroll
    for (int i = 0; i < 4; i++)
        #pragma unroll
        for (int j = 0; j < 4; j++)
            #pragma unroll
            for (int r = 0; r < 4; r++) acc[i][j][r] = 0.0f;

    const int nch = K >> 5;
    const int r0 = tid >> 2, r1 = (tid + 256) >> 2;
    const int cb0 = (tid & 3), cb1 = ((tid + 256) & 3);

    auto LOAD = [&](int chunk, int st) {
        const int k0 = chunk << 5;
        const uint32_t da = st ? sa1 : sa0;
        const uint32_t db = st ? sb1 : sb0;
        cp16(da + r0 * (HSTRIDE * 2) + cb0 * 16,
             A + (size_t)(brow + r0) * K + k0 + cb0 * 8, (brow + r0) < M);
        cp16(da + r1 * (HSTRIDE * 2) + cb1 * 16,
             A + (size_t)(brow + r1) * K + k0 + cb1 * 8, (brow + r1) < M);
        cp16(db + r0 * (HSTRIDE * 2) + cb0 * 16,
             Bt + (size_t)(bcol + r0) * K + k0 + cb0 * 8, true);
        cp16(db + r1 * (HSTRIDE * 2) + cb1 * 16,
             Bt + (size_t)(bcol + r1) * K + k0 + cb1 * 8, true);
        asm volatile("cp.async.commit_group;" ::: "memory");
    };

    LOAD(0, 0);

    for (int c = 0; c < nch; c++) {
        const int st = c & 1;
        if (c + 1 < nch) {
            LOAD(c + 1, st ^ 1);
            asm volatile("cp.async.wait_group 1;" ::: "memory");
        } else {
            asm volatile("cp.async.wait_group 0;" ::: "memory");
        }
        __syncthreads();

        const __half* As = sA[st];
        const __half* Bs = sB[st];
        #pragma unroll
        for (int ks = 0; ks < 2; ks++) {
            const int kk = ks * 16 + l2;
            uint32_t af[4][4], bf[4][2];
            #pragma unroll
            for (int tm = 0; tm < 4; tm++) {
                const int m = warpM + tm * 16 + g4;
                af[tm][0] = *(const uint32_t*)&As[m * HSTRIDE + kk];
                af[tm][1] = *(const uint32_t*)&As[(m + 8) * HSTRIDE + kk];
                af[tm][2] = *(const uint32_t*)&As[m * HSTRIDE + kk + 8];
                af[tm][3] = *(const uint32_t*)&As[(m + 8) * HSTRIDE + kk + 8];
            }
            #pragma unroll
            for (int tn = 0; tn < 4; tn++) {
                const int n = warpN + tn * 8 + g4;
                bf[tn][0] = *(const uint32_t*)&Bs[n * HSTRIDE + kk];
                bf[tn][1] = *(const uint32_t*)&Bs[n * HSTRIDE + kk + 8];
            }
            #pragma unroll
            for (int tm = 0; tm < 4; tm++)
                #pragma unroll
                for (int tn = 0; tn < 4; tn++)
                    mma_f16(acc[tm][tn], af[tm], bf[tn]);
        }
        __syncthreads();
    }

    #pragma unroll
    for (int tm = 0; tm < 4; tm++) {
        const int rr = brow + warpM + tm * 16 + g4;
        #pragma unroll
        for (int half = 0; half < 2; half++) {
            const int gr = rr + half * 8;
            if (gr >= M) continue;
            #pragma unroll
            for (int tn = 0; tn < 4; tn++) {
                const int gc = bcol + warpN + tn * 8 + l2;
                float o0 = acc[tm][tn][half * 2 + 0] + bias[gc];
                float o1 = acc[tm][tn][half * 2 + 1] + bias[gc + 1];
                if (ACT == 1) { o0 = gelu_f(o0); o1 = gelu_f(o1); }
                if (RES) {
                    o0 += res[(size_t)gr * N + gc];
                    o1 += res[(size_t)gr * N + gc + 1];
                }
                if (OUTH) {
                    *(__half2*)&Ch[(size_t)gr * N + gc] = __floats2half2_rn(o0, o1);
                } else {
                    Cf[(size_t)gr * N + gc]     = o0;
                    Cf[(size_t)gr * N + gc + 1] = o1;
                }
            }
        }
    }
}

// ---------------- weight transpose+convert ----------------------------------
__global__ void transpose_k(const float* __restrict__ in, __half* __restrict__ out,
                            int K, int N)
{
    __shared__ float t[32][33];
    const int l = blockIdx.z;
    const float* ip = in  + (size_t)l * K * N;
    __half*      op = out + (size_t)l * K * N;
    const int k0 = blockIdx.y * 32, n0 = blockIdx.x * 32;
    #pragma unroll
    for (int i = 0; i < 32; i += 8) {
        int k = k0 + threadIdx.y + i, n = n0 + threadIdx.x;
        if (k < K && n < N) t[threadIdx.y + i][threadIdx.x] = ip[(size_t)k * N + n];
    }
    __syncthreads();
    #pragma unroll
    for (int i = 0; i < 32; i += 8) {
        int n = n0 + threadIdx.y + i, k = k0 + threadIdx.x;
        if (n < N && k < K) op[(size_t)n * K + k] = __float2half_rn(t[threadIdx.x][threadIdx.y + i]);
    }
}

__global__ void cvt_k(const float* __restrict__ in, __half* __restrict__ out, long n)
{
    long i = (long)blockIdx.x * blockDim.x + threadIdx.x;
    if (i < n) out[i] = __float2half_rn(in[i]);
}

// ---------------- LayerNorm over 768 (fp32 in, half out), gated -------------
__global__ void ln_k(const float* __restrict__ X, long istride,
                     const float* __restrict__ g, const float* __restrict__ b,
                     __half* __restrict__ Y, long ostride,
                     const int* __restrict__ gate, int gstride, int rps)
{
    const int row = blockIdx.x;
    if (gate && !gate[(row / rps) * gstride]) return;
    const int tid = threadIdx.x;
    const float* x = X + (size_t)row * istride;
    __half* y      = Y + (size_t)row * ostride;
    __shared__ float red[8];
    __shared__ float stat[2];

    float v0 = x[tid], v1 = x[tid + 256], v2 = x[tid + 512];
    float s = v0 + v1 + v2;
    #pragma unroll
    for (int o = 16; o; o >>= 1) s += __shfl_xor_sync(~0u, s, o);
    if ((tid & 31) == 0) red[tid >> 5] = s;
    __syncthreads();
    if (tid == 0) {
        float t = 0.f;
        #pragma unroll
        for (int i = 0; i < 8; i++) t += red[i];
        stat[0] = t * (1.0f / 768.0f);
    }
    __syncthreads();
    const float mean = stat[0];
    float d0 = v0 - mean, d1 = v1 - mean, d2 = v2 - mean;
    s = d0 * d0 + d1 * d1 + d2 * d2;
    #pragma unroll
    for (int o = 16; o; o >>= 1) s += __shfl_xor_sync(~0u, s, o);
    __syncthreads();
    if ((tid & 31) == 0) red[tid >> 5] = s;
    __syncthreads();
    if (tid == 0) {
        float t = 0.f;
        #pragma unroll
        for (int i = 0; i < 8; i++) t += red[i];
        stat[1] = rsqrtf(t * (1.0f / 768.0f) + 1e-5f);
    }
    __syncthreads();
    const float rstd = stat[1];
    y[tid]       = __float2half_rn(d0 * rstd * g[tid]       + b[tid]);
    y[tid + 256] = __float2half_rn(d1 * rstd * g[tid + 256] + b[tid + 256]);
    y[tid + 512] = __float2half_rn(d2 * rstd * g[tid + 512] + b[tid + 512]);
}

// ---------------- tensor-core attention: one CTA (128 thr) per (b,h) --------
#define APAD 208
#define KST  72
#define VST  216
#define ATTN_SMEM_BYTES ((2*APAD*KST + 64*VST) * 2)

__global__ void __launch_bounds__(128) attn_k(const __half* __restrict__ qkv,
                                              __half* __restrict__ O, int N,
                                              const int* __restrict__ gate, int gstride)
{
    const int bh = blockIdx.x;
    const int b  = bh / HEADS, h = bh % HEADS;
    if (gate && !gate[b * gstride]) return;

    extern __shared__ __half smh[];
    __half* Qs = smh;
    __half* Ks = Qs + APAD * KST;
    __half* Vt = Ks + APAD * KST;

    const int tid = threadIdx.x;
    const int w = tid >> 5, lane = tid & 31;
    const int g4 = lane >> 2, l2 = (lane & 3) * 2;
    const __half* base = qkv + (size_t)b * N * (3 * EMB) + h * 64;

    for (int n = tid; n < APAD; n += 128) {
        uint4* qd = (uint4*)&Qs[n * KST];
        uint4* kd = (uint4*)&Ks[n * KST];
        if (n < N) {
            const uint4* qs = (const uint4*)(base + (size_t)n * (3 * EMB));
            const uint4* ks = (const uint4*)(base + (size_t)n * (3 * EMB) + EMB);
            #pragma unroll
            for (int i = 0; i < 8; i++) { qd[i] = qs[i]; kd[i] = ks[i]; }
        } else {
            uint4 z = make_uint4(0, 0, 0, 0);
            #pragma unroll
            for (int i = 0; i < 8; i++) { qd[i] = z; kd[i] = z; }
        }
    }
    for (int idx = tid; idx < APAD * 64; idx += 128) {
        const int n = idx >> 6, d = idx & 63;
        __half v = (n < N) ? base[(size_t)n * (3 * EMB) + 2 * EMB + d] : __ushort_as_half(0);
        Vt[d * VST + n] = v;
    }
    __syncthreads();

    for (int qt = w; qt < 13; qt += 4) {
        const int q0 = qt * 16;
        uint32_t aq[4][4];
        #pragma unroll
        for (int ks = 0; ks < 4; ks++) {
            const int kk = ks * 16 + l2;
            aq[ks][0] = *(const uint32_t*)&Qs[(q0 + g4) * KST + kk];
            aq[ks][1] = *(const uint32_t*)&Qs[(q0 + g4 + 8) * KST + kk];
            aq[ks][2] = *(const uint32_t*)&Qs[(q0 + g4) * KST + kk + 8];
            aq[ks][3] = *(const uint32_t*)&Qs[(q0 + g4 + 8) * KST + kk + 8];
        }
        float sc[26][4];
        #pragma unroll
        for (int nt = 0; nt < 26; nt++) {
            sc[nt][0] = sc[nt][1] = sc[nt][2] = sc[nt][3] = 0.f;
            #pragma unroll
            for (int ks = 0; ks < 4; ks++) {
                const int kk = ks * 16 + l2;
                uint32_t bf[2];
                bf[0] = *(const uint32_t*)&Ks[(nt * 8 + g4) * KST + kk];
                bf[1] = *(const uint32_t*)&Ks[(nt * 8 + g4) * KST + kk + 8];
                mma_f16(sc[nt], aq[ks], bf);
            }
        }
        float m0 = -1e30f, m1 = -1e30f;
        #pragma unroll
        for (int nt = 0; nt < 26; nt++) {
            #pragma unroll
            for (int e = 0; e < 2; e++) {
                const int col = nt * 8 + l2 + e;
                const bool ok = col < N;
                float v0 = ok ? sc[nt][e]     * 0.125f : -1e30f;
                float v1 = ok ? sc[nt][2 + e] * 0.125f : -1e30f;
                sc[nt][e] = v0; sc[nt][2 + e] = v1;
                m0 = fmaxf(m0, v0); m1 = fmaxf(m1, v1);
            }
        }
        m0 = fmaxf(m0, __shfl_xor_sync(~0u, m0, 1));
        m0 = fmaxf(m0, __shfl_xor_sync(~0u, m0, 2));
        m1 = fmaxf(m1, __shfl_xor_sync(~0u, m1, 1));
        m1 = fmaxf(m1, __shfl_xor_sync(~0u, m1, 2));
        float s0 = 0.f, s1 = 0.f;
        #pragma unroll
        for (int nt = 0; nt < 26; nt++) {
            #pragma unroll
            for (int e = 0; e < 2; e++) {
                float e0 = __expf(sc[nt][e]     - m0);
                float e1 = __expf(sc[nt][2 + e] - m1);
                sc[nt][e] = e0; sc[nt][2 + e] = e1;
                s0 += e0; s1 += e1;
            }
        }
        s0 += __shfl_xor_sync(~0u, s0, 1); s0 += __shfl_xor_sync(~0u, s0, 2);
        s1 += __shfl_xor_sync(~0u, s1, 1); s1 += __shfl_xor_sync(~0u, s1, 2);
        const float i0 = 1.0f / s0, i1 = 1.0f / s1;
        float o[8][4];
        #pragma unroll
        for (int dt = 0; dt < 8; dt++) o[dt][0] = o[dt][1] = o[dt][2] = o[dt][3] = 0.f;
        #pragma unroll
        for (int kt = 0; kt < 13; kt++) {
            uint32_t ap[4];
            ap[0] = h2_u32(__floats2half2_rn(sc[2*kt][0]   * i0, sc[2*kt][1]   * i0));
            ap[1] = h2_u32(__floats2half2_rn(sc[2*kt][2]   * i1, sc[2*kt][3]   * i1));
            ap[2] = h2_u32(__floats2half2_rn(sc[2*kt+1][0] * i0, sc[2*kt+1][1] * i0));
            ap[3] = h2_u32(__floats2half2_rn(sc[2*kt+1][2] * i1, sc[2*kt+1][3] * i1));
            #pragma unroll
            for (int dt = 0; dt < 8; dt++) {
                uint32_t bv[2];
                bv[0] = *(const uint32_t*)&Vt[(dt * 8 + g4) * VST + kt * 16 + l2];
                bv[1] = *(const uint32_t*)&Vt[(dt * 8 + g4) * VST + kt * 16 + l2 + 8];
                mma_f16(o[dt], ap, bv);
            }
        }
        const int r0 = q0 + g4, r1 = q0 + g4 + 8;
        __half* ob = O + h * 64;
        #pragma unroll
        for (int dt = 0; dt < 8; dt++) {
            const int c = dt * 8 + l2;
            if (r0 < N)
                *(__half2*)&ob[((size_t)b * N + r0) * EMB + c] = __floats2half2_rn(o[dt][0], o[dt][1]);
            if (r1 < N)
                *(__half2*)&ob[((size_t)b * N + r1) * EMB + c] = __floats2half2_rn(o[dt][2], o[dt][3]);
        }
    }
}

// ---------------- small / elementwise kernels -------------------------------
__global__ void im2col_k(const float* __restrict__ x, __half* __restrict__ col, long total)
{
    long i = (long)blockIdx.x * blockDim.x + threadIdx.x;
    if (i >= total) return;
    int k = (int)(i % EMB);
    long m = i / EMB;
    int b = (int)(m / NPATCH), p = (int)(m % NPATCH);
    int c = k >> 8, r = k & 255, ii = r >> 4, jj = r & 15;
    int py = p / 14, px = p % 14;
    col[i] = __float2half_rn(x[(((size_t)b * 3 + c) * 224 + py * 16 + ii) * 224 + px * 16 + jj]);
}

__global__ void lat1_k(const float* __restrict__ pe, const float* __restrict__ w1,
                       const float* __restrict__ b1, const float* __restrict__ budget,
                       float* __restrict__ out)
{
    int b = blockIdx.x;
    int idx = (int)rintf(budget[b] * (float)(PE_NN - 1));
    const float* row = pe + (size_t)idx * PE_DD;
    for (int e = threadIdx.x; e < EMB; e += 256) {
        float s = b1[e];
        for (int k = 0; k < PE_DD; k++) s += row[k] * w1[(size_t)k * EMB + e];
        out[(size_t)b * EMB + e] = gelu_f(s);
    }
}

__global__ void assemble_k(const float* __restrict__ lat, const float* __restrict__ cls,
                           const float* __restrict__ pat, const float* __restrict__ pos,
                           float* __restrict__ tok, long total)
{
    long i = (long)blockIdx.x * blockDim.x + threadIdx.x;
    if (i >= total) return;
    int e = (int)(i % EMB);
    long bn = i / EMB;
    int n = (int)(bn % NTOK), b = (int)(bn / NTOK);
    float v;
    if (n == 0)      v = lat[(size_t)b * EMB + e];
    else if (n == 1) v = cls[e];
    else             v = pat[((size_t)b * NPATCH + (n - 2)) * EMB + e];
    tok[i] = v + pos[(size_t)n * EMB + e];
}

__global__ void sched_k(const float* __restrict__ tok, const float* __restrict__ sw,
                        const float* __restrict__ sb, const float* __restrict__ budget,
                        int* __restrict__ active)
{
    int b = blockIdx.x, lane = threadIdx.x;
    __shared__ float lg[NADAPT];
    if (lane < NADAPT) {
        const float* x = tok + (size_t)b * NTOK * EMB;
        float s = sb[lane];
        for (int k = 0; k < EMB; k++) s += x[k] * sw[(size_t)k * NADAPT + lane];
        lg[lane] = s;
    }
    __syncwarp();
    if (lane < NADAPT) {
        int kk = (int)ceilf(budget[b] * (float)NADAPT);
        if (kk < 1) kk = 1;
        int rank = 0;
        for (int j = 0; j < NADAPT; j++)
            if (lg[j] > lg[lane] || (lg[j] == lg[lane] && j < lane)) rank++;
        active[b * NADAPT + lane] = (rank < kk) ? 1 : 0;
    }
}

__global__ void extract_k(const float* __restrict__ tok, float* __restrict__ t, long total)
{
    long i = (long)blockIdx.x * blockDim.x + threadIdx.x;
    if (i >= total) return;
    int e = (int)(i % EMB);
    long bn = i / EMB;
    int n = (int)(bn % NT2), b = (int)(bn / NT2);
    t[i] = tok[((size_t)b * NTOK + n + 1) * EMB + e];
}

__global__ void merge_k(const float* __restrict__ t2, float* __restrict__ t,
                        const int* __restrict__ active, int layer, long total)
{
    long i = (long)blockIdx.x * blockDim.x + threadIdx.x;
    if (i >= total) return;
    int b = (int)(i / ((long)NT2 * EMB));
    if (active[b * NADAPT + layer]) t[i] = t2[i];
}

__global__ void head_k(const __half* __restrict__ cls, const float* __restrict__ w,
                       const float* __restrict__ bias, float* __restrict__ out)
{
    int b = blockIdx.x, c = threadIdx.x;
    if (c >= NCLS) return;
    const __half* x = cls + (size_t)b * EMB;
    float s = bias[c];
    for (int k = 0; k < EMB; k++) s += __half2float(x[k]) * w[(size_t)k * NCLS + c];
    out[(size_t)b * NCLS + c] = s;
}

// ---------------- host orchestration ----------------------------------------
static inline void launch_gemm(int act, bool res, bool outh,
                               const __half* A, const __half* Bt, const float* bias,
                               const float* r, float* Cf, __half* Ch, int M, int N, int K,
                               const int* gate, int gstride, int rps)
{
    dim3 g(N / 128, (M + 127) / 128), blk(256);
    if (outh) {
        if (act == 1)      hgemm_k<1, false, true><<<g, blk>>>(A, Bt, bias, r, Cf, Ch, M, N, K, gate, gstride, rps);
        else               hgemm_k<0, false, true><<<g, blk>>>(A, Bt, bias, r, Cf, Ch, M, N, K, gate, gstride, rps);
    } else {
        if (res)           hgemm_k<0, true,  false><<<g, blk>>>(A, Bt, bias, r, Cf, Ch, M, N, K, gate, gstride, rps);
        else               hgemm_k<0, false, false><<<g, blk>>>(A, Bt, bias, r, Cf, Ch, M, N, K, gate, gstride, rps);
    }
}

struct Ptrs {
    float *tok, *t, *t2, *pat, *lat1, *lat3;
    __half *xn, *qkv, *att, *mlp, *col, *lat2, *cls;
    __half *wqkv, *wproj, *wfc1, *wfc2, *wlat2, *wpat;
    int   *actv;
};

// Xin: residual input (read). Xout: output buffer (written by proj and fc2).
static void run_block(const Ptrs& P, float* Xin, float* Xout, int N, int l,
                      const float* ln1g, const float* ln1b, const float* qkvb,
                      const float* projb, const float* ln2g, const float* ln2b,
                      const float* fc1b, const float* fc2b,
                      const int* gate, int gstride)
{
    const int M = BATCH * N;
    ln_k<<<M, 256>>>(Xin, EMB, ln1g + (size_t)l * EMB, ln1b + (size_t)l * EMB,
                     P.xn, EMB, gate, gstride, N);
    launch_gemm(0, false, true, P.xn, P.wqkv + (size_t)l * EMB * 3 * EMB,
                qkvb + (size_t)l * 3 * EMB, nullptr, nullptr, P.qkv, M, 3 * EMB, EMB,
                gate, gstride, N);
    attn_k<<<BATCH * HEADS, 128, ATTN_SMEM_BYTES>>>(P.qkv, P.att, N, gate, gstride);
    launch_gemm(0, true, false, P.att, P.wproj + (size_t)l * EMB * EMB,
                projb + (size_t)l * EMB, Xin, Xout, nullptr, M, EMB, EMB,
                gate, gstride, N);
    ln_k<<<M, 256>>>(Xout, EMB, ln2g + (size_t)l * EMB, ln2b + (size_t)l * EMB,
                     P.xn, EMB, gate, gstride, N);
    launch_gemm(1, false, true, P.xn, P.wfc1 + (size_t)l * EMB * MLPD,
                fc1b + (size_t)l * MLPD, nullptr, nullptr, P.mlp, M, MLPD, EMB,
                gate, gstride, N);
    launch_gemm(0, true, false, P.mlp, P.wfc2 + (size_t)l * MLPD * EMB,
                fc2b + (size_t)l * EMB, Xout, Xout, nullptr, M, EMB, MLPD,
                gate, gstride, N);
}

extern "C" void kernel_launch(void* const* d_in, const int* in_sizes, int n_in,
                              void* d_out, int out_size)
{
    const float* x        = (const float*)d_in[0];
    const float* budget   = (const float*)d_in[1];
    const float* pe_table = (const float*)d_in[2];
    const float* lat_w1   = (const float*)d_in[3];
    const float* lat_b1   = (const float*)d_in[4];
    const float* lat_ln_g = (const float*)d_in[5];
    const float* lat_ln_b = (const float*)d_in[6];
    const float* lat_w2   = (const float*)d_in[7];
    const float* lat_b2   = (const float*)d_in[8];
    const float* patch_w  = (const float*)d_in[9];
    const float* patch_b  = (const float*)d_in[10];
    const float* cls_tok  = (const float*)d_in[11];
    const float* pos_emb  = (const float*)d_in[12];
    const float* sched_w  = (const float*)d_in[13];
    const float* sched_b  = (const float*)d_in[14];
    const float* ln1_g    = (const float*)d_in[15];
    const float* ln1_b    = (const float*)d_in[16];
    const float* qkv_w    = (const float*)d_in[17];
    const float* qkv_b    = (const float*)d_in[18];
    const float* proj_w   = (const float*)d_in[19];
    const float* proj_b   = (const float*)d_in[20];
    const float* ln2_g    = (const float*)d_in[21];
    const float* ln2_b    = (const float*)d_in[22];
    const float* fc1_w    = (const float*)d_in[23];
    const float* fc1_b    = (const float*)d_in[24];
    const float* fc2_w    = (const float*)d_in[25];
    const float* fc2_b    = (const float*)d_in[26];
    const float* norm_g   = (const float*)d_in[27];
    const float* norm_b   = (const float*)d_in[28];
    const float* head_w   = (const float*)d_in[29];
    const float* head_b   = (const float*)d_in[30];
    float* out = (float*)d_out;

    Ptrs P;
    cudaGetSymbolAddress((void**)&P.tok,  g_tok);
    cudaGetSymbolAddress((void**)&P.xn,   g_xn);
    cudaGetSymbolAddress((void**)&P.qkv,  g_qkv);
    cudaGetSymbolAddress((void**)&P.att,  g_attb);
    cudaGetSymbolAddress((void**)&P.mlp,  g_mlpb);
    cudaGetSymbolAddress((void**)&P.t,    g_t);
    cudaGetSymbolAddress((void**)&P.t2,   g_t2);
    cudaGetSymbolAddress((void**)&P.col,  g_col);
    cudaGetSymbolAddress((void**)&P.pat,  g_pat);
    cudaGetSymbolAddress((void**)&P.lat1, g_lat1);
    cudaGetSymbolAddress((void**)&P.lat2, g_lat2);
    cudaGetSymbolAddress((void**)&P.lat3, g_lat3);
    cudaGetSymbolAddress((void**)&P.cls,  g_cls);
    cudaGetSymbolAddress((void**)&P.actv, g_actv);
    cudaGetSymbolAddress((void**)&P.wqkv, g_wqkv);
    cudaGetSymbolAddress((void**)&P.wproj,g_wproj);
    cudaGetSymbolAddress((void**)&P.wfc1, g_wfc1);
    cudaGetSymbolAddress((void**)&P.wfc2, g_wfc2);
    cudaGetSymbolAddress((void**)&P.wlat2,g_wlat2);
    cudaGetSymbolAddress((void**)&P.wpat, g_wpat);

    cudaFuncSetAttribute(attn_k, cudaFuncAttributeMaxDynamicSharedMemorySize, ATTN_SMEM_BYTES);

    // --- weight transposes+convert ([K,N] fp32 -> [N,K] half) ---
    {
        dim3 b32(32, 8);
        transpose_k<<<dim3(3*EMB/32, EMB/32, NLAYERS), b32>>>(qkv_w,  P.wqkv,  EMB, 3*EMB);
        transpose_k<<<dim3(EMB/32,   EMB/32, NLAYERS), b32>>>(proj_w, P.wproj, EMB, EMB);
        transpose_k<<<dim3(MLPD/32,  EMB/32, NLAYERS), b32>>>(fc1_w,  P.wfc1,  EMB, MLPD);
        transpose_k<<<dim3(EMB/32,  MLPD/32, NLAYERS), b32>>>(fc2_w,  P.wfc2,  MLPD, EMB);
        transpose_k<<<dim3(EMB/32,   EMB/32, 1),       b32>>>(lat_w2, P.wlat2, EMB, EMB);
        long pw = (long)EMB * EMB;
        cvt_k<<<(unsigned)((pw + 255) / 256), 256>>>(patch_w, P.wpat, pw);
    }

    // --- latent token ---
    lat1_k<<<BATCH, 256>>>(pe_table, lat_w1, lat_b1, budget, P.lat1);
    ln_k<<<BATCH, 256>>>(P.lat1, EMB, lat_ln_g, lat_ln_b, P.lat2, EMB, nullptr, 0, 1);
    launch_gemm(0, false, false, P.lat2, P.wlat2, lat_b2, nullptr, P.lat3, nullptr,
                BATCH, EMB, EMB, nullptr, 0, 1);

    // --- patch embedding ---
    {
        long tot = (long)BATCH * NPATCH * EMB;
        im2col_k<<<(unsigned)((tot + 255) / 256), 256>>>(x, P.col, tot);
        launch_gemm(0, false, false, P.col, P.wpat, patch_b, nullptr, P.pat, nullptr,
                    BATCH * NPATCH, EMB, EMB, nullptr, 0, 1);
        long ta = (long)BATCH * NTOK * EMB;
        assemble_k<<<(unsigned)((ta + 255) / 256), 256>>>(P.lat3, cls_tok, P.pat,
                                                          pos_emb, P.tok, ta);
    }

    // --- 6 fixed blocks on 198 tokens (in-place on tok) ---
    for (int l = 0; l < NFIX; l++)
        run_block(P, P.tok, P.tok, NTOK, l, ln1_g, ln1_b, qkv_b, proj_b,
                  ln2_g, ln2_b, fc1_b, fc2_b, nullptr, 0);

    // --- scheduler gating ---
    sched_k<<<BATCH, 32>>>(P.tok, sched_w, sched_b, budget, P.actv);

    // --- adaptive blocks on 197 tokens: t (residual in) -> t2 -> merge ---
    const long tlen = (long)BATCH * NT2 * EMB;
    extract_k<<<(unsigned)((tlen + 255) / 256), 256>>>(P.tok, P.t, tlen);
    for (int i = 0; i < NADAPT; i++) {
        const int* gate = P.actv + i;    // gate[s * NADAPT] = active[s][i]
        run_block(P, P.t, P.t2, NT2, NFIX + i, ln1_g, ln1_b, qkv_b, proj_b,
                  ln2_g, ln2_b, fc1_b, fc2_b, gate, NADAPT);
        merge_k<<<(unsigned)((tlen + 255) / 256), 256>>>(P.t2, P.t, P.actv, i, tlen);
    }

    // --- final LN (only row 0 per sample needed for output) + head ---
    ln_k<<<BATCH, 256>>>(P.t, (long)NT2 * EMB, norm_g, norm_b, P.cls, EMB, nullptr, 0, 1);
    head_k<<<BATCH, 128>>>(P.cls, head_w, head_b, out);
}

// round 9
// speedup vs baseline: 5.9294x; 1.0459x over previous
#include <cuda_runtime.h>
#include <cuda_fp16.h>
#include <math.h>
#include <stdint.h>

#define BATCH 32
#define EMB   768
#define HEADS 12
#define HD    64
#define NLAYERS 12
#define NFIX  6
#define NADAPT 6
#define MLPD  3072
#define NCLS  100
#define NTOK  198
#define NT2   197
#define PE_NN 100
#define PE_DD 256
#define NPATCH 196

// ---------------- scratch (device globals; no allocation allowed) ------------
__device__ float g_tok [BATCH*NTOK*EMB];
__device__ __align__(16) __half g_xn  [BATCH*NTOK*EMB];
__device__ __align__(16) __half g_qkv [BATCH*NTOK*3*EMB];
__device__ __align__(16) __half g_attb[BATCH*NTOK*EMB];
__device__ __align__(16) __half g_mlpb[BATCH*NTOK*MLPD];
__device__ float g_t   [BATCH*NT2*EMB];
__device__ float g_t2  [BATCH*NT2*EMB];
__device__ __align__(16) __half g_col [BATCH*NPATCH*EMB];
__device__ float g_pat [BATCH*NPATCH*EMB];
__device__ float g_lat1[BATCH*EMB];
__device__ __align__(16) __half g_lat2[BATCH*EMB];
__device__ float g_lat3[BATCH*EMB];
__device__ __align__(16) __half g_cls [BATCH*EMB];
__device__ int   g_actv[BATCH*NADAPT];
__device__ __align__(16) __half g_wqkv [NLAYERS*3*EMB*EMB];
__device__ __align__(16) __half g_wproj[NLAYERS*EMB*EMB];
__device__ __align__(16) __half g_wfc1 [NLAYERS*MLPD*EMB];
__device__ __align__(16) __half g_wfc2 [NLAYERS*EMB*MLPD];
__device__ __align__(16) __half g_wlat2[EMB*EMB];
__device__ __align__(16) __half g_wpat [EMB*EMB];

__device__ __forceinline__ float gelu_f(float v) {
    return 0.5f * v * (1.0f + erff(v * 0.70710678118654752440f));
}
__device__ __forceinline__ uint32_t smem_u32(const void* p) {
    uint32_t a;
    asm("{ .reg .u64 t; cvta.to.shared.u64 t, %1; cvt.u32.u64 %0, t; }" : "=r"(a) : "l"(p));
    return a;
}
__device__ __forceinline__ uint32_t h2_u32(__half2 h) {
    uint32_t u;
    *(__half2*)&u = h;
    return u;
}
__device__ __forceinline__ void cp16(uint32_t dst, const void* src, bool pred) {
    int sz = pred ? 16 : 0;
    asm volatile("cp.async.cg.shared.global [%0], [%1], 16, %2;"
                 :: "r"(dst), "l"(src), "r"(sz) : "memory");
}
__device__ __forceinline__ void mma_f16(float c[4], const uint32_t a[4], const uint32_t b[2]) {
    asm volatile(
        "mma.sync.aligned.m16n8k16.row.col.f32.f16.f16.f32 "
        "{%0,%1,%2,%3}, {%4,%5,%6,%7}, {%8,%9}, {%0,%1,%2,%3};\n"
        : "+f"(c[0]), "+f"(c[1]), "+f"(c[2]), "+f"(c[3])
        : "r"(a[0]), "r"(a[1]), "r"(a[2]), "r"(a[3]), "r"(b[0]), "r"(b[1]));
}

// ---------------- fp16 tensor-core GEMM: C = A[M,K] @ Bt[N,K]^T -------------
// gate: per-sample active flags (stride gstride), rps rows/sample.
// gate_rows: if nonzero, the epilogue also skips WRITING rows of inactive
// samples (used by fc2 writing the merged buffer directly).
#define HSTRIDE 40
template<int ACT, bool RES, bool OUTH>
__global__ void __launch_bounds__(256) hgemm_k(
    const __half* __restrict__ A, const __half* __restrict__ Bt,
    const float* __restrict__ bias, const float* __restrict__ res,
    float* __restrict__ Cf, __half* __restrict__ Ch, int M, int N, int K,
    const int* __restrict__ gate, int gstride, int rps, int gate_rows)
{
    const int brow = blockIdx.y * 128;
    if (gate) {
        const int s0 = brow / rps;
        const int s1 = min(brow + 127, M - 1) / rps;
        bool any = false;
        for (int s = s0; s <= s1; s++) any |= (gate[s * gstride] != 0);
        if (!any) return;
    }

    __shared__ __align__(16) __half sA[2][128 * HSTRIDE];
    __shared__ __align__(16) __half sB[2][128 * HSTRIDE];

    const int tid  = threadIdx.x;
    const int warp = tid >> 5, lane = tid & 31;
    const int bcol = blockIdx.x * 128;
    const int warpM = (warp >> 2) * 64;
    const int warpN = (warp & 3) * 32;
    const int g4 = lane >> 2, l2 = (lane & 3) * 2;

    const uint32_t sa0 = smem_u32(&sA[0][0]), sa1 = smem_u32(&sA[1][0]);
    const uint32_t sb0 = smem_u32(&sB[0][0]), sb1 = smem_u32(&sB[1][0]);

    float acc[4][4][4];
    #pragma unroll
    for (int i = 0; i < 4; i++)
        #pragma unroll
        for (int j = 0; j < 4; j++)
            #pragma unroll
            for (int r = 0; r < 4; r++) acc[i][j][r] = 0.0f;

    const int nch = K >> 5;
    const int r0 = tid >> 2, r1 = (tid + 256) >> 2;
    const int cb0 = (tid & 3), cb1 = ((tid + 256) & 3);

    auto LOAD = [&](int chunk, int st) {
        const int k0 = chunk << 5;
        const uint32_t da = st ? sa1 : sa0;
        const uint32_t db = st ? sb1 : sb0;
        cp16(da + r0 * (HSTRIDE * 2) + cb0 * 16,
             A + (size_t)(brow + r0) * K + k0 + cb0 * 8, (brow + r0) < M);
        cp16(da + r1 * (HSTRIDE * 2) + cb1 * 16,
             A + (size_t)(brow + r1) * K + k0 + cb1 * 8, (brow + r1) < M);
        cp16(db + r0 * (HSTRIDE * 2) + cb0 * 16,
             Bt + (size_t)(bcol + r0) * K + k0 + cb0 * 8, true);
        cp16(db + r1 * (HSTRIDE * 2) + cb1 * 16,
             Bt + (size_t)(bcol + r1) * K + k0 + cb1 * 8, true);
        asm volatile("cp.async.commit_group;" ::: "memory");
    };

    LOAD(0, 0);

    for (int c = 0; c < nch; c++) {
        const int st = c & 1;
        if (c + 1 < nch) {
            LOAD(c + 1, st ^ 1);
            asm volatile("cp.async.wait_group 1;" ::: "memory");
        } else {
            asm volatile("cp.async.wait_group 0;" ::: "memory");
        }
        __syncthreads();

        const __half* As = sA[st];
        const __half* Bs = sB[st];
        #pragma unroll
        for (int ks = 0; ks < 2; ks++) {
            const int kk = ks * 16 + l2;
            uint32_t af[4][4], bf[4][2];
            #pragma unroll
            for (int tm = 0; tm < 4; tm++) {
                const int m = warpM + tm * 16 + g4;
                af[tm][0] = *(const uint32_t*)&As[m * HSTRIDE + kk];
                af[tm][1] = *(const uint32_t*)&As[(m + 8) * HSTRIDE + kk];
                af[tm][2] = *(const uint32_t*)&As[m * HSTRIDE + kk + 8];
                af[tm][3] = *(const uint32_t*)&As[(m + 8) * HSTRIDE + kk + 8];
            }
            #pragma unroll
            for (int tn = 0; tn < 4; tn++) {
                const int n = warpN + tn * 8 + g4;
                bf[tn][0] = *(const uint32_t*)&Bs[n * HSTRIDE + kk];
                bf[tn][1] = *(const uint32_t*)&Bs[n * HSTRIDE + kk + 8];
            }
            #pragma unroll
            for (int tm = 0; tm < 4; tm++)
                #pragma unroll
                for (int tn = 0; tn < 4; tn++)
                    mma_f16(acc[tm][tn], af[tm], bf[tn]);
        }
        __syncthreads();
    }

    #pragma unroll
    for (int tm = 0; tm < 4; tm++) {
        const int rr = brow + warpM + tm * 16 + g4;
        #pragma unroll
        for (int half = 0; half < 2; half++) {
            const int gr = rr + half * 8;
            if (gr >= M) continue;
            if (gate_rows && gate && !gate[(gr / rps) * gstride]) continue;
            #pragma unroll
            for (int tn = 0; tn < 4; tn++) {
                const int gc = bcol + warpN + tn * 8 + l2;
                float o0 = acc[tm][tn][half * 2 + 0] + bias[gc];
                float o1 = acc[tm][tn][half * 2 + 1] + bias[gc + 1];
                if (ACT == 1) { o0 = gelu_f(o0); o1 = gelu_f(o1); }
                if (RES) {
                    o0 += res[(size_t)gr * N + gc];
                    o1 += res[(size_t)gr * N + gc + 1];
                }
                if (OUTH) {
                    *(__half2*)&Ch[(size_t)gr * N + gc] = __floats2half2_rn(o0, o1);
                } else {
                    Cf[(size_t)gr * N + gc]     = o0;
                    Cf[(size_t)gr * N + gc + 1] = o1;
                }
            }
        }
    }
}

// ---------------- weight transpose+convert ----------------------------------
__global__ void transpose_k(const float* __restrict__ in, __half* __restrict__ out,
                            int K, int N)
{
    __shared__ float t[32][33];
    const int l = blockIdx.z;
    const float* ip = in  + (size_t)l * K * N;
    __half*      op = out + (size_t)l * K * N;
    const int k0 = blockIdx.y * 32, n0 = blockIdx.x * 32;
    #pragma unroll
    for (int i = 0; i < 32; i += 8) {
        int k = k0 + threadIdx.y + i, n = n0 + threadIdx.x;
        if (k < K && n < N) t[threadIdx.y + i][threadIdx.x] = ip[(size_t)k * N + n];
    }
    __syncthreads();
    #pragma unroll
    for (int i = 0; i < 32; i += 8) {
        int n = n0 + threadIdx.y + i, k = k0 + threadIdx.x;
        if (n < N && k < K) op[(size_t)n * K + k] = __float2half_rn(t[threadIdx.x][threadIdx.y + i]);
    }
}

__global__ void cvt_k(const float* __restrict__ in, __half* __restrict__ out, long n)
{
    long i = (long)blockIdx.x * blockDim.x + threadIdx.x;
    if (i < n) out[i] = __float2half_rn(in[i]);
}

// ---------------- LayerNorm over 768 (fp32 in, half out), gated -------------
// 192 threads, float4 loads, half2 stores.
__global__ void __launch_bounds__(192) ln_k(
    const float* __restrict__ X, long istride,
    const float* __restrict__ g, const float* __restrict__ b,
    __half* __restrict__ Y, long ostride,
    const int* __restrict__ gate, int gstride, int rps)
{
    const int row = blockIdx.x;
    if (gate && !gate[(row / rps) * gstride]) return;
    const int tid = threadIdx.x;
    const float* x = X + (size_t)row * istride;
    __half* y      = Y + (size_t)row * ostride;
    __shared__ float red[6];
    __shared__ float stat[2];

    const float4 v = *(const float4*)&x[tid * 4];
    float s = v.x + v.y + v.z + v.w;
    #pragma unroll
    for (int o = 16; o; o >>= 1) s += __shfl_xor_sync(~0u, s, o);
    if ((tid & 31) == 0) red[tid >> 5] = s;
    __syncthreads();
    if (tid == 0) {
        float t = 0.f;
        #pragma unroll
        for (int i = 0; i < 6; i++) t += red[i];
        stat[0] = t * (1.0f / 768.0f);
    }
    __syncthreads();
    const float mean = stat[0];
    const float d0 = v.x - mean, d1 = v.y - mean, d2 = v.z - mean, d3 = v.w - mean;
    s = d0 * d0 + d1 * d1 + d2 * d2 + d3 * d3;
    #pragma unroll
    for (int o = 16; o; o >>= 1) s += __shfl_xor_sync(~0u, s, o);
    __syncthreads();
    if ((tid & 31) == 0) red[tid >> 5] = s;
    __syncthreads();
    if (tid == 0) {
        float t = 0.f;
        #pragma unroll
        for (int i = 0; i < 6; i++) t += red[i];
        stat[1] = rsqrtf(t * (1.0f / 768.0f) + 1e-5f);
    }
    __syncthreads();
    const float rstd = stat[1];
    const float4 gv = *(const float4*)&g[tid * 4];
    const float4 bv = *(const float4*)&b[tid * 4];
    __half2 h01 = __floats2half2_rn(d0 * rstd * gv.x + bv.x, d1 * rstd * gv.y + bv.y);
    __half2 h23 = __floats2half2_rn(d2 * rstd * gv.z + bv.z, d3 * rstd * gv.w + bv.w);
    *(__half2*)&y[tid * 4]     = h01;
    *(__half2*)&y[tid * 4 + 2] = h23;
}

// ---------------- tensor-core attention: one CTA (128 thr) per (b,h) --------
#define APAD 208
#define KST  72
#define VST  216
#define ATTN_SMEM_BYTES ((2*APAD*KST + 64*VST) * 2)

__global__ void __launch_bounds__(128) attn_k(const __half* __restrict__ qkv,
                                              __half* __restrict__ O, int N,
                                              const int* __restrict__ gate, int gstride)
{
    const int bh = blockIdx.x;
    const int b  = bh / HEADS, h = bh % HEADS;
    if (gate && !gate[b * gstride]) return;

    extern __shared__ __half smh[];
    __half* Qs = smh;
    __half* Ks = Qs + APAD * KST;
    __half* Vt = Ks + APAD * KST;

    const int tid = threadIdx.x;
    const int w = tid >> 5, lane = tid & 31;
    const int g4 = lane >> 2, l2 = (lane & 3) * 2;
    const __half* base = qkv + (size_t)b * N * (3 * EMB) + h * 64;

    for (int n = tid; n < APAD; n += 128) {
        uint4* qd = (uint4*)&Qs[n * KST];
        uint4* kd = (uint4*)&Ks[n * KST];
        if (n < N) {
            const uint4* qs = (const uint4*)(base + (size_t)n * (3 * EMB));
            const uint4* ks = (const uint4*)(base + (size_t)n * (3 * EMB) + EMB);
            #pragma unroll
            for (int i = 0; i < 8; i++) { qd[i] = qs[i]; kd[i] = ks[i]; }
        } else {
            uint4 z = make_uint4(0, 0, 0, 0);
            #pragma unroll
            for (int i = 0; i < 8; i++) { qd[i] = z; kd[i] = z; }
        }
    }
    for (int idx = tid; idx < APAD * 64; idx += 128) {
        const int n = idx >> 6, d = idx & 63;
        __half v = (n < N) ? base[(size_t)n * (3 * EMB) + 2 * EMB + d] : __ushort_as_half(0);
        Vt[d * VST + n] = v;
    }
    __syncthreads();

    for (int qt = w; qt < 13; qt += 4) {
        const int q0 = qt * 16;
        uint32_t aq[4][4];
        #pragma unroll
        for (int ks = 0; ks < 4; ks++) {
            const int kk = ks * 16 + l2;
            aq[ks][0] = *(const uint32_t*)&Qs[(q0 + g4) * KST + kk];
            aq[ks][1] = *(const uint32_t*)&Qs[(q0 + g4 + 8) * KST + kk];
            aq[ks][2] = *(const uint32_t*)&Qs[(q0 + g4) * KST + kk + 8];
            aq[ks][3] = *(const uint32_t*)&Qs[(q0 + g4 + 8) * KST + kk + 8];
        }
        float sc[26][4];
        #pragma unroll
        for (int nt = 0; nt < 26; nt++) {
            sc[nt][0] = sc[nt][1] = sc[nt][2] = sc[nt][3] = 0.f;
            #pragma unroll
            for (int ks = 0; ks < 4; ks++) {
                const int kk = ks * 16 + l2;
                uint32_t bf[2];
                bf[0] = *(const uint32_t*)&Ks[(nt * 8 + g4) * KST + kk];
                bf[1] = *(const uint32_t*)&Ks[(nt * 8 + g4) * KST + kk + 8];
                mma_f16(sc[nt], aq[ks], bf);
            }
        }
        float m0 = -1e30f, m1 = -1e30f;
        #pragma unroll
        for (int nt = 0; nt < 26; nt++) {
            #pragma unroll
            for (int e = 0; e < 2; e++) {
                const int col = nt * 8 + l2 + e;
                const bool ok = col < N;
                float v0 = ok ? sc[nt][e]     * 0.125f : -1e30f;
                float v1 = ok ? sc[nt][2 + e] * 0.125f : -1e30f;
                sc[nt][e] = v0; sc[nt][2 + e] = v1;
                m0 = fmaxf(m0, v0); m1 = fmaxf(m1, v1);
            }
        }
        m0 = fmaxf(m0, __shfl_xor_sync(~0u, m0, 1));
        m0 = fmaxf(m0, __shfl_xor_sync(~0u, m0, 2));
        m1 = fmaxf(m1, __shfl_xor_sync(~0u, m1, 1));
        m1 = fmaxf(m1, __shfl_xor_sync(~0u, m1, 2));
        float s0 = 0.f, s1 = 0.f;
        #pragma unroll
        for (int nt = 0; nt < 26; nt++) {
            #pragma unroll
            for (int e = 0; e < 2; e++) {
                float e0 = __expf(sc[nt][e]     - m0);
                float e1 = __expf(sc[nt][2 + e] - m1);
                sc[nt][e] = e0; sc[nt][2 + e] = e1;
                s0 += e0; s1 += e1;
            }
        }
        s0 += __shfl_xor_sync(~0u, s0, 1); s0 += __shfl_xor_sync(~0u, s0, 2);
        s1 += __shfl_xor_sync(~0u, s1, 1); s1 += __shfl_xor_sync(~0u, s1, 2);
        const float i0 = 1.0f / s0, i1 = 1.0f / s1;
        float o[8][4];
        #pragma unroll
        for (int dt = 0; dt < 8; dt++) o[dt][0] = o[dt][1] = o[dt][2] = o[dt][3] = 0.f;
        #pragma unroll
        for (int kt = 0; kt < 13; kt++) {
            uint32_t ap[4];
            ap[0] = h2_u32(__floats2half2_rn(sc[2*kt][0]   * i0, sc[2*kt][1]   * i0));
            ap[1] = h2_u32(__floats2half2_rn(sc[2*kt][2]   * i1, sc[2*kt][3]   * i1));
            ap[2] = h2_u32(__floats2half2_rn(sc[2*kt+1][0] * i0, sc[2*kt+1][1] * i0));
            ap[3] = h2_u32(__floats2half2_rn(sc[2*kt+1][2] * i1, sc[2*kt+1][3] * i1));
            #pragma unroll
            for (int dt = 0; dt < 8; dt++) {
                uint32_t bv[2];
                bv[0] = *(const uint32_t*)&Vt[(dt * 8 + g4) * VST + kt * 16 + l2];
                bv[1] = *(const uint32_t*)&Vt[(dt * 8 + g4) * VST + kt * 16 + l2 + 8];
                mma_f16(o[dt], ap, bv);
            }
        }
        const int r0 = q0 + g4, r1 = q0 + g4 + 8;
        __half* ob = O + h * 64;
        #pragma unroll
        for (int dt = 0; dt < 8; dt++) {
            const int c = dt * 8 + l2;
            if (r0 < N)
                *(__half2*)&ob[((size_t)b * N + r0) * EMB + c] = __floats2half2_rn(o[dt][0], o[dt][1]);
            if (r1 < N)
                *(__half2*)&ob[((size_t)b * N + r1) * EMB + c] = __floats2half2_rn(o[dt][2], o[dt][3]);
        }
    }
}

// ---------------- small / elementwise kernels -------------------------------
__global__ void im2col_k(const float* __restrict__ x, __half* __restrict__ col, long total)
{
    long i = (long)blockIdx.x * blockDim.x + threadIdx.x;
    if (i >= total) return;
    int k = (int)(i % EMB);
    long m = i / EMB;
    int b = (int)(m / NPATCH), p = (int)(m % NPATCH);
    int c = k >> 8, r = k & 255, ii = r >> 4, jj = r & 15;
    int py = p / 14, px = p % 14;
    col[i] = __float2half_rn(x[(((size_t)b * 3 + c) * 224 + py * 16 + ii) * 224 + px * 16 + jj]);
}

__global__ void lat1_k(const float* __restrict__ pe, const float* __restrict__ w1,
                       const float* __restrict__ b1, const float* __restrict__ budget,
                       float* __restrict__ out)
{
    int b = blockIdx.x;
    int idx = (int)rintf(budget[b] * (float)(PE_NN - 1));
    const float* row = pe + (size_t)idx * PE_DD;
    for (int e = threadIdx.x; e < EMB; e += 256) {
        float s = b1[e];
        for (int k = 0; k < PE_DD; k++) s += row[k] * w1[(size_t)k * EMB + e];
        out[(size_t)b * EMB + e] = gelu_f(s);
    }
}

__global__ void assemble_k(const float* __restrict__ lat, const float* __restrict__ cls,
                           const float* __restrict__ pat, const float* __restrict__ pos,
                           float* __restrict__ tok, long total)
{
    long i = (long)blockIdx.x * blockDim.x + threadIdx.x;
    if (i >= total) return;
    int e = (int)(i % EMB);
    long bn = i / EMB;
    int n = (int)(bn % NTOK), b = (int)(bn / NTOK);
    float v;
    if (n == 0)      v = lat[(size_t)b * EMB + e];
    else if (n == 1) v = cls[e];
    else             v = pat[((size_t)b * NPATCH + (n - 2)) * EMB + e];
    tok[i] = v + pos[(size_t)n * EMB + e];
}

__global__ void sched_k(const float* __restrict__ tok, const float* __restrict__ sw,
                        const float* __restrict__ sb, const float* __restrict__ budget,
                        int* __restrict__ active)
{
    int b = blockIdx.x, lane = threadIdx.x;
    __shared__ float lg[NADAPT];
    if (lane < NADAPT) {
        const float* x = tok + (size_t)b * NTOK * EMB;
        float s = sb[lane];
        for (int k = 0; k < EMB; k++) s += x[k] * sw[(size_t)k * NADAPT + lane];
        lg[lane] = s;
    }
    __syncwarp();
    if (lane < NADAPT) {
        int kk = (int)ceilf(budget[b] * (float)NADAPT);
        if (kk < 1) kk = 1;
        int rank = 0;
        for (int j = 0; j < NADAPT; j++)
            if (lg[j] > lg[lane] || (lg[j] == lg[lane] && j < lane)) rank++;
        active[b * NADAPT + lane] = (rank < kk) ? 1 : 0;
    }
}

__global__ void extract_k(const float* __restrict__ tok, float* __restrict__ t, long total)
{
    long i = (long)blockIdx.x * blockDim.x + threadIdx.x;
    if (i >= total) return;
    int e = (int)(i % EMB);
    long bn = i / EMB;
    int n = (int)(bn % NT2), b = (int)(bn / NT2);
    t[i] = tok[((size_t)b * NTOK + n + 1) * EMB + e];
}

__global__ void head_k(const __half* __restrict__ cls, const float* __restrict__ w,
                       const float* __restrict__ bias, float* __restrict__ out)
{
    int b = blockIdx.x, c = threadIdx.x;
    if (c >= NCLS) return;
    const __half* x = cls + (size_t)b * EMB;
    float s = bias[c];
    for (int k = 0; k < EMB; k++) s += __half2float(x[k]) * w[(size_t)k * NCLS + c];
    out[(size_t)b * NCLS + c] = s;
}

// ---------------- host orchestration ----------------------------------------
static inline void launch_gemm(int act, bool res, bool outh,
                               const __half* A, const __half* Bt, const float* bias,
                               const float* r, float* Cf, __half* Ch, int M, int N, int K,
                               const int* gate, int gstride, int rps, int gate_rows)
{
    dim3 g(N / 128, (M + 127) / 128), blk(256);
    if (outh) {
        if (act == 1)      hgemm_k<1, false, true><<<g, blk>>>(A, Bt, bias, r, Cf, Ch, M, N, K, gate, gstride, rps, gate_rows);
        else               hgemm_k<0, false, true><<<g, blk>>>(A, Bt, bias, r, Cf, Ch, M, N, K, gate, gstride, rps, gate_rows);
    } else {
        if (res)           hgemm_k<0, true,  false><<<g, blk>>>(A, Bt, bias, r, Cf, Ch, M, N, K, gate, gstride, rps, gate_rows);
        else               hgemm_k<0, false, false><<<g, blk>>>(A, Bt, bias, r, Cf, Ch, M, N, K, gate, gstride, rps, gate_rows);
    }
}

struct Ptrs {
    float *tok, *t, *t2, *pat, *lat1, *lat3;
    __half *xn, *qkv, *att, *mlp, *col, *lat2, *cls;
    __half *wqkv, *wproj, *wfc1, *wfc2, *wlat2, *wpat;
    int   *actv;
};

// Xin: residual input (read). Xmid: post-attention buffer. Xout: final target
// written by fc2 (row-gated when gate_rows=1, emulating the where-merge).
static void run_block(const Ptrs& P, float* Xin, float* Xmid, float* Xout, int N, int l,
                      const float* ln1g, const float* ln1b, const float* qkvb,
                      const float* projb, const float* ln2g, const float* ln2b,
                      const float* fc1b, const float* fc2b,
                      const int* gate, int gstride, int gate_rows)
{
    const int M = BATCH * N;
    ln_k<<<M, 192>>>(Xin, EMB, ln1g + (size_t)l * EMB, ln1b + (size_t)l * EMB,
                     P.xn, EMB, gate, gstride, N);
    launch_gemm(0, false, true, P.xn, P.wqkv + (size_t)l * EMB * 3 * EMB,
                qkvb + (size_t)l * 3 * EMB, nullptr, nullptr, P.qkv, M, 3 * EMB, EMB,
                gate, gstride, N, 0);
    attn_k<<<BATCH * HEADS, 128, ATTN_SMEM_BYTES>>>(P.qkv, P.att, N, gate, gstride);
    launch_gemm(0, true, false, P.att, P.wproj + (size_t)l * EMB * EMB,
                projb + (size_t)l * EMB, Xin, Xmid, nullptr, M, EMB, EMB,
                gate, gstride, N, 0);
    ln_k<<<M, 192>>>(Xmid, EMB, ln2g + (size_t)l * EMB, ln2b + (size_t)l * EMB,
                     P.xn, EMB, gate, gstride, N);
    launch_gemm(1, false, true, P.xn, P.wfc1 + (size_t)l * EMB * MLPD,
                fc1b + (size_t)l * MLPD, nullptr, nullptr, P.mlp, M, MLPD, EMB,
                gate, gstride, N, 0);
    launch_gemm(0, true, false, P.mlp, P.wfc2 + (size_t)l * MLPD * EMB,
                fc2b + (size_t)l * EMB, Xmid, Xout, nullptr, M, EMB, MLPD,
                gate, gstride, N, gate_rows);
}

extern "C" void kernel_launch(void* const* d_in, const int* in_sizes, int n_in,
                              void* d_out, int out_size)
{
    const float* x        = (const float*)d_in[0];
    const float* budget   = (const float*)d_in[1];
    const float* pe_table = (const float*)d_in[2];
    const float* lat_w1   = (const float*)d_in[3];
    const float* lat_b1   = (const float*)d_in[4];
    const float* lat_ln_g = (const float*)d_in[5];
    const float* lat_ln_b = (const float*)d_in[6];
    const float* lat_w2   = (const float*)d_in[7];
    const float* lat_b2   = (const float*)d_in[8];
    const float* patch_w  = (const float*)d_in[9];
    const float* patch_b  = (const float*)d_in[10];
    const float* cls_tok  = (const float*)d_in[11];
    const float* pos_emb  = (const float*)d_in[12];
    const float* sched_w  = (const float*)d_in[13];
    const float* sched_b  = (const float*)d_in[14];
    const float* ln1_g    = (const float*)d_in[15];
    const float* ln1_b    = (const float*)d_in[16];
    const float* qkv_w    = (const float*)d_in[17];
    const float* qkv_b    = (const float*)d_in[18];
    const float* proj_w   = (const float*)d_in[19];
    const float* proj_b   = (const float*)d_in[20];
    const float* ln2_g    = (const float*)d_in[21];
    const float* ln2_b    = (const float*)d_in[22];
    const float* fc1_w    = (const float*)d_in[23];
    const float* fc1_b    = (const float*)d_in[24];
    const float* fc2_w    = (const float*)d_in[25];
    const float* fc2_b    = (const float*)d_in[26];
    const float* norm_g   = (const float*)d_in[27];
    const float* norm_b   = (const float*)d_in[28];
    const float* head_w   = (const float*)d_in[29];
    const float* head_b   = (const float*)d_in[30];
    float* out = (float*)d_out;

    Ptrs P;
    cudaGetSymbolAddress((void**)&P.tok,  g_tok);
    cudaGetSymbolAddress((void**)&P.xn,   g_xn);
    cudaGetSymbolAddress((void**)&P.qkv,  g_qkv);
    cudaGetSymbolAddress((void**)&P.att,  g_attb);
    cudaGetSymbolAddress((void**)&P.mlp,  g_mlpb);
    cudaGetSymbolAddress((void**)&P.t,    g_t);
    cudaGetSymbolAddress((void**)&P.t2,   g_t2);
    cudaGetSymbolAddress((void**)&P.col,  g_col);
    cudaGetSymbolAddress((void**)&P.pat,  g_pat);
    cudaGetSymbolAddress((void**)&P.lat1, g_lat1);
    cudaGetSymbolAddress((void**)&P.lat2, g_lat2);
    cudaGetSymbolAddress((void**)&P.lat3, g_lat3);
    cudaGetSymbolAddress((void**)&P.cls,  g_cls);
    cudaGetSymbolAddress((void**)&P.actv, g_actv);
    cudaGetSymbolAddress((void**)&P.wqkv, g_wqkv);
    cudaGetSymbolAddress((void**)&P.wproj,g_wproj);
    cudaGetSymbolAddress((void**)&P.wfc1, g_wfc1);
    cudaGetSymbolAddress((void**)&P.wfc2, g_wfc2);
    cudaGetSymbolAddress((void**)&P.wlat2,g_wlat2);
    cudaGetSymbolAddress((void**)&P.wpat, g_wpat);

    cudaFuncSetAttribute(attn_k, cudaFuncAttributeMaxDynamicSharedMemorySize, ATTN_SMEM_BYTES);

    // --- weight transposes+convert ([K,N] fp32 -> [N,K] half) ---
    {
        dim3 b32(32, 8);
        transpose_k<<<dim3(3*EMB/32, EMB/32, NLAYERS), b32>>>(qkv_w,  P.wqkv,  EMB, 3*EMB);
        transpose_k<<<dim3(EMB/32,   EMB/32, NLAYERS), b32>>>(proj_w, P.wproj, EMB, EMB);
        transpose_k<<<dim3(MLPD/32,  EMB/32, NLAYERS), b32>>>(fc1_w,  P.wfc1,  EMB, MLPD);
        transpose_k<<<dim3(EMB/32,  MLPD/32, NLAYERS), b32>>>(fc2_w,  P.wfc2,  MLPD, EMB);
        transpose_k<<<dim3(EMB/32,   EMB/32, 1),       b32>>>(lat_w2, P.wlat2, EMB, EMB);
        long pw = (long)EMB * EMB;
        cvt_k<<<(unsigned)((pw + 255) / 256), 256>>>(patch_w, P.wpat, pw);
    }

    // --- latent token ---
    lat1_k<<<BATCH, 256>>>(pe_table, lat_w1, lat_b1, budget, P.lat1);
    ln_k<<<BATCH, 192>>>(P.lat1, EMB, lat_ln_g, lat_ln_b, P.lat2, EMB, nullptr, 0, 1);
    launch_gemm(0, false, false, P.lat2, P.wlat2, lat_b2, nullptr, P.lat3, nullptr,
                BATCH, EMB, EMB, nullptr, 0, 1, 0);

    // --- patch embedding ---
    {
        long tot = (long)BATCH * NPATCH * EMB;
        im2col_k<<<(unsigned)((tot + 255) / 256), 256>>>(x, P.col, tot);
        launch_gemm(0, false, false, P.col, P.wpat, patch_b, nullptr, P.pat, nullptr,
                    BATCH * NPATCH, EMB, EMB, nullptr, 0, 1, 0);
        long ta = (long)BATCH * NTOK * EMB;
        assemble_k<<<(unsigned)((ta + 255) / 256), 256>>>(P.lat3, cls_tok, P.pat,
                                                          pos_emb, P.tok, ta);
    }

    // --- 6 fixed blocks on 198 tokens (in-place on tok) ---
    for (int l = 0; l < NFIX; l++)
        run_block(P, P.tok, P.tok, P.tok, NTOK, l, ln1_g, ln1_b, qkv_b, proj_b,
                  ln2_g, ln2_b, fc1_b, fc2_b, nullptr, 0, 0);

    // --- scheduler gating ---
    sched_k<<<BATCH, 32>>>(P.tok, sched_w, sched_b, budget, P.actv);

    // --- adaptive blocks on 197 tokens: t -> t2 (mid) -> t (gated write) ---
    const long tlen = (long)BATCH * NT2 * EMB;
    extract_k<<<(unsigned)((tlen + 255) / 256), 256>>>(P.tok, P.t, tlen);
    for (int i = 0; i < NADAPT; i++) {
        const int* gate = P.actv + i;    // gate[s * NADAPT] = active[s][i]
        run_block(P, P.t, P.t2, P.t, NT2, NFIX + i, ln1_g, ln1_b, qkv_b, proj_b,
                  ln2_g, ln2_b, fc1_b, fc2_b, gate, NADAPT, 1);
    }

    // --- final LN (only row 0 per sample needed for output) + head ---
    ln_k<<<BATCH, 192>>>(P.t, (long)NT2 * EMB, norm_g, norm_b, P.cls, EMB, nullptr, 0, 1);
    head_k<<<BATCH, 128>>>(P.cls, head_w, head_b, out);
}

// round 10
// speedup vs baseline: 6.3105x; 1.0643x over previous
#include <cuda_runtime.h>
#include <cuda_fp16.h>
#include <math.h>
#include <stdint.h>

#define BATCH 32
#define EMB   768
#define HEADS 12
#define HD    64
#define NLAYERS 12
#define NFIX  6
#define NADAPT 6
#define MLPD  3072
#define NCLS  100
#define NTOK  198
#define NT2   197
#define PE_NN 100
#define PE_DD 256
#define NPATCH 196

// ---------------- scratch (device globals; no allocation allowed) ------------
__device__ float g_tok [BATCH*NTOK*EMB];
__device__ __align__(16) __half g_xn  [BATCH*NTOK*EMB];
__device__ __align__(16) __half g_qkv [BATCH*NTOK*3*EMB];
__device__ __align__(16) __half g_attb[BATCH*NTOK*EMB];
__device__ __align__(16) __half g_mlpb[BATCH*NTOK*MLPD];
__device__ float g_t   [BATCH*NT2*EMB];
__device__ float g_t2  [BATCH*NT2*EMB];
__device__ __align__(16) __half g_col [BATCH*NPATCH*EMB];
__device__ float g_pat [BATCH*NPATCH*EMB];
__device__ float g_lat1[BATCH*EMB];
__device__ __align__(16) __half g_lat2[BATCH*EMB];
__device__ float g_lat3[BATCH*EMB];
__device__ __align__(16) __half g_cls [BATCH*EMB];
__device__ int   g_actv[BATCH*NADAPT];
__device__ __align__(16) __half g_wqkv [NLAYERS*3*EMB*EMB];
__device__ __align__(16) __half g_wproj[NLAYERS*EMB*EMB];
__device__ __align__(16) __half g_wfc1 [NLAYERS*MLPD*EMB];
__device__ __align__(16) __half g_wfc2 [NLAYERS*EMB*MLPD];
__device__ __align__(16) __half g_wlat2[EMB*EMB];
__device__ __align__(16) __half g_wpat [EMB*EMB];

__device__ __forceinline__ float gelu_f(float v) {
    return 0.5f * v * (1.0f + erff(v * 0.70710678118654752440f));
}
__device__ __forceinline__ uint32_t smem_u32(const void* p) {
    uint32_t a;
    asm("{ .reg .u64 t; cvta.to.shared.u64 t, %1; cvt.u32.u64 %0, t; }" : "=r"(a) : "l"(p));
    return a;
}
__device__ __forceinline__ uint32_t h2_u32(__half2 h) {
    uint32_t u;
    *(__half2*)&u = h;
    return u;
}
__device__ __forceinline__ void cp16(uint32_t dst, const void* src, bool pred) {
    int sz = pred ? 16 : 0;
    asm volatile("cp.async.cg.shared.global [%0], [%1], 16, %2;"
                 :: "r"(dst), "l"(src), "r"(sz) : "memory");
}
__device__ __forceinline__ void mma_f16(float c[4], const uint32_t a[4], const uint32_t b[2]) {
    asm volatile(
        "mma.sync.aligned.m16n8k16.row.col.f32.f16.f16.f32 "
        "{%0,%1,%2,%3}, {%4,%5,%6,%7}, {%8,%9}, {%0,%1,%2,%3};\n"
        : "+f"(c[0]), "+f"(c[1]), "+f"(c[2]), "+f"(c[3])
        : "r"(a[0]), "r"(a[1]), "r"(a[2]), "r"(a[3]), "r"(b[0]), "r"(b[1]));
}
__device__ __forceinline__ void ldsm_x4(uint32_t r[4], uint32_t addr) {
    asm volatile("ldmatrix.sync.aligned.m8n8.x4.shared.b16 {%0,%1,%2,%3}, [%4];"
                 : "=r"(r[0]), "=r"(r[1]), "=r"(r[2]), "=r"(r[3]) : "r"(addr));
}

// ---------------- fp16 tensor-core GEMM: C = A[M,K] @ Bt[N,K]^T -------------
// 128x128x64 tiles, dynamic smem double buffer, ldmatrix fragment loads.
// gate: per-sample active flags; gate_rows also gates epilogue row writes.
#define HST2 72                               // halves per smem row (144 B)
#define GSTAGE (128 * HST2)                   // halves per stage per operand
#define GEMM_SMEM_BYTES (4 * GSTAGE * 2)      // 73728
template<int ACT, bool RES, bool OUTH>
__global__ void __launch_bounds__(256) hgemm_k(
    const __half* __restrict__ A, const __half* __restrict__ Bt,
    const float* __restrict__ bias, const float* __restrict__ res,
    float* __restrict__ Cf, __half* __restrict__ Ch, int M, int N, int K,
    const int* __restrict__ gate, int gstride, int rps, int gate_rows)
{
    const int brow = blockIdx.y * 128;
    if (gate) {
        const int s0 = brow / rps;
        const int s1 = min(brow + 127, M - 1) / rps;
        bool any = false;
        for (int s = s0; s <= s1; s++) any |= (gate[s * gstride] != 0);
        if (!any) return;
    }

    extern __shared__ __align__(16) __half hsm[];
    __half* sA[2] = { hsm,              hsm + GSTAGE };
    __half* sB[2] = { hsm + 2 * GSTAGE, hsm + 3 * GSTAGE };

    const int tid  = threadIdx.x;
    const int warp = tid >> 5, lane = tid & 31;
    const int bcol = blockIdx.x * 128;
    const int warpM = (warp >> 2) * 64;
    const int warpN = (warp & 3) * 32;
    const int g4 = lane >> 2, l2 = (lane & 3) * 2;

    const uint32_t saU[2] = { smem_u32(sA[0]), smem_u32(sA[1]) };
    const uint32_t sbU[2] = { smem_u32(sB[0]), smem_u32(sB[1]) };

    // per-lane ldmatrix row/col offset (halves): sel = lane>>3
    const int lmoff = ((lane & 7) + ((lane >> 3) & 1) * 8) * HST2 + (lane >> 4) * 8;

    float acc[4][4][4];
    #pragma unroll
    for (int i = 0; i < 4; i++)
        #pragma unroll
        for (int j = 0; j < 4; j++)
            #pragma unroll
            for (int r = 0; r < 4; r++) acc[i][j][r] = 0.0f;

    const int nch = K >> 6;                   // 64-K chunks

    auto LOAD = [&](int chunk, int st) {
        const int k0 = chunk << 6;
        const uint32_t da = saU[st], db = sbU[st];
        #pragma unroll
        for (int i = 0; i < 4; i++) {
            const int ch  = i * 256 + tid;    // 0..1023
            const int row = ch >> 3, col = ch & 7;
            cp16(da + row * (HST2 * 2) + col * 16,
                 A + (size_t)(brow + row) * K + k0 + col * 8, (brow + row) < M);
            cp16(db + row * (HST2 * 2) + col * 16,
                 Bt + (size_t)(bcol + row) * K + k0 + col * 8, true);
        }
        asm volatile("cp.async.commit_group;" ::: "memory");
    };

    LOAD(0, 0);

    for (int c = 0; c < nch; c++) {
        const int st = c & 1;
        if (c + 1 < nch) {
            LOAD(c + 1, st ^ 1);
            asm volatile("cp.async.wait_group 1;" ::: "memory");
        } else {
            asm volatile("cp.async.wait_group 0;" ::: "memory");
        }
        __syncthreads();

        const uint32_t aB = saU[st], bB = sbU[st];
        #pragma unroll
        for (int ks = 0; ks < 4; ks++) {
            uint32_t af[4][4], bf[4][2];
            #pragma unroll
            for (int tm = 0; tm < 4; tm++)
                ldsm_x4(af[tm], aB + 2 * ((warpM + tm * 16) * HST2 + ks * 16 + lmoff));
            #pragma unroll
            for (int tnp = 0; tnp < 2; tnp++) {
                uint32_t rb[4];
                ldsm_x4(rb, bB + 2 * ((warpN + tnp * 16) * HST2 + ks * 16 + lmoff));
                bf[2 * tnp][0]     = rb[0];
                bf[2 * tnp + 1][0] = rb[1];
                bf[2 * tnp][1]     = rb[2];
                bf[2 * tnp + 1][1] = rb[3];
            }
            #pragma unroll
            for (int tm = 0; tm < 4; tm++)
                #pragma unroll
                for (int tn = 0; tn < 4; tn++)
                    mma_f16(acc[tm][tn], af[tm], bf[tn]);
        }
        __syncthreads();
    }

    #pragma unroll
    for (int tm = 0; tm < 4; tm++) {
        const int rr = brow + warpM + tm * 16 + g4;
        #pragma unroll
        for (int half = 0; half < 2; half++) {
            const int gr = rr + half * 8;
            if (gr >= M) continue;
            if (gate_rows && gate && !gate[(gr / rps) * gstride]) continue;
            #pragma unroll
            for (int tn = 0; tn < 4; tn++) {
                const int gc = bcol + warpN + tn * 8 + l2;
                float o0 = acc[tm][tn][half * 2 + 0] + bias[gc];
                float o1 = acc[tm][tn][half * 2 + 1] + bias[gc + 1];
                if (ACT == 1) { o0 = gelu_f(o0); o1 = gelu_f(o1); }
                if (RES) {
                    o0 += res[(size_t)gr * N + gc];
                    o1 += res[(size_t)gr * N + gc + 1];
                }
                if (OUTH) {
                    *(__half2*)&Ch[(size_t)gr * N + gc] = __floats2half2_rn(o0, o1);
                } else {
                    Cf[(size_t)gr * N + gc]     = o0;
                    Cf[(size_t)gr * N + gc + 1] = o1;
                }
            }
        }
    }
}

// ---------------- weight transpose+convert ----------------------------------
__global__ void transpose_k(const float* __restrict__ in, __half* __restrict__ out,
                            int K, int N)
{
    __shared__ float t[32][33];
    const int l = blockIdx.z;
    const float* ip = in  + (size_t)l * K * N;
    __half*      op = out + (size_t)l * K * N;
    const int k0 = blockIdx.y * 32, n0 = blockIdx.x * 32;
    #pragma unroll
    for (int i = 0; i < 32; i += 8) {
        int k = k0 + threadIdx.y + i, n = n0 + threadIdx.x;
        if (k < K && n < N) t[threadIdx.y + i][threadIdx.x] = ip[(size_t)k * N + n];
    }
    __syncthreads();
    #pragma unroll
    for (int i = 0; i < 32; i += 8) {
        int n = n0 + threadIdx.y + i, k = k0 + threadIdx.x;
        if (n < N && k < K) op[(size_t)n * K + k] = __float2half_rn(t[threadIdx.x][threadIdx.y + i]);
    }
}

__global__ void cvt_k(const float* __restrict__ in, __half* __restrict__ out, long n)
{
    long i = (long)blockIdx.x * blockDim.x + threadIdx.x;
    if (i < n) out[i] = __float2half_rn(in[i]);
}

// ---------------- LayerNorm over 768 (fp32 in, half out), gated -------------
__global__ void __launch_bounds__(192) ln_k(
    const float* __restrict__ X, long istride,
    const float* __restrict__ g, const float* __restrict__ b,
    __half* __restrict__ Y, long ostride,
    const int* __restrict__ gate, int gstride, int rps)
{
    const int row = blockIdx.x;
    if (gate && !gate[(row / rps) * gstride]) return;
    const int tid = threadIdx.x;
    const float* x = X + (size_t)row * istride;
    __half* y      = Y + (size_t)row * ostride;
    __shared__ float red[6];
    __shared__ float stat[2];

    const float4 v = *(const float4*)&x[tid * 4];
    float s = v.x + v.y + v.z + v.w;
    #pragma unroll
    for (int o = 16; o; o >>= 1) s += __shfl_xor_sync(~0u, s, o);
    if ((tid & 31) == 0) red[tid >> 5] = s;
    __syncthreads();
    if (tid == 0) {
        float t = 0.f;
        #pragma unroll
        for (int i = 0; i < 6; i++) t += red[i];
        stat[0] = t * (1.0f / 768.0f);
    }
    __syncthreads();
    const float mean = stat[0];
    const float d0 = v.x - mean, d1 = v.y - mean, d2 = v.z - mean, d3 = v.w - mean;
    s = d0 * d0 + d1 * d1 + d2 * d2 + d3 * d3;
    #pragma unroll
    for (int o = 16; o; o >>= 1) s += __shfl_xor_sync(~0u, s, o);
    __syncthreads();
    if ((tid & 31) == 0) red[tid >> 5] = s;
    __syncthreads();
    if (tid == 0) {
        float t = 0.f;
        #pragma unroll
        for (int i = 0; i < 6; i++) t += red[i];
        stat[1] = rsqrtf(t * (1.0f / 768.0f) + 1e-5f);
    }
    __syncthreads();
    const float rstd = stat[1];
    const float4 gv = *(const float4*)&g[tid * 4];
    const float4 bv = *(const float4*)&b[tid * 4];
    __half2 h01 = __floats2half2_rn(d0 * rstd * gv.x + bv.x, d1 * rstd * gv.y + bv.y);
    __half2 h23 = __floats2half2_rn(d2 * rstd * gv.z + bv.z, d3 * rstd * gv.w + bv.w);
    *(__half2*)&y[tid * 4]     = h01;
    *(__half2*)&y[tid * 4 + 2] = h23;
}

// ---------------- tensor-core attention: one CTA (128 thr) per (b,h) --------
#define APAD 208
#define KST  72
#define VST  216
#define ATTN_SMEM_BYTES ((2*APAD*KST + 64*VST) * 2)

__global__ void __launch_bounds__(128) attn_k(const __half* __restrict__ qkv,
                                              __half* __restrict__ O, int N,
                                              const int* __restrict__ gate, int gstride)
{
    const int bh = blockIdx.x;
    const int b  = bh / HEADS, h = bh % HEADS;
    if (gate && !gate[b * gstride]) return;

    extern __shared__ __half smh[];
    __half* Qs = smh;
    __half* Ks = Qs + APAD * KST;
    __half* Vt = Ks + APAD * KST;

    const int tid = threadIdx.x;
    const int w = tid >> 5, lane = tid & 31;
    const int g4 = lane >> 2, l2 = (lane & 3) * 2;
    const __half* base = qkv + (size_t)b * N * (3 * EMB) + h * 64;

    for (int n = tid; n < APAD; n += 128) {
        uint4* qd = (uint4*)&Qs[n * KST];
        uint4* kd = (uint4*)&Ks[n * KST];
        if (n < N) {
            const uint4* qs = (const uint4*)(base + (size_t)n * (3 * EMB));
            const uint4* ks = (const uint4*)(base + (size_t)n * (3 * EMB) + EMB);
            #pragma unroll
            for (int i = 0; i < 8; i++) { qd[i] = qs[i]; kd[i] = ks[i]; }
        } else {
            uint4 z = make_uint4(0, 0, 0, 0);
            #pragma unroll
            for (int i = 0; i < 8; i++) { qd[i] = z; kd[i] = z; }
        }
    }
    for (int idx = tid; idx < APAD * 64; idx += 128) {
        const int n = idx >> 6, d = idx & 63;
        __half v = (n < N) ? base[(size_t)n * (3 * EMB) + 2 * EMB + d] : __ushort_as_half(0);
        Vt[d * VST + n] = v;
    }
    __syncthreads();

    for (int qt = w; qt < 13; qt += 4) {
        const int q0 = qt * 16;
        uint32_t aq[4][4];
        #pragma unroll
        for (int ks = 0; ks < 4; ks++) {
            const int kk = ks * 16 + l2;
            aq[ks][0] = *(const uint32_t*)&Qs[(q0 + g4) * KST + kk];
            aq[ks][1] = *(const uint32_t*)&Qs[(q0 + g4 + 8) * KST + kk];
            aq[ks][2] = *(const uint32_t*)&Qs[(q0 + g4) * KST + kk + 8];
            aq[ks][3] = *(const uint32_t*)&Qs[(q0 + g4 + 8) * KST + kk + 8];
        }
        float sc[26][4];
        #pragma unroll
        for (int nt = 0; nt < 26; nt++) {
            sc[nt][0] = sc[nt][1] = sc[nt][2] = sc[nt][3] = 0.f;
            #pragma unroll
            for (int ks = 0; ks < 4; ks++) {
                const int kk = ks * 16 + l2;
                uint32_t bf[2];
                bf[0] = *(const uint32_t*)&Ks[(nt * 8 + g4) * KST + kk];
                bf[1] = *(const uint32_t*)&Ks[(nt * 8 + g4) * KST + kk + 8];
                mma_f16(sc[nt], aq[ks], bf);
            }
        }
        float m0 = -1e30f, m1 = -1e30f;
        #pragma unroll
        for (int nt = 0; nt < 26; nt++) {
            #pragma unroll
            for (int e = 0; e < 2; e++) {
                const int col = nt * 8 + l2 + e;
                const bool ok = col < N;
                float v0 = ok ? sc[nt][e]     * 0.125f : -1e30f;
                float v1 = ok ? sc[nt][2 + e] * 0.125f : -1e30f;
                sc[nt][e] = v0; sc[nt][2 + e] = v1;
                m0 = fmaxf(m0, v0); m1 = fmaxf(m1, v1);
            }
        }
        m0 = fmaxf(m0, __shfl_xor_sync(~0u, m0, 1));
        m0 = fmaxf(m0, __shfl_xor_sync(~0u, m0, 2));
        m1 = fmaxf(m1, __shfl_xor_sync(~0u, m1, 1));
        m1 = fmaxf(m1, __shfl_xor_sync(~0u, m1, 2));
        float s0 = 0.f, s1 = 0.f;
        #pragma unroll
        for (int nt = 0; nt < 26; nt++) {
            #pragma unroll
            for (int e = 0; e < 2; e++) {
                float e0 = __expf(sc[nt][e]     - m0);
                float e1 = __expf(sc[nt][2 + e] - m1);
                sc[nt][e] = e0; sc[nt][2 + e] = e1;
                s0 += e0; s1 += e1;
            }
        }
        s0 += __shfl_xor_sync(~0u, s0, 1); s0 += __shfl_xor_sync(~0u, s0, 2);
        s1 += __shfl_xor_sync(~0u, s1, 1); s1 += __shfl_xor_sync(~0u, s1, 2);
        const float i0 = 1.0f / s0, i1 = 1.0f / s1;
        float o[8][4];
        #pragma unroll
        for (int dt = 0; dt < 8; dt++) o[dt][0] = o[dt][1] = o[dt][2] = o[dt][3] = 0.f;
        #pragma unroll
        for (int kt = 0; kt < 13; kt++) {
            uint32_t ap[4];
            ap[0] = h2_u32(__floats2half2_rn(sc[2*kt][0]   * i0, sc[2*kt][1]   * i0));
            ap[1] = h2_u32(__floats2half2_rn(sc[2*kt][2]   * i1, sc[2*kt][3]   * i1));
            ap[2] = h2_u32(__floats2half2_rn(sc[2*kt+1][0] * i0, sc[2*kt+1][1] * i0));
            ap[3] = h2_u32(__floats2half2_rn(sc[2*kt+1][2] * i1, sc[2*kt+1][3] * i1));
            #pragma unroll
            for (int dt = 0; dt < 8; dt++) {
                uint32_t bv[2];
                bv[0] = *(const uint32_t*)&Vt[(dt * 8 + g4) * VST + kt * 16 + l2];
                bv[1] = *(const uint32_t*)&Vt[(dt * 8 + g4) * VST + kt * 16 + l2 + 8];
                mma_f16(o[dt], ap, bv);
            }
        }
        const int r0 = q0 + g4, r1 = q0 + g4 + 8;
        __half* ob = O + h * 64;
        #pragma unroll
        for (int dt = 0; dt < 8; dt++) {
            const int c = dt * 8 + l2;
            if (r0 < N)
                *(__half2*)&ob[((size_t)b * N + r0) * EMB + c] = __floats2half2_rn(o[dt][0], o[dt][1]);
            if (r1 < N)
                *(__half2*)&ob[((size_t)b * N + r1) * EMB + c] = __floats2half2_rn(o[dt][2], o[dt][3]);
        }
    }
}

// ---------------- small / elementwise kernels -------------------------------
__global__ void im2col_k(const float* __restrict__ x, __half* __restrict__ col, long total)
{
    long i = (long)blockIdx.x * blockDim.x + threadIdx.x;
    if (i >= total) return;
    int k = (int)(i % EMB);
    long m = i / EMB;
    int b = (int)(m / NPATCH), p = (int)(m % NPATCH);
    int c = k >> 8, r = k & 255, ii = r >> 4, jj = r & 15;
    int py = p / 14, px = p % 14;
    col[i] = __float2half_rn(x[(((size_t)b * 3 + c) * 224 + py * 16 + ii) * 224 + px * 16 + jj]);
}

__global__ void lat1_k(const float* __restrict__ pe, const float* __restrict__ w1,
                       const float* __restrict__ b1, const float* __restrict__ budget,
                       float* __restrict__ out)
{
    int b = blockIdx.x;
    int idx = (int)rintf(budget[b] * (float)(PE_NN - 1));
    const float* row = pe + (size_t)idx * PE_DD;
    for (int e = threadIdx.x; e < EMB; e += 256) {
        float s = b1[e];
        for (int k = 0; k < PE_DD; k++) s += row[k] * w1[(size_t)k * EMB + e];
        out[(size_t)b * EMB + e] = gelu_f(s);
    }
}

__global__ void assemble_k(const float* __restrict__ lat, const float* __restrict__ cls,
                           const float* __restrict__ pat, const float* __restrict__ pos,
                           float* __restrict__ tok, long total)
{
    long i = (long)blockIdx.x * blockDim.x + threadIdx.x;
    if (i >= total) return;
    int e = (int)(i % EMB);
    long bn = i / EMB;
    int n = (int)(bn % NTOK), b = (int)(bn / NTOK);
    float v;
    if (n == 0)      v = lat[(size_t)b * EMB + e];
    else if (n == 1) v = cls[e];
    else             v = pat[((size_t)b * NPATCH + (n - 2)) * EMB + e];
    tok[i] = v + pos[(size_t)n * EMB + e];
}

__global__ void sched_k(const float* __restrict__ tok, const float* __restrict__ sw,
                        const float* __restrict__ sb, const float* __restrict__ budget,
                        int* __restrict__ active)
{
    int b = blockIdx.x, lane = threadIdx.x;
    __shared__ float lg[NADAPT];
    if (lane < NADAPT) {
        const float* x = tok + (size_t)b * NTOK * EMB;
        float s = sb[lane];
        for (int k = 0; k < EMB; k++) s += x[k] * sw[(size_t)k * NADAPT + lane];
        lg[lane] = s;
    }
    __syncwarp();
    if (lane < NADAPT) {
        int kk = (int)ceilf(budget[b] * (float)NADAPT);
        if (kk < 1) kk = 1;
        int rank = 0;
        for (int j = 0; j < NADAPT; j++)
            if (lg[j] > lg[lane] || (lg[j] == lg[lane] && j < lane)) rank++;
        active[b * NADAPT + lane] = (rank < kk) ? 1 : 0;
    }
}

__global__ void extract_k(const float* __restrict__ tok, float* __restrict__ t, long total)
{
    long i = (long)blockIdx.x * blockDim.x + threadIdx.x;
    if (i >= total) return;
    int e = (int)(i % EMB);
    long bn = i / EMB;
    int n = (int)(bn % NT2), b = (int)(bn / NT2);
    t[i] = tok[((size_t)b * NTOK + n + 1) * EMB + e];
}

__global__ void head_k(const __half* __restrict__ cls, const float* __restrict__ w,
                       const float* __restrict__ bias, float* __restrict__ out)
{
    int b = blockIdx.x, c = threadIdx.x;
    if (c >= NCLS) return;
    const __half* x = cls + (size_t)b * EMB;
    float s = bias[c];
    for (int k = 0; k < EMB; k++) s += __half2float(x[k]) * w[(size_t)k * NCLS + c];
    out[(size_t)b * NCLS + c] = s;
}

// ---------------- host orchestration ----------------------------------------
static inline void launch_gemm(int act, bool res, bool outh,
                               const __half* A, const __half* Bt, const float* bias,
                               const float* r, float* Cf, __half* Ch, int M, int N, int K,
                               const int* gate, int gstride, int rps, int gate_rows)
{
    dim3 g(N / 128, (M + 127) / 128), blk(256);
    if (outh) {
        if (act == 1)      hgemm_k<1, false, true><<<g, blk, GEMM_SMEM_BYTES>>>(A, Bt, bias, r, Cf, Ch, M, N, K, gate, gstride, rps, gate_rows);
        else               hgemm_k<0, false, true><<<g, blk, GEMM_SMEM_BYTES>>>(A, Bt, bias, r, Cf, Ch, M, N, K, gate, gstride, rps, gate_rows);
    } else {
        if (res)           hgemm_k<0, true,  false><<<g, blk, GEMM_SMEM_BYTES>>>(A, Bt, bias, r, Cf, Ch, M, N, K, gate, gstride, rps, gate_rows);
        else               hgemm_k<0, false, false><<<g, blk, GEMM_SMEM_BYTES>>>(A, Bt, bias, r, Cf, Ch, M, N, K, gate, gstride, rps, gate_rows);
    }
}

struct Ptrs {
    float *tok, *t, *t2, *pat, *lat1, *lat3;
    __half *xn, *qkv, *att, *mlp, *col, *lat2, *cls;
    __half *wqkv, *wproj, *wfc1, *wfc2, *wlat2, *wpat;
    int   *actv;
};

static void run_block(const Ptrs& P, float* Xin, float* Xmid, float* Xout, int N, int l,
                      const float* ln1g, const float* ln1b, const float* qkvb,
                      const float* projb, const float* ln2g, const float* ln2b,
                      const float* fc1b, const float* fc2b,
                      const int* gate, int gstride, int gate_rows)
{
    const int M = BATCH * N;
    ln_k<<<M, 192>>>(Xin, EMB, ln1g + (size_t)l * EMB, ln1b + (size_t)l * EMB,
                     P.xn, EMB, gate, gstride, N);
    launch_gemm(0, false, true, P.xn, P.wqkv + (size_t)l * EMB * 3 * EMB,
                qkvb + (size_t)l * 3 * EMB, nullptr, nullptr, P.qkv, M, 3 * EMB, EMB,
                gate, gstride, N, 0);
    attn_k<<<BATCH * HEADS, 128, ATTN_SMEM_BYTES>>>(P.qkv, P.att, N, gate, gstride);
    launch_gemm(0, true, false, P.att, P.wproj + (size_t)l * EMB * EMB,
                projb + (size_t)l * EMB, Xin, Xmid, nullptr, M, EMB, EMB,
                gate, gstride, N, 0);
    ln_k<<<M, 192>>>(Xmid, EMB, ln2g + (size_t)l * EMB, ln2b + (size_t)l * EMB,
                     P.xn, EMB, gate, gstride, N);
    launch_gemm(1, false, true, P.xn, P.wfc1 + (size_t)l * EMB * MLPD,
                fc1b + (size_t)l * MLPD, nullptr, nullptr, P.mlp, M, MLPD, EMB,
                gate, gstride, N, 0);
    launch_gemm(0, true, false, P.mlp, P.wfc2 + (size_t)l * MLPD * EMB,
                fc2b + (size_t)l * EMB, Xmid, Xout, nullptr, M, EMB, MLPD,
                gate, gstride, N, gate_rows);
}

extern "C" void kernel_launch(void* const* d_in, const int* in_sizes, int n_in,
                              void* d_out, int out_size)
{
    const float* x        = (const float*)d_in[0];
    const float* budget   = (const float*)d_in[1];
    const float* pe_table = (const float*)d_in[2];
    const float* lat_w1   = (const float*)d_in[3];
    const float* lat_b1   = (const float*)d_in[4];
    const float* lat_ln_g = (const float*)d_in[5];
    const float* lat_ln_b = (const float*)d_in[6];
    const float* lat_w2   = (const float*)d_in[7];
    const float* lat_b2   = (const float*)d_in[8];
    const float* patch_w  = (const float*)d_in[9];
    const float* patch_b  = (const float*)d_in[10];
    const float* cls_tok  = (const float*)d_in[11];
    const float* pos_emb  = (const float*)d_in[12];
    const float* sched_w  = (const float*)d_in[13];
    const float* sched_b  = (const float*)d_in[14];
    const float* ln1_g    = (const float*)d_in[15];
    const float* ln1_b    = (const float*)d_in[16];
    const float* qkv_w    = (const float*)d_in[17];
    const float* qkv_b    = (const float*)d_in[18];
    const float* proj_w   = (const float*)d_in[19];
    const float* proj_b   = (const float*)d_in[20];
    const float* ln2_g    = (const float*)d_in[21];
    const float* ln2_b    = (const float*)d_in[22];
    const float* fc1_w    = (const float*)d_in[23];
    const float* fc1_b    = (const float*)d_in[24];
    const float* fc2_w    = (const float*)d_in[25];
    const float* fc2_b    = (const float*)d_in[26];
    const float* norm_g   = (const float*)d_in[27];
    const float* norm_b   = (const float*)d_in[28];
    const float* head_w   = (const float*)d_in[29];
    const float* head_b   = (const float*)d_in[30];
    float* out = (float*)d_out;

    Ptrs P;
    cudaGetSymbolAddress((void**)&P.tok,  g_tok);
    cudaGetSymbolAddress((void**)&P.xn,   g_xn);
    cudaGetSymbolAddress((void**)&P.qkv,  g_qkv);
    cudaGetSymbolAddress((void**)&P.att,  g_attb);
    cudaGetSymbolAddress((void**)&P.mlp,  g_mlpb);
    cudaGetSymbolAddress((void**)&P.t,    g_t);
    cudaGetSymbolAddress((void**)&P.t2,   g_t2);
    cudaGetSymbolAddress((void**)&P.col,  g_col);
    cudaGetSymbolAddress((void**)&P.pat,  g_pat);
    cudaGetSymbolAddress((void**)&P.lat1, g_lat1);
    cudaGetSymbolAddress((void**)&P.lat2, g_lat2);
    cudaGetSymbolAddress((void**)&P.lat3, g_lat3);
    cudaGetSymbolAddress((void**)&P.cls,  g_cls);
    cudaGetSymbolAddress((void**)&P.actv, g_actv);
    cudaGetSymbolAddress((void**)&P.wqkv, g_wqkv);
    cudaGetSymbolAddress((void**)&P.wproj,g_wproj);
    cudaGetSymbolAddress((void**)&P.wfc1, g_wfc1);
    cudaGetSymbolAddress((void**)&P.wfc2, g_wfc2);
    cudaGetSymbolAddress((void**)&P.wlat2,g_wlat2);
    cudaGetSymbolAddress((void**)&P.wpat, g_wpat);

    cudaFuncSetAttribute(attn_k, cudaFuncAttributeMaxDynamicSharedMemorySize, ATTN_SMEM_BYTES);
    cudaFuncSetAttribute(hgemm_k<0,false,true >, cudaFuncAttributeMaxDynamicSharedMemorySize, GEMM_SMEM_BYTES);
    cudaFuncSetAttribute(hgemm_k<1,false,true >, cudaFuncAttributeMaxDynamicSharedMemorySize, GEMM_SMEM_BYTES);
    cudaFuncSetAttribute(hgemm_k<0,true, false>, cudaFuncAttributeMaxDynamicSharedMemorySize, GEMM_SMEM_BYTES);
    cudaFuncSetAttribute(hgemm_k<0,false,false>, cudaFuncAttributeMaxDynamicSharedMemorySize, GEMM_SMEM_BYTES);

    // --- weight transposes+convert ([K,N] fp32 -> [N,K] half) ---
    {
        dim3 b32(32, 8);
        transpose_k<<<dim3(3*EMB/32, EMB/32, NLAYERS), b32>>>(qkv_w,  P.wqkv,  EMB, 3*EMB);
        transpose_k<<<dim3(EMB/32,   EMB/32, NLAYERS), b32>>>(proj_w, P.wproj, EMB, EMB);
        transpose_k<<<dim3(MLPD/32,  EMB/32, NLAYERS), b32>>>(fc1_w,  P.wfc1,  EMB, MLPD);
        transpose_k<<<dim3(EMB/32,  MLPD/32, NLAYERS), b32>>>(fc2_w,  P.wfc2,  MLPD, EMB);
        transpose_k<<<dim3(EMB/32,   EMB/32, 1),       b32>>>(lat_w2, P.wlat2, EMB, EMB);
        long pw = (long)EMB * EMB;
        cvt_k<<<(unsigned)((pw + 255) / 256), 256>>>(patch_w, P.wpat, pw);
    }

    // --- latent token ---
    lat1_k<<<BATCH, 256>>>(pe_table, lat_w1, lat_b1, budget, P.lat1);
    ln_k<<<BATCH, 192>>>(P.lat1, EMB, lat_ln_g, lat_ln_b, P.lat2, EMB, nullptr, 0, 1);
    launch_gemm(0, false, false, P.lat2, P.wlat2, lat_b2, nullptr, P.lat3, nullptr,
                BATCH, EMB, EMB, nullptr, 0, 1, 0);

    // --- patch embedding ---
    {
        long tot = (long)BATCH * NPATCH * EMB;
        im2col_k<<<(unsigned)((tot + 255) / 256), 256>>>(x, P.col, tot);
        launch_gemm(0, false, false, P.col, P.wpat, patch_b, nullptr, P.pat, nullptr,
                    BATCH * NPATCH, EMB, EMB, nullptr, 0, 1, 0);
        long ta = (long)BATCH * NTOK * EMB;
        assemble_k<<<(unsigned)((ta + 255) / 256), 256>>>(P.lat3, cls_tok, P.pat,
                                                          pos_emb, P.tok, ta);
    }

    // --- 6 fixed blocks on 198 tokens (in-place on tok) ---
    for (int l = 0; l < NFIX; l++)
        run_block(P, P.tok, P.tok, P.tok, NTOK, l, ln1_g, ln1_b, qkv_b, proj_b,
                  ln2_g, ln2_b, fc1_b, fc2_b, nullptr, 0, 0);

    // --- scheduler gating ---
    sched_k<<<BATCH, 32>>>(P.tok, sched_w, sched_b, budget, P.actv);

    // --- adaptive blocks on 197 tokens: t -> t2 (mid) -> t (gated write) ---
    const long tlen = (long)BATCH * NT2 * EMB;
    extract_k<<<(unsigned)((tlen + 255) / 256), 256>>>(P.tok, P.t, tlen);
    for (int i = 0; i < NADAPT; i++) {
        const int* gate = P.actv + i;
        run_block(P, P.t, P.t2, P.t, NT2, NFIX + i, ln1_g, ln1_b, qkv_b, proj_b,
                  ln2_g, ln2_b, fc1_b, fc2_b, gate, NADAPT, 1);
    }

    // --- final LN (only row 0 per sample needed for output) + head ---
    ln_k<<<BATCH, 192>>>(P.t, (long)NT2 * EMB, norm_g, norm_b, P.cls, EMB, nullptr, 0, 1);
    head_k<<<BATCH, 128>>>(P.cls, head_w, head_b, out);
}